// round 4
// baseline (speedup 1.0000x reference)
#include <cuda_runtime.h>
#include <math.h>

// Problem constants
#define BB     2
#define NN     1024
#define DIMM   1024
#define DEPTH  4
#define HEADS  16
#define DHEAD  64
#define INNER  1024          // HEADS*DHEAD
#define MLPD   4096
#define TOK    (BB*NN)       // 2048

// ---------------------------------------------------------------------------
// Scratch (no cudaMalloc allowed)
// ---------------------------------------------------------------------------
__device__ float g_h  [TOK * DIMM];       // LN output (8 MB)
__device__ float g_h2 [TOK * MLPD];       // FF1 output (32 MB)
__device__ float g_qkv[TOK * 3 * INNER];  // QKV (24 MB)
__device__ float g_o  [TOK * INNER];      // attention output (8 MB)

// ---------------------------------------------------------------------------
// LayerNorm: one block per token row (DIM=1024), two-pass, exact
// ---------------------------------------------------------------------------
__global__ void ln_kernel(const float* __restrict__ x,
                          const float* __restrict__ g,
                          const float* __restrict__ b,
                          float* __restrict__ out)
{
    int row = blockIdx.x;
    int tid = threadIdx.x;
    const float* xr = x + (size_t)row * DIMM;

    __shared__ float xs[DIMM];
    __shared__ float red[256];

    float s = 0.f;
    for (int i = tid; i < DIMM; i += 256) {
        float v = xr[i];
        xs[i] = v;
        s += v;
    }
    red[tid] = s;
    __syncthreads();
    for (int o = 128; o > 0; o >>= 1) {
        if (tid < o) red[tid] += red[tid + o];
        __syncthreads();
    }
    float mu = red[0] * (1.f / DIMM);
    __syncthreads();   // all threads read red[0] before it is reused

    float s2 = 0.f;
    for (int i = tid; i < DIMM; i += 256) {
        float d = xs[i] - mu;
        s2 += d * d;
    }
    red[tid] = s2;
    __syncthreads();
    for (int o = 128; o > 0; o >>= 1) {
        if (tid < o) red[tid] += red[tid + o];
        __syncthreads();
    }
    float rstd = rsqrtf(red[0] * (1.f / DIMM) + 1e-5f);

    float* outr = out + (size_t)row * DIMM;
    for (int i = tid; i < DIMM; i += 256)
        outr[i] = (xs[i] - mu) * rstd * g[i] + b[i];
}

// ---------------------------------------------------------------------------
// SGEMM: C[M,Ncols] = A[M,K] @ Bm[K,Ncols]  (row-major fp32)
// 128x128 block tile, K-step 8, 256 threads, 8x8 per thread.
// EPI: 0 = plain store, 1 = +bias +residual(in-place on C), 2 = +bias then GELU
// ---------------------------------------------------------------------------
template <int EPI>
__global__ __launch_bounds__(256)
void sgemm_kernel(const float* __restrict__ A,
                  const float* __restrict__ Bm,
                  float* __restrict__ C,
                  const float* __restrict__ bias,
                  int M, int Ncols, int K)
{
    __shared__ __align__(16) float As[8][128];
    __shared__ __align__(16) float Bs[8][128];

    int tid = threadIdx.x;
    int bx = blockIdx.x, by = blockIdx.y;
    int tx = tid & 15, ty = tid >> 4;

    const int arow = tid >> 1;        // 0..127
    const int acol = (tid & 1) * 4;   // 0 or 4
    const int brow = tid >> 5;        // 0..7
    const int bcol = (tid & 31) * 4;  // 0..124

    const float* Aptr = A + (size_t)(by * 128 + arow) * K + acol;
    const float* Bptr = Bm + (size_t)brow * Ncols + bx * 128 + bcol;

    float acc[8][8] = {};

    for (int k0 = 0; k0 < K; k0 += 8) {
        float4 av = *(const float4*)(Aptr + k0);
        float4 bv = *(const float4*)(Bptr + (size_t)k0 * Ncols);

        As[acol + 0][arow] = av.x;
        As[acol + 1][arow] = av.y;
        As[acol + 2][arow] = av.z;
        As[acol + 3][arow] = av.w;
        *(float4*)&Bs[brow][bcol] = bv;
        __syncthreads();

#pragma unroll
        for (int k = 0; k < 8; ++k) {
            float4 a0 = *(const float4*)&As[k][ty * 8];
            float4 a1 = *(const float4*)&As[k][ty * 8 + 4];
            float4 b0 = *(const float4*)&Bs[k][tx * 8];
            float4 b1 = *(const float4*)&Bs[k][tx * 8 + 4];
            float a[8] = {a0.x, a0.y, a0.z, a0.w, a1.x, a1.y, a1.z, a1.w};
            float b[8] = {b0.x, b0.y, b0.z, b0.w, b1.x, b1.y, b1.z, b1.w};
#pragma unroll
            for (int i = 0; i < 8; ++i)
#pragma unroll
                for (int j = 0; j < 8; ++j)
                    acc[i][j] += a[i] * b[j];
        }
        __syncthreads();
    }

#pragma unroll
    for (int i = 0; i < 8; ++i) {
        int r = by * 128 + ty * 8 + i;
#pragma unroll
        for (int j = 0; j < 8; ++j) {
            int c = bx * 128 + tx * 8 + j;
            float v = acc[i][j];
            size_t idx = (size_t)r * Ncols + c;
            if (EPI == 1) {
                v += bias[c] + C[idx];              // residual (in-place)
            } else if (EPI == 2) {
                v += bias[c];
                v = 0.5f * v * (1.f + erff(v * 0.70710678118654752f)); // exact GELU
            }
            C[idx] = v;
        }
    }
}

// ---------------------------------------------------------------------------
// Fused attention (flash-style online softmax), fp32.
// Grid: (N/64 q-tiles, B*HEADS). 256 threads/block.
// Dynamic smem: Qs,Ks,Vs,Ss each [64][65] floats = 66560 B.
// ---------------------------------------------------------------------------
#define ATT_SMEM (4 * 64 * 65 * 4)

__global__ __launch_bounds__(256)
void attn_kernel(const float* __restrict__ qkv,
                 const int* __restrict__ mask,
                 float* __restrict__ o)
{
    extern __shared__ float sm[];
    float* Qs = sm;              // [64][65]
    float* Ks = Qs + 64 * 65;
    float* Vs = Ks + 64 * 65;
    float* Ss = Vs + 64 * 65;
    __shared__ float m_s[64], l_s[64], corr_s[64];

    int tid = threadIdx.x;
    int bh = blockIdx.y;
    int b  = bh >> 4;
    int h  = bh & 15;
    int q0 = blockIdx.x * 64;

    int tr = tid >> 4;   // row group 0..15 -> rows tr*4..tr*4+3
    int tc = tid & 15;   // col group 0..15 -> cols tc*4..tc*4+3
    const float scale = 0.125f;  // 64^-0.5

    // Load Q tile (64 rows x 64 dims)
    const float* qbase = qkv + ((size_t)(b * NN + q0)) * (3 * INNER) + h * DHEAD;
    for (int idx = tid; idx < 64 * 16; idx += 256) {
        int r = idx >> 4, c4 = (idx & 15) * 4;
        float4 v = *(const float4*)(qbase + (size_t)r * (3 * INNER) + c4);
        float* q = &Qs[r * 65 + c4];
        q[0] = v.x; q[1] = v.y; q[2] = v.z; q[3] = v.w;
    }
    if (tid < 64) { m_s[tid] = -INFINITY; l_s[tid] = 0.f; }

    float oacc[4][4];
#pragma unroll
    for (int i = 0; i < 4; ++i)
#pragma unroll
        for (int j = 0; j < 4; ++j) oacc[i][j] = 0.f;

    __syncthreads();

    for (int k0 = 0; k0 < NN; k0 += 64) {
        // Load K,V tiles
        const float* kbase = qkv + ((size_t)(b * NN + k0)) * (3 * INNER) + INNER + h * DHEAD;
        const float* vbase = kbase + INNER;
        for (int idx = tid; idx < 64 * 16; idx += 256) {
            int r = idx >> 4, c4 = (idx & 15) * 4;
            float4 kv = *(const float4*)(kbase + (size_t)r * (3 * INNER) + c4);
            float4 vv = *(const float4*)(vbase + (size_t)r * (3 * INNER) + c4);
            float* kp = &Ks[r * 65 + c4];
            float* vp = &Vs[r * 65 + c4];
            kp[0] = kv.x; kp[1] = kv.y; kp[2] = kv.z; kp[3] = kv.w;
            vp[0] = vv.x; vp[1] = vv.y; vp[2] = vv.z; vp[3] = vv.w;
        }
        __syncthreads();

        // S = Q @ K^T  (4x4 per thread)
        float s[4][4] = {};
#pragma unroll 4
        for (int d = 0; d < 64; ++d) {
            float a[4], kk[4];
#pragma unroll
            for (int i = 0; i < 4; ++i) a[i]  = Qs[(tr * 4 + i) * 65 + d];
#pragma unroll
            for (int j = 0; j < 4; ++j) kk[j] = Ks[(tc * 4 + j) * 65 + d];
#pragma unroll
            for (int i = 0; i < 4; ++i)
#pragma unroll
                for (int j = 0; j < 4; ++j)
                    s[i][j] += a[i] * kk[j];
        }

        // scale + mask, write into Ss
#pragma unroll
        for (int i = 0; i < 4; ++i) {
            int qrow = q0 + tr * 4 + i;
            const int* mrow = mask + ((size_t)b * NN + qrow) * NN + k0;
#pragma unroll
            for (int j = 0; j < 4; ++j) {
                float v = s[i][j] * scale;
                if (mrow[tc * 4 + j] == 0) v = -1e9f;
                Ss[(tr * 4 + i) * 65 + tc * 4 + j] = v;
            }
        }
        __syncthreads();

        // Online softmax row update (one thread per row)
        if (tid < 64) {
            int r = tid;
            float mx = m_s[r];
            float tmax = -INFINITY;
            for (int j = 0; j < 64; ++j) tmax = fmaxf(tmax, Ss[r * 65 + j]);
            float nm = fmaxf(mx, tmax);
            float corr = __expf(mx - nm);
            float sum = 0.f;
            for (int j = 0; j < 64; ++j) {
                float p = __expf(Ss[r * 65 + j] - nm);
                Ss[r * 65 + j] = p;
                sum += p;
            }
            m_s[r] = nm;
            l_s[r] = l_s[r] * corr + sum;
            corr_s[r] = corr;
        }
        __syncthreads();

        // O = O*corr + P @ V
#pragma unroll
        for (int i = 0; i < 4; ++i) {
            float corr = corr_s[tr * 4 + i];
#pragma unroll
            for (int j = 0; j < 4; ++j) oacc[i][j] *= corr;
        }
#pragma unroll 4
        for (int j = 0; j < 64; ++j) {
            float p[4], v[4];
#pragma unroll
            for (int i = 0; i < 4; ++i) p[i] = Ss[(tr * 4 + i) * 65 + j];
#pragma unroll
            for (int c = 0; c < 4; ++c) v[c] = Vs[j * 65 + tc * 4 + c];
#pragma unroll
            for (int i = 0; i < 4; ++i)
#pragma unroll
                for (int c = 0; c < 4; ++c)
                    oacc[i][c] += p[i] * v[c];
        }
        __syncthreads();
    }

    // Write O (normalize by l)
#pragma unroll
    for (int i = 0; i < 4; ++i) {
        int r = tr * 4 + i;
        float inv = 1.f / l_s[r];
        float* orow = o + ((size_t)(b * NN + q0 + r)) * INNER + h * DHEAD + tc * 4;
#pragma unroll
        for (int c = 0; c < 4; ++c)
            orow[c] = oacc[i][c] * inv;
    }
}

// ---------------------------------------------------------------------------
// Launch
// ---------------------------------------------------------------------------
extern "C" void kernel_launch(void* const* d_in, const int* in_sizes, int n_in,
                              void* d_out, int out_size)
{
    const float* x_in  = (const float*)d_in[0];
    const int*   mask  = (const int*)  d_in[1];
    const float* ln1_g = (const float*)d_in[2];
    const float* ln1_b = (const float*)d_in[3];
    const float* qkv_w = (const float*)d_in[4];
    const float* out_w = (const float*)d_in[5];
    const float* out_b = (const float*)d_in[6];
    const float* ln2_g = (const float*)d_in[7];
    const float* ln2_b = (const float*)d_in[8];
    const float* ff1_w = (const float*)d_in[9];
    const float* ff1_b = (const float*)d_in[10];
    const float* ff2_w = (const float*)d_in[11];
    const float* ff2_b = (const float*)d_in[12];
    float* x = (float*)d_out;

    float *h, *h2, *qkvb, *ob;
    cudaGetSymbolAddress((void**)&h,    g_h);
    cudaGetSymbolAddress((void**)&h2,   g_h2);
    cudaGetSymbolAddress((void**)&qkvb, g_qkv);
    cudaGetSymbolAddress((void**)&ob,   g_o);

    cudaFuncSetAttribute(attn_kernel,
                         cudaFuncAttributeMaxDynamicSharedMemorySize, ATT_SMEM);

    // x (residual stream) lives in d_out
    cudaMemcpyAsync(x, x_in, sizeof(float) * (size_t)TOK * DIMM,
                    cudaMemcpyDeviceToDevice);

    for (int l = 0; l < DEPTH; ++l) {
        // h = LN1(x)
        ln_kernel<<<TOK, 256>>>(x, ln1_g + (size_t)l * DIMM,
                                   ln1_b + (size_t)l * DIMM, h);
        // qkv = h @ qkv_w[l]
        sgemm_kernel<0><<<dim3(3 * INNER / 128, TOK / 128), 256>>>(
            h, qkv_w + (size_t)l * DIMM * 3 * INNER, qkvb, nullptr,
            TOK, 3 * INNER, DIMM);
        // o = softmax(QK^T * scale + mask) @ V
        attn_kernel<<<dim3(NN / 64, BB * HEADS), 256, ATT_SMEM>>>(qkvb, mask, ob);
        // x = o @ out_w[l] + out_b[l] + x
        sgemm_kernel<1><<<dim3(DIMM / 128, TOK / 128), 256>>>(
            ob, out_w + (size_t)l * INNER * DIMM, x, out_b + (size_t)l * DIMM,
            TOK, DIMM, INNER);
        // h = LN2(x)
        ln_kernel<<<TOK, 256>>>(x, ln2_g + (size_t)l * DIMM,
                                   ln2_b + (size_t)l * DIMM, h);
        // h2 = gelu(h @ ff1_w[l] + ff1_b[l])
        sgemm_kernel<2><<<dim3(MLPD / 128, TOK / 128), 256>>>(
            h, ff1_w + (size_t)l * DIMM * MLPD, h2, ff1_b + (size_t)l * MLPD,
            TOK, MLPD, DIMM);
        // x = h2 @ ff2_w[l] + ff2_b[l] + x
        sgemm_kernel<1><<<dim3(DIMM / 128, TOK / 128), 256>>>(
            h2, ff2_w + (size_t)l * MLPD * DIMM, x, ff2_b + (size_t)l * DIMM,
            TOK, DIMM, MLPD);
    }
}

// round 6
// speedup vs baseline: 1.9374x; 1.9374x over previous
#include <cuda_runtime.h>
#include <cuda_bf16.h>
#include <math.h>
#include <stdint.h>

// Problem constants
#define BB     2
#define NN     1024
#define DIMM   1024
#define DEPTH  4
#define HEADS  16
#define DHEAD  64
#define INNER  1024
#define MLPD   4096
#define TOK    (BB*NN)       // 2048

// ---------------------------------------------------------------------------
// Scratch (no cudaMalloc allowed)
// ---------------------------------------------------------------------------
__device__ float g_h  [TOK * DIMM];
__device__ float g_h2 [TOK * MLPD];
__device__ float g_qkv[TOK * 3 * INNER];
__device__ float g_o  [TOK * INNER];

// ---------------------------------------------------------------------------
// Helpers
// ---------------------------------------------------------------------------
__device__ __forceinline__ uint32_t s2u(const void* p) {
    uint32_t a;
    asm("{ .reg .u64 t; cvta.to.shared.u64 t, %1; cvt.u32.u64 %0, t; }"
        : "=r"(a) : "l"(p));
    return a;
}

// split fp32 pair -> packed bf16x2 (hi) and bf16x2 (lo residual)
__device__ __forceinline__ void splitpair(float x0, float x1,
                                          uint32_t& h, uint32_t& l) {
    __nv_bfloat16 h0 = __float2bfloat16(x0);
    __nv_bfloat16 h1 = __float2bfloat16(x1);
    __nv_bfloat16 l0 = __float2bfloat16(x0 - __bfloat162float(h0));
    __nv_bfloat16 l1 = __float2bfloat16(x1 - __bfloat162float(h1));
    __nv_bfloat162 hp = __halves2bfloat162(h0, h1);
    __nv_bfloat162 lp = __halves2bfloat162(l0, l1);
    h = *reinterpret_cast<uint32_t*>(&hp);
    l = *reinterpret_cast<uint32_t*>(&lp);
}

__device__ __forceinline__ void cvt8(float4 a, float4 b, uint4& h, uint4& l) {
    uint32_t h0, l0, h1, l1, h2, l2, h3, l3;
    splitpair(a.x, a.y, h0, l0);
    splitpair(a.z, a.w, h1, l1);
    splitpair(b.x, b.y, h2, l2);
    splitpair(b.z, b.w, h3, l3);
    h = make_uint4(h0, h1, h2, h3);
    l = make_uint4(l0, l1, l2, l3);
}

#define LDX4(r, addr) \
    asm volatile("ldmatrix.sync.aligned.m8n8.x4.shared.b16 {%0,%1,%2,%3}, [%4];" \
        : "=r"((r)[0]), "=r"((r)[1]), "=r"((r)[2]), "=r"((r)[3]) : "r"(addr))

#define LDX4T(r, addr) \
    asm volatile("ldmatrix.sync.aligned.m8n8.x4.trans.shared.b16 {%0,%1,%2,%3}, [%4];" \
        : "=r"((r)[0]), "=r"((r)[1]), "=r"((r)[2]), "=r"((r)[3]) : "r"(addr))

#define MMA(cd, a, b) \
    asm volatile("mma.sync.aligned.m16n8k16.row.col.f32.bf16.bf16.f32 " \
        "{%0,%1,%2,%3}, {%4,%5,%6,%7}, {%8,%9}, {%0,%1,%2,%3};" \
        : "+f"((cd)[0]), "+f"((cd)[1]), "+f"((cd)[2]), "+f"((cd)[3]) \
        : "r"((a)[0]), "r"((a)[1]), "r"((a)[2]), "r"((a)[3]), \
          "r"((b)[0]), "r"((b)[1]))

__device__ __forceinline__ float gelu1(float v) {
    return 0.5f * v * (1.f + erff(v * 0.70710678118654752f));
}

// ---------------------------------------------------------------------------
// Tensor-core GEMM via mma.sync bf16 (split hi/lo, 3-term, fp32 accumulate).
// C[M,Ncols] = A[M,K] @ B[K,Ncols], fp32 in/out.
// 128x128 tile / CTA, 256 threads (8 warps, each 64x32), K-chunk 16,
// double-buffered smem. EPI: 0 plain, 1 +bias+residual(in-place), 2 +bias+GELU.
// ---------------------------------------------------------------------------
#define APITCH 24    // bf16 elems per A smem row (16 data + 8 pad)
#define BPITCH 136   // bf16 elems per B smem row (128 data + 8 pad)

template <int EPI>
__global__ __launch_bounds__(256)
void mma_gemm(const float* __restrict__ A, const float* __restrict__ Bm,
              float* __restrict__ C, const float* __restrict__ bias,
              int M, int Ncols, int K)
{
    __shared__ __align__(16) __nv_bfloat16 sAh[2][128 * APITCH];
    __shared__ __align__(16) __nv_bfloat16 sAl[2][128 * APITCH];
    __shared__ __align__(16) __nv_bfloat16 sBh[2][16 * BPITCH];
    __shared__ __align__(16) __nv_bfloat16 sBl[2][16 * BPITCH];

    const int tid = threadIdx.x, lane = tid & 31, wid = tid >> 5;
    const int m0 = blockIdx.y * 128, n0 = blockIdx.x * 128;
    const int wm = (wid >> 2) * 64, wn = (wid & 3) * 32;

    // loader mapping
    const int ar = tid >> 1, ac = (tid & 1) * 8;     // A: row, col8
    const int bkr = tid >> 4, bn = (tid & 15) * 8;   // B: k-row, n col8

    const float* aptr = A + (size_t)(m0 + ar) * K + ac;
    const float* bptr = Bm + (size_t)bkr * Ncols + n0 + bn;

    float acc[4][4][4];
#pragma unroll
    for (int i = 0; i < 4; ++i)
#pragma unroll
        for (int j = 0; j < 4; ++j)
#pragma unroll
            for (int q = 0; q < 4; ++q) acc[i][j][q] = 0.f;

    // ldmatrix per-lane element offsets
    const int a_off = (wm + (lane & 15)) * APITCH + (lane >> 4) * 8;
    const int b_off = (lane & 15) * BPITCH + wn + (lane >> 4) * 8;

    // prologue: load + convert chunk 0
    float4 av0 = *(const float4*)(aptr);
    float4 av1 = *(const float4*)(aptr + 4);
    float4 bv0 = *(const float4*)(bptr);
    float4 bv1 = *(const float4*)(bptr + 4);
    {
        uint4 h, l;
        cvt8(av0, av1, h, l);
        *(uint4*)&sAh[0][ar * APITCH + ac] = h;
        *(uint4*)&sAl[0][ar * APITCH + ac] = l;
        cvt8(bv0, bv1, h, l);
        *(uint4*)&sBh[0][bkr * BPITCH + bn] = h;
        *(uint4*)&sBl[0][bkr * BPITCH + bn] = l;
    }
    __syncthreads();

    const int NCH = K / 16;
    for (int c = 0; c < NCH; ++c) {
        const int st = c & 1;
        // prefetch next chunk into registers (overlap with MMAs)
        if (c + 1 < NCH) {
            const float* ap = aptr + (c + 1) * 16;
            av0 = *(const float4*)ap;
            av1 = *(const float4*)(ap + 4);
            const float* bp = bptr + (size_t)(c + 1) * 16 * Ncols;
            bv0 = *(const float4*)bp;
            bv1 = *(const float4*)(bp + 4);
        }

        // load fragments
        uint32_t bh[8], bl[8], ah[16], al[16];
        {
            uint32_t bb = s2u(&sBh[st][0]) + b_off * 2;
            uint32_t lb = s2u(&sBl[st][0]) + b_off * 2;
            LDX4T(bh + 0, bb);
            LDX4T(bh + 4, bb + 32);     // +16 n elems
            LDX4T(bl + 0, lb);
            LDX4T(bl + 4, lb + 32);
            uint32_t ab = s2u(&sAh[st][0]) + a_off * 2;
            uint32_t la = s2u(&sAl[st][0]) + a_off * 2;
#pragma unroll
            for (int mi = 0; mi < 4; ++mi) {
                LDX4(ah + mi * 4, ab + mi * 16 * APITCH * 2);
                LDX4(al + mi * 4, la + mi * 16 * APITCH * 2);
            }
        }

        // 3-term split MMAs
#pragma unroll
        for (int mi = 0; mi < 4; ++mi)
#pragma unroll
            for (int ni = 0; ni < 4; ++ni) {
                MMA(acc[mi][ni], ah + mi * 4, bh + ni * 2);
                MMA(acc[mi][ni], ah + mi * 4, bl + ni * 2);
                MMA(acc[mi][ni], al + mi * 4, bh + ni * 2);
            }

        // store next chunk to the other buffer
        if (c + 1 < NCH) {
            const int s2 = st ^ 1;
            uint4 h, l;
            cvt8(av0, av1, h, l);
            *(uint4*)&sAh[s2][ar * APITCH + ac] = h;
            *(uint4*)&sAl[s2][ar * APITCH + ac] = l;
            cvt8(bv0, bv1, h, l);
            *(uint4*)&sBh[s2][bkr * BPITCH + bn] = h;
            *(uint4*)&sBl[s2][bkr * BPITCH + bn] = l;
            __syncthreads();
        }
    }

    // epilogue
#pragma unroll
    for (int mi = 0; mi < 4; ++mi) {
        int row = m0 + wm + mi * 16 + (lane >> 2);
#pragma unroll
        for (int ni = 0; ni < 4; ++ni) {
            int col = n0 + wn + ni * 8 + (lane & 3) * 2;
#pragma unroll
            for (int half = 0; half < 2; ++half) {
                int r = row + half * 8;
                float v0 = acc[mi][ni][half * 2 + 0];
                float v1 = acc[mi][ni][half * 2 + 1];
                float* cp = C + (size_t)r * Ncols + col;
                if (EPI == 1) {
                    v0 += bias[col]     + cp[0];
                    v1 += bias[col + 1] + cp[1];
                } else if (EPI == 2) {
                    v0 = gelu1(v0 + bias[col]);
                    v1 = gelu1(v1 + bias[col + 1]);
                }
                float2 o = make_float2(v0, v1);
                *(float2*)cp = o;
            }
        }
    }
}

// ---------------------------------------------------------------------------
// LayerNorm: one block per token row (DIM=1024)
// ---------------------------------------------------------------------------
__global__ void ln_kernel(const float* __restrict__ x,
                          const float* __restrict__ g,
                          const float* __restrict__ b,
                          float* __restrict__ out)
{
    int row = blockIdx.x;
    int tid = threadIdx.x;
    const float* xr = x + (size_t)row * DIMM;

    __shared__ float xs[DIMM];
    __shared__ float red[256];

    float s = 0.f;
    for (int i = tid; i < DIMM; i += 256) {
        float v = xr[i];
        xs[i] = v;
        s += v;
    }
    red[tid] = s;
    __syncthreads();
    for (int o = 128; o > 0; o >>= 1) {
        if (tid < o) red[tid] += red[tid + o];
        __syncthreads();
    }
    float mu = red[0] * (1.f / DIMM);
    __syncthreads();

    float s2 = 0.f;
    for (int i = tid; i < DIMM; i += 256) {
        float d = xs[i] - mu;
        s2 += d * d;
    }
    red[tid] = s2;
    __syncthreads();
    for (int o = 128; o > 0; o >>= 1) {
        if (tid < o) red[tid] += red[tid + o];
        __syncthreads();
    }
    float rstd = rsqrtf(red[0] * (1.f / DIMM) + 1e-5f);

    float* outr = out + (size_t)row * DIMM;
    for (int i = tid; i < DIMM; i += 256)
        outr[i] = (xs[i] - mu) * rstd * g[i] + b[i];
}

// ---------------------------------------------------------------------------
// Fused attention (flash-style online softmax), fp32
// ---------------------------------------------------------------------------
#define ATT_SMEM (4 * 64 * 65 * 4)

__global__ __launch_bounds__(256)
void attn_kernel(const float* __restrict__ qkv,
                 const int* __restrict__ mask,
                 float* __restrict__ o)
{
    extern __shared__ float sm[];
    float* Qs = sm;
    float* Ks = Qs + 64 * 65;
    float* Vs = Ks + 64 * 65;
    float* Ss = Vs + 64 * 65;
    __shared__ float m_s[64], l_s[64], corr_s[64];

    int tid = threadIdx.x;
    int bh = blockIdx.y;
    int b  = bh >> 4;
    int h  = bh & 15;
    int q0 = blockIdx.x * 64;

    int tr = tid >> 4;
    int tc = tid & 15;
    const float scale = 0.125f;

    const float* qbase = qkv + ((size_t)(b * NN + q0)) * (3 * INNER) + h * DHEAD;
    for (int idx = tid; idx < 64 * 16; idx += 256) {
        int r = idx >> 4, c4 = (idx & 15) * 4;
        float4 v = *(const float4*)(qbase + (size_t)r * (3 * INNER) + c4);
        float* q = &Qs[r * 65 + c4];
        q[0] = v.x; q[1] = v.y; q[2] = v.z; q[3] = v.w;
    }
    if (tid < 64) { m_s[tid] = -INFINITY; l_s[tid] = 0.f; }

    float oacc[4][4];
#pragma unroll
    for (int i = 0; i < 4; ++i)
#pragma unroll
        for (int j = 0; j < 4; ++j) oacc[i][j] = 0.f;

    __syncthreads();

    for (int k0 = 0; k0 < NN; k0 += 64) {
        const float* kbase = qkv + ((size_t)(b * NN + k0)) * (3 * INNER) + INNER + h * DHEAD;
        const float* vbase = kbase + INNER;
        for (int idx = tid; idx < 64 * 16; idx += 256) {
            int r = idx >> 4, c4 = (idx & 15) * 4;
            float4 kv = *(const float4*)(kbase + (size_t)r * (3 * INNER) + c4);
            float4 vv = *(const float4*)(vbase + (size_t)r * (3 * INNER) + c4);
            float* kp = &Ks[r * 65 + c4];
            float* vp = &Vs[r * 65 + c4];
            kp[0] = kv.x; kp[1] = kv.y; kp[2] = kv.z; kp[3] = kv.w;
            vp[0] = vv.x; vp[1] = vv.y; vp[2] = vv.z; vp[3] = vv.w;
        }
        __syncthreads();

        float s[4][4] = {};
#pragma unroll 4
        for (int d = 0; d < 64; ++d) {
            float a[4], kk[4];
#pragma unroll
            for (int i = 0; i < 4; ++i) a[i]  = Qs[(tr * 4 + i) * 65 + d];
#pragma unroll
            for (int j = 0; j < 4; ++j) kk[j] = Ks[(tc * 4 + j) * 65 + d];
#pragma unroll
            for (int i = 0; i < 4; ++i)
#pragma unroll
                for (int j = 0; j < 4; ++j)
                    s[i][j] += a[i] * kk[j];
        }

#pragma unroll
        for (int i = 0; i < 4; ++i) {
            int qrow = q0 + tr * 4 + i;
            const int* mrow = mask + ((size_t)b * NN + qrow) * NN + k0;
#pragma unroll
            for (int j = 0; j < 4; ++j) {
                float v = s[i][j] * scale;
                if (mrow[tc * 4 + j] == 0) v = -1e9f;
                Ss[(tr * 4 + i) * 65 + tc * 4 + j] = v;
            }
        }
        __syncthreads();

        if (tid < 64) {
            int r = tid;
            float mx = m_s[r];
            float tmax = -INFINITY;
            for (int j = 0; j < 64; ++j) tmax = fmaxf(tmax, Ss[r * 65 + j]);
            float nm = fmaxf(mx, tmax);
            float corr = __expf(mx - nm);
            float sum = 0.f;
            for (int j = 0; j < 64; ++j) {
                float p = __expf(Ss[r * 65 + j] - nm);
                Ss[r * 65 + j] = p;
                sum += p;
            }
            m_s[r] = nm;
            l_s[r] = l_s[r] * corr + sum;
            corr_s[r] = corr;
        }
        __syncthreads();

#pragma unroll
        for (int i = 0; i < 4; ++i) {
            float corr = corr_s[tr * 4 + i];
#pragma unroll
            for (int j = 0; j < 4; ++j) oacc[i][j] *= corr;
        }
#pragma unroll 4
        for (int j = 0; j < 64; ++j) {
            float p[4], v[4];
#pragma unroll
            for (int i = 0; i < 4; ++i) p[i] = Ss[(tr * 4 + i) * 65 + j];
#pragma unroll
            for (int c = 0; c < 4; ++c) v[c] = Vs[j * 65 + tc * 4 + c];
#pragma unroll
            for (int i = 0; i < 4; ++i)
#pragma unroll
                for (int c = 0; c < 4; ++c)
                    oacc[i][c] += p[i] * v[c];
        }
        __syncthreads();
    }

#pragma unroll
    for (int i = 0; i < 4; ++i) {
        int r = tr * 4 + i;
        float inv = 1.f / l_s[r];
        float* orow = o + ((size_t)(b * NN + q0 + r)) * INNER + h * DHEAD + tc * 4;
#pragma unroll
        for (int c = 0; c < 4; ++c)
            orow[c] = oacc[i][c] * inv;
    }
}

// ---------------------------------------------------------------------------
// Launch
// ---------------------------------------------------------------------------
extern "C" void kernel_launch(void* const* d_in, const int* in_sizes, int n_in,
                              void* d_out, int out_size)
{
    const float* x_in  = (const float*)d_in[0];
    const int*   mask  = (const int*)  d_in[1];
    const float* ln1_g = (const float*)d_in[2];
    const float* ln1_b = (const float*)d_in[3];
    const float* qkv_w = (const float*)d_in[4];
    const float* out_w = (const float*)d_in[5];
    const float* out_b = (const float*)d_in[6];
    const float* ln2_g = (const float*)d_in[7];
    const float* ln2_b = (const float*)d_in[8];
    const float* ff1_w = (const float*)d_in[9];
    const float* ff1_b = (const float*)d_in[10];
    const float* ff2_w = (const float*)d_in[11];
    const float* ff2_b = (const float*)d_in[12];
    float* x = (float*)d_out;

    float *h, *h2, *qkvb, *ob;
    cudaGetSymbolAddress((void**)&h,    g_h);
    cudaGetSymbolAddress((void**)&h2,   g_h2);
    cudaGetSymbolAddress((void**)&qkvb, g_qkv);
    cudaGetSymbolAddress((void**)&ob,   g_o);

    cudaFuncSetAttribute(attn_kernel,
                         cudaFuncAttributeMaxDynamicSharedMemorySize, ATT_SMEM);

    cudaMemcpyAsync(x, x_in, sizeof(float) * (size_t)TOK * DIMM,
                    cudaMemcpyDeviceToDevice);

    for (int l = 0; l < DEPTH; ++l) {
        ln_kernel<<<TOK, 256>>>(x, ln1_g + (size_t)l * DIMM,
                                   ln1_b + (size_t)l * DIMM, h);
        mma_gemm<0><<<dim3(3 * INNER / 128, TOK / 128), 256>>>(
            h, qkv_w + (size_t)l * DIMM * 3 * INNER, qkvb, nullptr,
            TOK, 3 * INNER, DIMM);
        attn_kernel<<<dim3(NN / 64, BB * HEADS), 256, ATT_SMEM>>>(qkvb, mask, ob);
        mma_gemm<1><<<dim3(DIMM / 128, TOK / 128), 256>>>(
            ob, out_w + (size_t)l * INNER * DIMM, x, out_b + (size_t)l * DIMM,
            TOK, DIMM, INNER);
        ln_kernel<<<TOK, 256>>>(x, ln2_g + (size_t)l * DIMM,
                                   ln2_b + (size_t)l * DIMM, h);
        mma_gemm<2><<<dim3(MLPD / 128, TOK / 128), 256>>>(
            h, ff1_w + (size_t)l * DIMM * MLPD, h2, ff1_b + (size_t)l * MLPD,
            TOK, MLPD, DIMM);
        mma_gemm<1><<<dim3(DIMM / 128, TOK / 128), 256>>>(
            h2, ff2_w + (size_t)l * MLPD * DIMM, x, ff2_b + (size_t)l * DIMM,
            TOK, DIMM, MLPD);
    }
}

// round 7
// speedup vs baseline: 2.1431x; 1.1062x over previous
#include <cuda_runtime.h>
#include <cuda_bf16.h>
#include <math.h>
#include <stdint.h>

// Problem constants
#define BB     2
#define NN     1024
#define DIMM   1024
#define DEPTH  4
#define HEADS  16
#define DHEAD  64
#define INNER  1024
#define MLPD   4096
#define TOK    (BB*NN)       // 2048

typedef __nv_bfloat16 bf16;

// ---------------------------------------------------------------------------
// Scratch (no cudaMalloc allowed)
// ---------------------------------------------------------------------------
__device__ float g_qkv[TOK * 3 * INNER];          // fp32 QKV (attention input)

// bf16 hi/lo activations
__device__ bf16 g_hh [TOK * DIMM],  g_hl [TOK * DIMM];    // LN output
__device__ bf16 g_h2h[TOK * MLPD],  g_h2l[TOK * MLPD];    // GELU output
__device__ bf16 g_oh [TOK * INNER], g_ol [TOK * INNER];   // attention output

// bf16 hi/lo weights (converted once per launch)
__device__ bf16 g_wqkv_h[DEPTH * DIMM * 3 * INNER], g_wqkv_l[DEPTH * DIMM * 3 * INNER];
__device__ bf16 g_wout_h[DEPTH * INNER * DIMM],     g_wout_l[DEPTH * INNER * DIMM];
__device__ bf16 g_wff1_h[DEPTH * DIMM * MLPD],      g_wff1_l[DEPTH * DIMM * MLPD];
__device__ bf16 g_wff2_h[DEPTH * MLPD * DIMM],      g_wff2_l[DEPTH * MLPD * DIMM];

// ---------------------------------------------------------------------------
// Helpers
// ---------------------------------------------------------------------------
__device__ __forceinline__ uint32_t s2u(const void* p) {
    uint32_t a;
    asm("{ .reg .u64 t; cvta.to.shared.u64 t, %1; cvt.u32.u64 %0, t; }"
        : "=r"(a) : "l"(p));
    return a;
}

__device__ __forceinline__ void split1(float x, bf16& h, bf16& l) {
    h = __float2bfloat16(x);
    l = __float2bfloat16(x - __bfloat162float(h));
}

#define LDX4(r, addr) \
    asm volatile("ldmatrix.sync.aligned.m8n8.x4.shared.b16 {%0,%1,%2,%3}, [%4];" \
        : "=r"((r)[0]), "=r"((r)[1]), "=r"((r)[2]), "=r"((r)[3]) : "r"(addr))

#define LDX4T(r, addr) \
    asm volatile("ldmatrix.sync.aligned.m8n8.x4.trans.shared.b16 {%0,%1,%2,%3}, [%4];" \
        : "=r"((r)[0]), "=r"((r)[1]), "=r"((r)[2]), "=r"((r)[3]) : "r"(addr))

#define MMA(cd, a, b) \
    asm volatile("mma.sync.aligned.m16n8k16.row.col.f32.bf16.bf16.f32 " \
        "{%0,%1,%2,%3}, {%4,%5,%6,%7}, {%8,%9}, {%0,%1,%2,%3};" \
        : "+f"((cd)[0]), "+f"((cd)[1]), "+f"((cd)[2]), "+f"((cd)[3]) \
        : "r"((a)[0]), "r"((a)[1]), "r"((a)[2]), "r"((a)[3]), \
          "r"((b)[0]), "r"((b)[1]))

#define CP16(dst, src) \
    asm volatile("cp.async.cg.shared.global [%0], [%1], 16;" \
        :: "r"(dst), "l"(src) : "memory")

__device__ __forceinline__ float gelu1(float v) {
    return 0.5f * v * (1.f + erff(v * 0.70710678118654752f));
}

// ---------------------------------------------------------------------------
// fp32 -> bf16 hi/lo elementwise convert (grid-stride, float4)
// ---------------------------------------------------------------------------
__global__ void cvt_kernel(const float* __restrict__ in,
                           bf16* __restrict__ h, bf16* __restrict__ l, int n4)
{
    for (int i = blockIdx.x * blockDim.x + threadIdx.x; i < n4;
         i += gridDim.x * blockDim.x) {
        float4 v = ((const float4*)in)[i];
        bf16 h0, l0, h1, l1, h2, l2, h3, l3;
        split1(v.x, h0, l0); split1(v.y, h1, l1);
        split1(v.z, h2, l2); split1(v.w, h3, l3);
        __nv_bfloat162 hp0 = __halves2bfloat162(h0, h1);
        __nv_bfloat162 hp1 = __halves2bfloat162(h2, h3);
        __nv_bfloat162 lp0 = __halves2bfloat162(l0, l1);
        __nv_bfloat162 lp1 = __halves2bfloat162(l2, l3);
        ((uint2*)h)[i] = make_uint2(*(uint32_t*)&hp0, *(uint32_t*)&hp1);
        ((uint2*)l)[i] = make_uint2(*(uint32_t*)&lp0, *(uint32_t*)&lp1);
    }
}

// ---------------------------------------------------------------------------
// Tensor-core GEMM, bf16 hi/lo inputs (pre-converted), 3-term split MMA.
// 128x128 tile/CTA, 256 threads (8 warps x 64x32), K-chunk 16,
// cp.async double-buffered. EPI: 0 plain fp32, 1 +bias+residual fp32 in-place,
// 2 +bias+GELU -> bf16 hi/lo outputs.
// ---------------------------------------------------------------------------
#define APITCH 24
#define BPITCH 136
#define A_STAGE (128 * APITCH)   // bf16 elems
#define B_STAGE (16 * BPITCH)

template <int EPI>
__global__ __launch_bounds__(256, 2)
void mma_gemm(const bf16* __restrict__ Ah, const bf16* __restrict__ Al,
              const bf16* __restrict__ Bh, const bf16* __restrict__ Bl,
              float* __restrict__ C, const float* __restrict__ bias,
              bf16* __restrict__ Ch, bf16* __restrict__ Cl,
              int M, int Ncols, int K)
{
    __shared__ __align__(16) bf16 sAh[2][A_STAGE];
    __shared__ __align__(16) bf16 sAl[2][A_STAGE];
    __shared__ __align__(16) bf16 sBh[2][B_STAGE];
    __shared__ __align__(16) bf16 sBl[2][B_STAGE];

    const int tid = threadIdx.x, lane = tid & 31, wid = tid >> 5;
    const int m0 = blockIdx.y * 128, n0 = blockIdx.x * 128;
    const int wm = (wid >> 2) * 64, wn = (wid & 3) * 32;

    // loader mapping
    const int ar = tid >> 1, ac = (tid & 1) * 8;     // A: row 0..127, k-col8
    const int bkr = tid >> 4, bn = (tid & 15) * 8;   // B: k-row 0..15, n-col8

    const bf16* agh = Ah + (size_t)(m0 + ar) * K + ac;
    const bf16* agl = Al + (size_t)(m0 + ar) * K + ac;
    const bf16* bgh = Bh + (size_t)bkr * Ncols + n0 + bn;
    const bf16* bgl = Bl + (size_t)bkr * Ncols + n0 + bn;

    const uint32_t sa_h = s2u(&sAh[0][0]) + (ar * APITCH + ac) * 2;
    const uint32_t sa_l = s2u(&sAl[0][0]) + (ar * APITCH + ac) * 2;
    const uint32_t sb_h = s2u(&sBh[0][0]) + (bkr * BPITCH + bn) * 2;
    const uint32_t sb_l = s2u(&sBl[0][0]) + (bkr * BPITCH + bn) * 2;

    float acc[4][4][4];
#pragma unroll
    for (int i = 0; i < 4; ++i)
#pragma unroll
        for (int j = 0; j < 4; ++j)
#pragma unroll
            for (int q = 0; q < 4; ++q) acc[i][j][q] = 0.f;

    // ldmatrix per-lane element offsets
    const int a_off = (wm + (lane & 15)) * APITCH + (lane >> 4) * 8;
    const int b_off = (lane & 15) * BPITCH + wn + (lane >> 4) * 8;

    const int NCH = K / 16;

    // prologue: chunk 0
    CP16(sa_h, agh);
    CP16(sa_l, agl);
    CP16(sb_h, bgh);
    CP16(sb_l, bgl);
    asm volatile("cp.async.commit_group;" ::: "memory");

    for (int c = 0; c < NCH; ++c) {
        const int st = c & 1;
        if (c + 1 < NCH) {
            const int s2 = st ^ 1;
            CP16(sa_h + s2 * (A_STAGE * 2), agh + (c + 1) * 16);
            CP16(sa_l + s2 * (A_STAGE * 2), agl + (c + 1) * 16);
            CP16(sb_h + s2 * (B_STAGE * 2), bgh + (size_t)(c + 1) * 16 * Ncols);
            CP16(sb_l + s2 * (B_STAGE * 2), bgl + (size_t)(c + 1) * 16 * Ncols);
            asm volatile("cp.async.commit_group;" ::: "memory");
            asm volatile("cp.async.wait_group 1;" ::: "memory");
        } else {
            asm volatile("cp.async.wait_group 0;" ::: "memory");
        }
        __syncthreads();

        uint32_t bh[8], bl[8], ah[16], al[16];
        {
            uint32_t bb = s2u(&sBh[st][0]) + b_off * 2;
            uint32_t lb = s2u(&sBl[st][0]) + b_off * 2;
            LDX4T(bh + 0, bb);
            LDX4T(bh + 4, bb + 32);
            LDX4T(bl + 0, lb);
            LDX4T(bl + 4, lb + 32);
            uint32_t ab = s2u(&sAh[st][0]) + a_off * 2;
            uint32_t la = s2u(&sAl[st][0]) + a_off * 2;
#pragma unroll
            for (int mi = 0; mi < 4; ++mi) {
                LDX4(ah + mi * 4, ab + mi * 16 * APITCH * 2);
                LDX4(al + mi * 4, la + mi * 16 * APITCH * 2);
            }
        }

#pragma unroll
        for (int mi = 0; mi < 4; ++mi)
#pragma unroll
            for (int ni = 0; ni < 4; ++ni) {
                MMA(acc[mi][ni], ah + mi * 4, bh + ni * 2);
                MMA(acc[mi][ni], ah + mi * 4, bl + ni * 2);
                MMA(acc[mi][ni], al + mi * 4, bh + ni * 2);
            }
        __syncthreads();
    }

    // epilogue
#pragma unroll
    for (int mi = 0; mi < 4; ++mi) {
        int row = m0 + wm + mi * 16 + (lane >> 2);
#pragma unroll
        for (int ni = 0; ni < 4; ++ni) {
            int col = n0 + wn + ni * 8 + (lane & 3) * 2;
#pragma unroll
            for (int half = 0; half < 2; ++half) {
                int r = row + half * 8;
                float v0 = acc[mi][ni][half * 2 + 0];
                float v1 = acc[mi][ni][half * 2 + 1];
                size_t idx = (size_t)r * Ncols + col;
                if (EPI == 0) {
                    *(float2*)(C + idx) = make_float2(v0, v1);
                } else if (EPI == 1) {
                    float* cp = C + idx;
                    v0 += bias[col]     + cp[0];
                    v1 += bias[col + 1] + cp[1];
                    *(float2*)cp = make_float2(v0, v1);
                } else {
                    v0 = gelu1(v0 + bias[col]);
                    v1 = gelu1(v1 + bias[col + 1]);
                    bf16 h0, l0, h1, l1;
                    split1(v0, h0, l0);
                    split1(v1, h1, l1);
                    __nv_bfloat162 hp = __halves2bfloat162(h0, h1);
                    __nv_bfloat162 lp = __halves2bfloat162(l0, l1);
                    *(uint32_t*)(Ch + idx) = *(uint32_t*)&hp;
                    *(uint32_t*)(Cl + idx) = *(uint32_t*)&lp;
                }
            }
        }
    }
}

// ---------------------------------------------------------------------------
// LayerNorm: one block (256 thr) per token row, vectorized, bf16 hi/lo out
// ---------------------------------------------------------------------------
__global__ void ln_kernel(const float* __restrict__ x,
                          const float* __restrict__ g,
                          const float* __restrict__ b,
                          bf16* __restrict__ oh, bf16* __restrict__ ol)
{
    int row = blockIdx.x;
    int tid = threadIdx.x;
    int lane = tid & 31, wid = tid >> 5;
    __shared__ float red[8];
    __shared__ float bc[2];

    float4 v = *(const float4*)(x + (size_t)row * DIMM + tid * 4);

    float s = v.x + v.y + v.z + v.w;
#pragma unroll
    for (int o = 16; o > 0; o >>= 1) s += __shfl_xor_sync(~0u, s, o);
    if (lane == 0) red[wid] = s;
    __syncthreads();
    if (tid == 0) {
        float t = 0.f;
#pragma unroll
        for (int i = 0; i < 8; ++i) t += red[i];
        bc[0] = t * (1.f / DIMM);
    }
    __syncthreads();
    float mu = bc[0];

    float dx = v.x - mu, dy = v.y - mu, dz = v.z - mu, dw = v.w - mu;
    float s2 = dx * dx + dy * dy + dz * dz + dw * dw;
#pragma unroll
    for (int o = 16; o > 0; o >>= 1) s2 += __shfl_xor_sync(~0u, s2, o);
    if (lane == 0) red[wid] = s2;
    __syncthreads();
    if (tid == 0) {
        float t = 0.f;
#pragma unroll
        for (int i = 0; i < 8; ++i) t += red[i];
        bc[1] = rsqrtf(t * (1.f / DIMM) + 1e-5f);
    }
    __syncthreads();
    float rstd = bc[1];

    float4 gg = *(const float4*)(g + tid * 4);
    float4 bb = *(const float4*)(b + tid * 4);
    float o0 = dx * rstd * gg.x + bb.x;
    float o1 = dy * rstd * gg.y + bb.y;
    float o2 = dz * rstd * gg.z + bb.z;
    float o3 = dw * rstd * gg.w + bb.w;

    bf16 h0, l0, h1, l1, h2, l2, h3, l3;
    split1(o0, h0, l0); split1(o1, h1, l1);
    split1(o2, h2, l2); split1(o3, h3, l3);
    __nv_bfloat162 hp0 = __halves2bfloat162(h0, h1);
    __nv_bfloat162 hp1 = __halves2bfloat162(h2, h3);
    __nv_bfloat162 lp0 = __halves2bfloat162(l0, l1);
    __nv_bfloat162 lp1 = __halves2bfloat162(l2, l3);
    size_t idx = (size_t)row * DIMM + tid * 4;
    *(uint2*)(oh + idx) = make_uint2(*(uint32_t*)&hp0, *(uint32_t*)&hp1);
    *(uint2*)(ol + idx) = make_uint2(*(uint32_t*)&lp0, *(uint32_t*)&lp1);
}

// ---------------------------------------------------------------------------
// Fused attention (flash-style), fp32 compute, bf16 hi/lo output
// ---------------------------------------------------------------------------
#define ATT_SMEM (4 * 64 * 65 * 4)

__global__ __launch_bounds__(256)
void attn_kernel(const float* __restrict__ qkv,
                 const int* __restrict__ mask,
                 bf16* __restrict__ oh, bf16* __restrict__ ol)
{
    extern __shared__ float sm[];
    float* Qs = sm;
    float* Ks = Qs + 64 * 65;
    float* Vs = Ks + 64 * 65;
    float* Ss = Vs + 64 * 65;
    __shared__ float m_s[64], l_s[64], corr_s[64];

    int tid = threadIdx.x;
    int bh = blockIdx.y;
    int b  = bh >> 4;
    int h  = bh & 15;
    int q0 = blockIdx.x * 64;

    int tr = tid >> 4;
    int tc = tid & 15;
    const float scale = 0.125f;

    const float* qbase = qkv + ((size_t)(b * NN + q0)) * (3 * INNER) + h * DHEAD;
    for (int idx = tid; idx < 64 * 16; idx += 256) {
        int r = idx >> 4, c4 = (idx & 15) * 4;
        float4 v = *(const float4*)(qbase + (size_t)r * (3 * INNER) + c4);
        float* q = &Qs[r * 65 + c4];
        q[0] = v.x; q[1] = v.y; q[2] = v.z; q[3] = v.w;
    }
    if (tid < 64) { m_s[tid] = -INFINITY; l_s[tid] = 0.f; }

    float oacc[4][4];
#pragma unroll
    for (int i = 0; i < 4; ++i)
#pragma unroll
        for (int j = 0; j < 4; ++j) oacc[i][j] = 0.f;

    __syncthreads();

    for (int k0 = 0; k0 < NN; k0 += 64) {
        const float* kbase = qkv + ((size_t)(b * NN + k0)) * (3 * INNER) + INNER + h * DHEAD;
        const float* vbase = kbase + INNER;
        for (int idx = tid; idx < 64 * 16; idx += 256) {
            int r = idx >> 4, c4 = (idx & 15) * 4;
            float4 kv = *(const float4*)(kbase + (size_t)r * (3 * INNER) + c4);
            float4 vv = *(const float4*)(vbase + (size_t)r * (3 * INNER) + c4);
            float* kp = &Ks[r * 65 + c4];
            float* vp = &Vs[r * 65 + c4];
            kp[0] = kv.x; kp[1] = kv.y; kp[2] = kv.z; kp[3] = kv.w;
            vp[0] = vv.x; vp[1] = vv.y; vp[2] = vv.z; vp[3] = vv.w;
        }
        __syncthreads();

        float s[4][4] = {};
#pragma unroll 4
        for (int d = 0; d < 64; ++d) {
            float a[4], kk[4];
#pragma unroll
            for (int i = 0; i < 4; ++i) a[i]  = Qs[(tr * 4 + i) * 65 + d];
#pragma unroll
            for (int j = 0; j < 4; ++j) kk[j] = Ks[(tc * 4 + j) * 65 + d];
#pragma unroll
            for (int i = 0; i < 4; ++i)
#pragma unroll
                for (int j = 0; j < 4; ++j)
                    s[i][j] += a[i] * kk[j];
        }

#pragma unroll
        for (int i = 0; i < 4; ++i) {
            int qrow = q0 + tr * 4 + i;
            const int* mrow = mask + ((size_t)b * NN + qrow) * NN + k0;
#pragma unroll
            for (int j = 0; j < 4; ++j) {
                float v = s[i][j] * scale;
                if (mrow[tc * 4 + j] == 0) v = -1e9f;
                Ss[(tr * 4 + i) * 65 + tc * 4 + j] = v;
            }
        }
        __syncthreads();

        if (tid < 64) {
            int r = tid;
            float mx = m_s[r];
            float tmax = -INFINITY;
            for (int j = 0; j < 64; ++j) tmax = fmaxf(tmax, Ss[r * 65 + j]);
            float nm = fmaxf(mx, tmax);
            float corr = __expf(mx - nm);
            float sum = 0.f;
            for (int j = 0; j < 64; ++j) {
                float p = __expf(Ss[r * 65 + j] - nm);
                Ss[r * 65 + j] = p;
                sum += p;
            }
            m_s[r] = nm;
            l_s[r] = l_s[r] * corr + sum;
            corr_s[r] = corr;
        }
        __syncthreads();

#pragma unroll
        for (int i = 0; i < 4; ++i) {
            float corr = corr_s[tr * 4 + i];
#pragma unroll
            for (int j = 0; j < 4; ++j) oacc[i][j] *= corr;
        }
#pragma unroll 4
        for (int j = 0; j < 64; ++j) {
            float p[4], v[4];
#pragma unroll
            for (int i = 0; i < 4; ++i) p[i] = Ss[(tr * 4 + i) * 65 + j];
#pragma unroll
            for (int c = 0; c < 4; ++c) v[c] = Vs[j * 65 + tc * 4 + c];
#pragma unroll
            for (int i = 0; i < 4; ++i)
#pragma unroll
                for (int c = 0; c < 4; ++c)
                    oacc[i][c] += p[i] * v[c];
        }
        __syncthreads();
    }

#pragma unroll
    for (int i = 0; i < 4; ++i) {
        int r = tr * 4 + i;
        float inv = 1.f / l_s[r];
        size_t idx = ((size_t)(b * NN + q0 + r)) * INNER + h * DHEAD + tc * 4;
        float o0 = oacc[i][0] * inv, o1 = oacc[i][1] * inv;
        float o2 = oacc[i][2] * inv, o3 = oacc[i][3] * inv;
        bf16 h0, l0, h1, l1, h2, l2, h3, l3;
        split1(o0, h0, l0); split1(o1, h1, l1);
        split1(o2, h2, l2); split1(o3, h3, l3);
        __nv_bfloat162 hp0 = __halves2bfloat162(h0, h1);
        __nv_bfloat162 hp1 = __halves2bfloat162(h2, h3);
        __nv_bfloat162 lp0 = __halves2bfloat162(l0, l1);
        __nv_bfloat162 lp1 = __halves2bfloat162(l2, l3);
        *(uint2*)(oh + idx) = make_uint2(*(uint32_t*)&hp0, *(uint32_t*)&hp1);
        *(uint2*)(ol + idx) = make_uint2(*(uint32_t*)&lp0, *(uint32_t*)&lp1);
    }
}

// ---------------------------------------------------------------------------
// Launch
// ---------------------------------------------------------------------------
extern "C" void kernel_launch(void* const* d_in, const int* in_sizes, int n_in,
                              void* d_out, int out_size)
{
    const float* x_in  = (const float*)d_in[0];
    const int*   mask  = (const int*)  d_in[1];
    const float* ln1_g = (const float*)d_in[2];
    const float* ln1_b = (const float*)d_in[3];
    const float* qkv_w = (const float*)d_in[4];
    const float* out_w = (const float*)d_in[5];
    const float* out_b = (const float*)d_in[6];
    const float* ln2_g = (const float*)d_in[7];
    const float* ln2_b = (const float*)d_in[8];
    const float* ff1_w = (const float*)d_in[9];
    const float* ff1_b = (const float*)d_in[10];
    const float* ff2_w = (const float*)d_in[11];
    const float* ff2_b = (const float*)d_in[12];
    float* x = (float*)d_out;

    float* qkvb;
    bf16 *hh, *hl, *h2h, *h2l, *oh, *ol;
    bf16 *wqh, *wql, *woh, *wol, *wf1h, *wf1l, *wf2h, *wf2l;
    cudaGetSymbolAddress((void**)&qkvb, g_qkv);
    cudaGetSymbolAddress((void**)&hh,  g_hh);  cudaGetSymbolAddress((void**)&hl,  g_hl);
    cudaGetSymbolAddress((void**)&h2h, g_h2h); cudaGetSymbolAddress((void**)&h2l, g_h2l);
    cudaGetSymbolAddress((void**)&oh,  g_oh);  cudaGetSymbolAddress((void**)&ol,  g_ol);
    cudaGetSymbolAddress((void**)&wqh, g_wqkv_h); cudaGetSymbolAddress((void**)&wql, g_wqkv_l);
    cudaGetSymbolAddress((void**)&woh, g_wout_h); cudaGetSymbolAddress((void**)&wol, g_wout_l);
    cudaGetSymbolAddress((void**)&wf1h, g_wff1_h); cudaGetSymbolAddress((void**)&wf1l, g_wff1_l);
    cudaGetSymbolAddress((void**)&wf2h, g_wff2_h); cudaGetSymbolAddress((void**)&wf2l, g_wff2_l);

    cudaFuncSetAttribute(attn_kernel,
                         cudaFuncAttributeMaxDynamicSharedMemorySize, ATT_SMEM);

    // residual stream in d_out
    cudaMemcpyAsync(x, x_in, sizeof(float) * (size_t)TOK * DIMM,
                    cudaMemcpyDeviceToDevice);

    // weight conversion (once per launch)
    cvt_kernel<<<4096, 256>>>(qkv_w, wqh, wql, DEPTH * DIMM * 3 * INNER / 4);
    cvt_kernel<<<2048, 256>>>(out_w, woh, wol, DEPTH * INNER * DIMM / 4);
    cvt_kernel<<<4096, 256>>>(ff1_w, wf1h, wf1l, DEPTH * DIMM * MLPD / 4);
    cvt_kernel<<<4096, 256>>>(ff2_w, wf2h, wf2l, DEPTH * MLPD * DIMM / 4);

    for (int l = 0; l < DEPTH; ++l) {
        size_t wq = (size_t)l * DIMM * 3 * INNER;
        size_t wo = (size_t)l * INNER * DIMM;
        size_t w1 = (size_t)l * DIMM * MLPD;
        size_t w2 = (size_t)l * MLPD * DIMM;

        ln_kernel<<<TOK, 256>>>(x, ln1_g + (size_t)l * DIMM,
                                   ln1_b + (size_t)l * DIMM, hh, hl);
        mma_gemm<0><<<dim3(3 * INNER / 128, TOK / 128), 256>>>(
            hh, hl, wqh + wq, wql + wq, qkvb, nullptr, nullptr, nullptr,
            TOK, 3 * INNER, DIMM);
        attn_kernel<<<dim3(NN / 64, BB * HEADS), 256, ATT_SMEM>>>(qkvb, mask, oh, ol);
        mma_gemm<1><<<dim3(DIMM / 128, TOK / 128), 256>>>(
            oh, ol, woh + wo, wol + wo, x, out_b + (size_t)l * DIMM,
            nullptr, nullptr, TOK, DIMM, INNER);
        ln_kernel<<<TOK, 256>>>(x, ln2_g + (size_t)l * DIMM,
                                   ln2_b + (size_t)l * DIMM, hh, hl);
        mma_gemm<2><<<dim3(MLPD / 128, TOK / 128), 256>>>(
            hh, hl, wf1h + w1, wf1l + w1, nullptr, ff1_b + (size_t)l * MLPD,
            h2h, h2l, TOK, MLPD, DIMM);
        mma_gemm<1><<<dim3(DIMM / 128, TOK / 128), 256>>>(
            h2h, h2l, wf2h + w2, wf2l + w2, x, ff2_b + (size_t)l * DIMM,
            nullptr, nullptr, TOK, DIMM, MLPD);
    }
}

// round 8
// speedup vs baseline: 2.1924x; 1.0230x over previous
#include <cuda_runtime.h>
#include <cuda_bf16.h>
#include <math.h>
#include <stdint.h>

// Problem constants
#define BB     2
#define NN     1024
#define DIMM   1024
#define DEPTH  4
#define HEADS  16
#define DHEAD  64
#define INNER  1024
#define MLPD   4096
#define TOK    (BB*NN)       // 2048

typedef __nv_bfloat16 bf16;

// ---------------------------------------------------------------------------
// Scratch (no cudaMalloc allowed)
// ---------------------------------------------------------------------------
__device__ float g_qkv[TOK * 3 * INNER];          // fp32 QKV (attention input)

// bf16 hi/lo activations
__device__ bf16 g_hh [TOK * DIMM],  g_hl [TOK * DIMM];    // LN output
__device__ bf16 g_h2h[TOK * MLPD],  g_h2l[TOK * MLPD];    // GELU output
__device__ bf16 g_oh [TOK * INNER], g_ol [TOK * INNER];   // attention output

// bf16 hi/lo weights (converted once per launch)
__device__ bf16 g_wqkv_h[DEPTH * DIMM * 3 * INNER], g_wqkv_l[DEPTH * DIMM * 3 * INNER];
__device__ bf16 g_wout_h[DEPTH * INNER * DIMM],     g_wout_l[DEPTH * INNER * DIMM];
__device__ bf16 g_wff1_h[DEPTH * DIMM * MLPD],      g_wff1_l[DEPTH * DIMM * MLPD];
__device__ bf16 g_wff2_h[DEPTH * MLPD * DIMM],      g_wff2_l[DEPTH * MLPD * DIMM];

// ---------------------------------------------------------------------------
// Helpers
// ---------------------------------------------------------------------------
__device__ __forceinline__ uint32_t s2u(const void* p) {
    uint32_t a;
    asm("{ .reg .u64 t; cvta.to.shared.u64 t, %1; cvt.u32.u64 %0, t; }"
        : "=r"(a) : "l"(p));
    return a;
}

__device__ __forceinline__ void split1(float x, bf16& h, bf16& l) {
    h = __float2bfloat16(x);
    l = __float2bfloat16(x - __bfloat162float(h));
}

#define LDX4(r, addr) \
    asm volatile("ldmatrix.sync.aligned.m8n8.x4.shared.b16 {%0,%1,%2,%3}, [%4];" \
        : "=r"((r)[0]), "=r"((r)[1]), "=r"((r)[2]), "=r"((r)[3]) : "r"(addr))

#define LDX4T(r, addr) \
    asm volatile("ldmatrix.sync.aligned.m8n8.x4.trans.shared.b16 {%0,%1,%2,%3}, [%4];" \
        : "=r"((r)[0]), "=r"((r)[1]), "=r"((r)[2]), "=r"((r)[3]) : "r"(addr))

#define MMA(cd, a, b) \
    asm volatile("mma.sync.aligned.m16n8k16.row.col.f32.bf16.bf16.f32 " \
        "{%0,%1,%2,%3}, {%4,%5,%6,%7}, {%8,%9}, {%0,%1,%2,%3};" \
        : "+f"((cd)[0]), "+f"((cd)[1]), "+f"((cd)[2]), "+f"((cd)[3]) \
        : "r"((a)[0]), "r"((a)[1]), "r"((a)[2]), "r"((a)[3]), \
          "r"((b)[0]), "r"((b)[1]))

#define CP16(dst, src) \
    asm volatile("cp.async.cg.shared.global [%0], [%1], 16;" \
        :: "r"(dst), "l"(src) : "memory")

__device__ __forceinline__ float gelu1(float v) {
    return 0.5f * v * (1.f + erff(v * 0.70710678118654752f));
}

// ---------------------------------------------------------------------------
// fp32 -> bf16 hi/lo elementwise convert (grid-stride, float4)
// ---------------------------------------------------------------------------
__global__ void cvt_kernel(const float* __restrict__ in,
                           bf16* __restrict__ h, bf16* __restrict__ l, int n4)
{
    for (int i = blockIdx.x * blockDim.x + threadIdx.x; i < n4;
         i += gridDim.x * blockDim.x) {
        float4 v = ((const float4*)in)[i];
        bf16 h0, l0, h1, l1, h2, l2, h3, l3;
        split1(v.x, h0, l0); split1(v.y, h1, l1);
        split1(v.z, h2, l2); split1(v.w, h3, l3);
        __nv_bfloat162 hp0 = __halves2bfloat162(h0, h1);
        __nv_bfloat162 hp1 = __halves2bfloat162(h2, h3);
        __nv_bfloat162 lp0 = __halves2bfloat162(l0, l1);
        __nv_bfloat162 lp1 = __halves2bfloat162(l2, l3);
        ((uint2*)h)[i] = make_uint2(*(uint32_t*)&hp0, *(uint32_t*)&hp1);
        ((uint2*)l)[i] = make_uint2(*(uint32_t*)&lp0, *(uint32_t*)&lp1);
    }
}

// ---------------------------------------------------------------------------
// Tensor-core GEMM, bf16 hi/lo inputs, 3-term split MMA, fp32 accumulate.
// 128x128 tile/CTA, 256 threads (8 warps x 64x32), K-chunk 16,
// 3-stage cp.async ring, ONE __syncthreads per chunk.
// EPI: 0 plain fp32, 1 +bias+residual fp32 in-place, 2 +bias+GELU -> bf16 h/l
// ---------------------------------------------------------------------------
#define APITCH 24
#define BPITCH 136
#define AH_OFF 0
#define AL_OFF (128 * APITCH * 2)              // 6144
#define BH_OFF (2 * 128 * APITCH * 2)          // 12288
#define BL_OFF (BH_OFF + 16 * BPITCH * 2)      // 16640
#define STG_BYTES (BL_OFF + 16 * BPITCH * 2)   // 20992
#define NST 3
#define GEMM_SMEM (NST * STG_BYTES)            // 62976

template <int EPI>
__global__ __launch_bounds__(256, 2)
void mma_gemm(const bf16* __restrict__ Ah, const bf16* __restrict__ Al,
              const bf16* __restrict__ Bh, const bf16* __restrict__ Bl,
              float* __restrict__ C, const float* __restrict__ bias,
              bf16* __restrict__ Ch, bf16* __restrict__ Cl,
              int M, int Ncols, int K)
{
    extern __shared__ __align__(16) char smem[];
    const uint32_t sbase = s2u(smem);

    const int tid = threadIdx.x, lane = tid & 31, wid = tid >> 5;
    const int m0 = blockIdx.y * 128, n0 = blockIdx.x * 128;
    const int wm = (wid >> 2) * 64, wn = (wid & 3) * 32;

    // loader mapping
    const int ar = tid >> 1, ac = (tid & 1) * 8;     // A: row 0..127, k-col8
    const int bkr = tid >> 4, bn = (tid & 15) * 8;   // B: k-row 0..15, n-col8

    const bf16* agh = Ah + (size_t)(m0 + ar) * K + ac;
    const bf16* agl = Al + (size_t)(m0 + ar) * K + ac;
    const bf16* bgh = Bh + (size_t)bkr * Ncols + n0 + bn;
    const bf16* bgl = Bl + (size_t)bkr * Ncols + n0 + bn;

    const uint32_t wAh = sbase + AH_OFF + (ar * APITCH + ac) * 2;
    const uint32_t wAl = sbase + AL_OFF + (ar * APITCH + ac) * 2;
    const uint32_t wBh = sbase + BH_OFF + (bkr * BPITCH + bn) * 2;
    const uint32_t wBl = sbase + BL_OFF + (bkr * BPITCH + bn) * 2;

    float acc[4][4][4];
#pragma unroll
    for (int i = 0; i < 4; ++i)
#pragma unroll
        for (int j = 0; j < 4; ++j)
#pragma unroll
            for (int q = 0; q < 4; ++q) acc[i][j][q] = 0.f;

    // ldmatrix per-lane element offsets (relative to stage base)
    const uint32_t a_off = ((wm + (lane & 15)) * APITCH + (lane >> 4) * 8) * 2;
    const uint32_t b_off = ((lane & 15) * BPITCH + wn + (lane >> 4) * 8) * 2;

    const int NCH = K / 16;

    // prologue: stages 0 and 1
#pragma unroll
    for (int p = 0; p < 2; ++p) {
        uint32_t so = p * STG_BYTES;
        CP16(wAh + so, agh + p * 16);
        CP16(wAl + so, agl + p * 16);
        CP16(wBh + so, bgh + (size_t)p * 16 * Ncols);
        CP16(wBl + so, bgl + (size_t)p * 16 * Ncols);
        asm volatile("cp.async.commit_group;" ::: "memory");
    }

    int st = 0, wr = 2;
    for (int c = 0; c < NCH; ++c) {
        if (c + 1 < NCH)
            asm volatile("cp.async.wait_group 1;" ::: "memory");
        else
            asm volatile("cp.async.wait_group 0;" ::: "memory");
        __syncthreads();   // stage c landed; stage c-1 reads drained

        if (c + 2 < NCH) {
            uint32_t so = wr * STG_BYTES;
            CP16(wAh + so, agh + (c + 2) * 16);
            CP16(wAl + so, agl + (c + 2) * 16);
            CP16(wBh + so, bgh + (size_t)(c + 2) * 16 * Ncols);
            CP16(wBl + so, bgl + (size_t)(c + 2) * 16 * Ncols);
            asm volatile("cp.async.commit_group;" ::: "memory");
            wr = (wr + 1 == NST) ? 0 : wr + 1;
        }

        // fragments from stage st
        uint32_t bh[8], bl[8], ah[16], al[16];
        {
            uint32_t sb = sbase + st * STG_BYTES;
            uint32_t bb = sb + BH_OFF + b_off;
            uint32_t lb = sb + BL_OFF + b_off;
            LDX4T(bh + 0, bb);
            LDX4T(bh + 4, bb + 32);
            LDX4T(bl + 0, lb);
            LDX4T(bl + 4, lb + 32);
            uint32_t ab = sb + AH_OFF + a_off;
            uint32_t la = sb + AL_OFF + a_off;
#pragma unroll
            for (int mi = 0; mi < 4; ++mi) {
                LDX4(ah + mi * 4, ab + mi * 16 * APITCH * 2);
                LDX4(al + mi * 4, la + mi * 16 * APITCH * 2);
            }
        }

#pragma unroll
        for (int mi = 0; mi < 4; ++mi)
#pragma unroll
            for (int ni = 0; ni < 4; ++ni) {
                MMA(acc[mi][ni], ah + mi * 4, bh + ni * 2);
                MMA(acc[mi][ni], ah + mi * 4, bl + ni * 2);
                MMA(acc[mi][ni], al + mi * 4, bh + ni * 2);
            }
        st = (st + 1 == NST) ? 0 : st + 1;
    }

    // epilogue
#pragma unroll
    for (int mi = 0; mi < 4; ++mi) {
        int row = m0 + wm + mi * 16 + (lane >> 2);
#pragma unroll
        for (int ni = 0; ni < 4; ++ni) {
            int col = n0 + wn + ni * 8 + (lane & 3) * 2;
#pragma unroll
            for (int half = 0; half < 2; ++half) {
                int r = row + half * 8;
                float v0 = acc[mi][ni][half * 2 + 0];
                float v1 = acc[mi][ni][half * 2 + 1];
                size_t idx = (size_t)r * Ncols + col;
                if (EPI == 0) {
                    *(float2*)(C + idx) = make_float2(v0, v1);
                } else if (EPI == 1) {
                    float* cp = C + idx;
                    v0 += bias[col]     + cp[0];
                    v1 += bias[col + 1] + cp[1];
                    *(float2*)cp = make_float2(v0, v1);
                } else {
                    v0 = gelu1(v0 + bias[col]);
                    v1 = gelu1(v1 + bias[col + 1]);
                    bf16 h0, l0, h1, l1;
                    split1(v0, h0, l0);
                    split1(v1, h1, l1);
                    __nv_bfloat162 hp = __halves2bfloat162(h0, h1);
                    __nv_bfloat162 lp = __halves2bfloat162(l0, l1);
                    *(uint32_t*)(Ch + idx) = *(uint32_t*)&hp;
                    *(uint32_t*)(Cl + idx) = *(uint32_t*)&lp;
                }
            }
        }
    }
}

// ---------------------------------------------------------------------------
// LayerNorm: one block (256 thr) per token row, vectorized, bf16 hi/lo out
// ---------------------------------------------------------------------------
__global__ void ln_kernel(const float* __restrict__ x,
                          const float* __restrict__ g,
                          const float* __restrict__ b,
                          bf16* __restrict__ oh, bf16* __restrict__ ol)
{
    int row = blockIdx.x;
    int tid = threadIdx.x;
    int lane = tid & 31, wid = tid >> 5;
    __shared__ float red[8];
    __shared__ float bc[2];

    float4 v = *(const float4*)(x + (size_t)row * DIMM + tid * 4);

    float s = v.x + v.y + v.z + v.w;
#pragma unroll
    for (int o = 16; o > 0; o >>= 1) s += __shfl_xor_sync(~0u, s, o);
    if (lane == 0) red[wid] = s;
    __syncthreads();
    if (tid == 0) {
        float t = 0.f;
#pragma unroll
        for (int i = 0; i < 8; ++i) t += red[i];
        bc[0] = t * (1.f / DIMM);
    }
    __syncthreads();
    float mu = bc[0];

    float dx = v.x - mu, dy = v.y - mu, dz = v.z - mu, dw = v.w - mu;
    float s2 = dx * dx + dy * dy + dz * dz + dw * dw;
#pragma unroll
    for (int o = 16; o > 0; o >>= 1) s2 += __shfl_xor_sync(~0u, s2, o);
    if (lane == 0) red[wid] = s2;
    __syncthreads();
    if (tid == 0) {
        float t = 0.f;
#pragma unroll
        for (int i = 0; i < 8; ++i) t += red[i];
        bc[1] = rsqrtf(t * (1.f / DIMM) + 1e-5f);
    }
    __syncthreads();
    float rstd = bc[1];

    float4 gg = *(const float4*)(g + tid * 4);
    float4 bb = *(const float4*)(b + tid * 4);
    float o0 = dx * rstd * gg.x + bb.x;
    float o1 = dy * rstd * gg.y + bb.y;
    float o2 = dz * rstd * gg.z + bb.z;
    float o3 = dw * rstd * gg.w + bb.w;

    bf16 h0, l0, h1, l1, h2, l2, h3, l3;
    split1(o0, h0, l0); split1(o1, h1, l1);
    split1(o2, h2, l2); split1(o3, h3, l3);
    __nv_bfloat162 hp0 = __halves2bfloat162(h0, h1);
    __nv_bfloat162 hp1 = __halves2bfloat162(h2, h3);
    __nv_bfloat162 lp0 = __halves2bfloat162(l0, l1);
    __nv_bfloat162 lp1 = __halves2bfloat162(l2, l3);
    size_t idx = (size_t)row * DIMM + tid * 4;
    *(uint2*)(oh + idx) = make_uint2(*(uint32_t*)&hp0, *(uint32_t*)&hp1);
    *(uint2*)(ol + idx) = make_uint2(*(uint32_t*)&lp0, *(uint32_t*)&lp1);
}

// ---------------------------------------------------------------------------
// Fused attention (flash-style), fp32 compute, bf16 hi/lo output.
// Softmax parallelized: 4 threads per row.
// ---------------------------------------------------------------------------
#define ATT_SMEM (4 * 64 * 65 * 4)

__global__ __launch_bounds__(256)
void attn_kernel(const float* __restrict__ qkv,
                 const int* __restrict__ mask,
                 bf16* __restrict__ oh, bf16* __restrict__ ol)
{
    extern __shared__ float sm[];
    float* Qs = sm;
    float* Ks = Qs + 64 * 65;
    float* Vs = Ks + 64 * 65;
    float* Ss = Vs + 64 * 65;
    __shared__ float m_s[64], l_s[64], corr_s[64];

    int tid = threadIdx.x;
    int bh = blockIdx.y;
    int b  = bh >> 4;
    int h  = bh & 15;
    int q0 = blockIdx.x * 64;

    int tr = tid >> 4;
    int tc = tid & 15;
    const float scale = 0.125f;

    const float* qbase = qkv + ((size_t)(b * NN + q0)) * (3 * INNER) + h * DHEAD;
    for (int idx = tid; idx < 64 * 16; idx += 256) {
        int r = idx >> 4, c4 = (idx & 15) * 4;
        float4 v = *(const float4*)(qbase + (size_t)r * (3 * INNER) + c4);
        float* q = &Qs[r * 65 + c4];
        q[0] = v.x; q[1] = v.y; q[2] = v.z; q[3] = v.w;
    }
    if (tid < 64) { m_s[tid] = -INFINITY; l_s[tid] = 0.f; }

    float oacc[4][4];
#pragma unroll
    for (int i = 0; i < 4; ++i)
#pragma unroll
        for (int j = 0; j < 4; ++j) oacc[i][j] = 0.f;

    __syncthreads();

    for (int k0 = 0; k0 < NN; k0 += 64) {
        const float* kbase = qkv + ((size_t)(b * NN + k0)) * (3 * INNER) + INNER + h * DHEAD;
        const float* vbase = kbase + INNER;
        for (int idx = tid; idx < 64 * 16; idx += 256) {
            int r = idx >> 4, c4 = (idx & 15) * 4;
            float4 kv = *(const float4*)(kbase + (size_t)r * (3 * INNER) + c4);
            float4 vv = *(const float4*)(vbase + (size_t)r * (3 * INNER) + c4);
            float* kp = &Ks[r * 65 + c4];
            float* vp = &Vs[r * 65 + c4];
            kp[0] = kv.x; kp[1] = kv.y; kp[2] = kv.z; kp[3] = kv.w;
            vp[0] = vv.x; vp[1] = vv.y; vp[2] = vv.z; vp[3] = vv.w;
        }
        __syncthreads();

        float s[4][4] = {};
#pragma unroll 4
        for (int d = 0; d < 64; ++d) {
            float a[4], kk[4];
#pragma unroll
            for (int i = 0; i < 4; ++i) a[i]  = Qs[(tr * 4 + i) * 65 + d];
#pragma unroll
            for (int j = 0; j < 4; ++j) kk[j] = Ks[(tc * 4 + j) * 65 + d];
#pragma unroll
            for (int i = 0; i < 4; ++i)
#pragma unroll
                for (int j = 0; j < 4; ++j)
                    s[i][j] += a[i] * kk[j];
        }

#pragma unroll
        for (int i = 0; i < 4; ++i) {
            int qrow = q0 + tr * 4 + i;
            const int* mrow = mask + ((size_t)b * NN + qrow) * NN + k0;
#pragma unroll
            for (int j = 0; j < 4; ++j) {
                float v = s[i][j] * scale;
                if (mrow[tc * 4 + j] == 0) v = -1e9f;
                Ss[(tr * 4 + i) * 65 + tc * 4 + j] = v;
            }
        }
        __syncthreads();

        // Online softmax: 4 threads per row
        {
            int r = tid >> 2, q = tid & 3;
            float* row = &Ss[r * 65 + q * 16];
            float mx = m_s[r];
            float tmax = -INFINITY;
#pragma unroll
            for (int j = 0; j < 16; ++j) tmax = fmaxf(tmax, row[j]);
            tmax = fmaxf(tmax, __shfl_xor_sync(~0u, tmax, 1));
            tmax = fmaxf(tmax, __shfl_xor_sync(~0u, tmax, 2));
            float nm = fmaxf(mx, tmax);
            float sum = 0.f;
#pragma unroll
            for (int j = 0; j < 16; ++j) {
                float p = __expf(row[j] - nm);
                row[j] = p;
                sum += p;
            }
            sum += __shfl_xor_sync(~0u, sum, 1);
            sum += __shfl_xor_sync(~0u, sum, 2);
            if (q == 0) {
                float corr = __expf(mx - nm);
                m_s[r] = nm;
                l_s[r] = l_s[r] * corr + sum;
                corr_s[r] = corr;
            }
        }
        __syncthreads();

#pragma unroll
        for (int i = 0; i < 4; ++i) {
            float corr = corr_s[tr * 4 + i];
#pragma unroll
            for (int j = 0; j < 4; ++j) oacc[i][j] *= corr;
        }
#pragma unroll 4
        for (int j = 0; j < 64; ++j) {
            float p[4], v[4];
#pragma unroll
            for (int i = 0; i < 4; ++i) p[i] = Ss[(tr * 4 + i) * 65 + j];
#pragma unroll
            for (int c = 0; c < 4; ++c) v[c] = Vs[j * 65 + tc * 4 + c];
#pragma unroll
            for (int i = 0; i < 4; ++i)
#pragma unroll
                for (int c = 0; c < 4; ++c)
                    oacc[i][c] += p[i] * v[c];
        }
        __syncthreads();
    }

#pragma unroll
    for (int i = 0; i < 4; ++i) {
        int r = tr * 4 + i;
        float inv = 1.f / l_s[r];
        size_t idx = ((size_t)(b * NN + q0 + r)) * INNER + h * DHEAD + tc * 4;
        float o0 = oacc[i][0] * inv, o1 = oacc[i][1] * inv;
        float o2 = oacc[i][2] * inv, o3 = oacc[i][3] * inv;
        bf16 h0, l0, h1, l1, h2, l2, h3, l3;
        split1(o0, h0, l0); split1(o1, h1, l1);
        split1(o2, h2, l2); split1(o3, h3, l3);
        __nv_bfloat162 hp0 = __halves2bfloat162(h0, h1);
        __nv_bfloat162 hp1 = __halves2bfloat162(h2, h3);
        __nv_bfloat162 lp0 = __halves2bfloat162(l0, l1);
        __nv_bfloat162 lp1 = __halves2bfloat162(l2, l3);
        *(uint2*)(oh + idx) = make_uint2(*(uint32_t*)&hp0, *(uint32_t*)&hp1);
        *(uint2*)(ol + idx) = make_uint2(*(uint32_t*)&lp0, *(uint32_t*)&lp1);
    }
}

// ---------------------------------------------------------------------------
// Launch
// ---------------------------------------------------------------------------
extern "C" void kernel_launch(void* const* d_in, const int* in_sizes, int n_in,
                              void* d_out, int out_size)
{
    const float* x_in  = (const float*)d_in[0];
    const int*   mask  = (const int*)  d_in[1];
    const float* ln1_g = (const float*)d_in[2];
    const float* ln1_b = (const float*)d_in[3];
    const float* qkv_w = (const float*)d_in[4];
    const float* out_w = (const float*)d_in[5];
    const float* out_b = (const float*)d_in[6];
    const float* ln2_g = (const float*)d_in[7];
    const float* ln2_b = (const float*)d_in[8];
    const float* ff1_w = (const float*)d_in[9];
    const float* ff1_b = (const float*)d_in[10];
    const float* ff2_w = (const float*)d_in[11];
    const float* ff2_b = (const float*)d_in[12];
    float* x = (float*)d_out;

    float* qkvb;
    bf16 *hh, *hl, *h2h, *h2l, *oh, *ol;
    bf16 *wqh, *wql, *woh, *wol, *wf1h, *wf1l, *wf2h, *wf2l;
    cudaGetSymbolAddress((void**)&qkvb, g_qkv);
    cudaGetSymbolAddress((void**)&hh,  g_hh);  cudaGetSymbolAddress((void**)&hl,  g_hl);
    cudaGetSymbolAddress((void**)&h2h, g_h2h); cudaGetSymbolAddress((void**)&h2l, g_h2l);
    cudaGetSymbolAddress((void**)&oh,  g_oh);  cudaGetSymbolAddress((void**)&ol,  g_ol);
    cudaGetSymbolAddress((void**)&wqh, g_wqkv_h); cudaGetSymbolAddress((void**)&wql, g_wqkv_l);
    cudaGetSymbolAddress((void**)&woh, g_wout_h); cudaGetSymbolAddress((void**)&wol, g_wout_l);
    cudaGetSymbolAddress((void**)&wf1h, g_wff1_h); cudaGetSymbolAddress((void**)&wf1l, g_wff1_l);
    cudaGetSymbolAddress((void**)&wf2h, g_wff2_h); cudaGetSymbolAddress((void**)&wf2l, g_wff2_l);

    cudaFuncSetAttribute(attn_kernel,
                         cudaFuncAttributeMaxDynamicSharedMemorySize, ATT_SMEM);
    cudaFuncSetAttribute(mma_gemm<0>,
                         cudaFuncAttributeMaxDynamicSharedMemorySize, GEMM_SMEM);
    cudaFuncSetAttribute(mma_gemm<1>,
                         cudaFuncAttributeMaxDynamicSharedMemorySize, GEMM_SMEM);
    cudaFuncSetAttribute(mma_gemm<2>,
                         cudaFuncAttributeMaxDynamicSharedMemorySize, GEMM_SMEM);

    // residual stream in d_out
    cudaMemcpyAsync(x, x_in, sizeof(float) * (size_t)TOK * DIMM,
                    cudaMemcpyDeviceToDevice);

    // weight conversion (once per launch)
    cvt_kernel<<<4096, 256>>>(qkv_w, wqh, wql, DEPTH * DIMM * 3 * INNER / 4);
    cvt_kernel<<<2048, 256>>>(out_w, woh, wol, DEPTH * INNER * DIMM / 4);
    cvt_kernel<<<4096, 256>>>(ff1_w, wf1h, wf1l, DEPTH * DIMM * MLPD / 4);
    cvt_kernel<<<4096, 256>>>(ff2_w, wf2h, wf2l, DEPTH * MLPD * DIMM / 4);

    for (int l = 0; l < DEPTH; ++l) {
        size_t wq = (size_t)l * DIMM * 3 * INNER;
        size_t wo = (size_t)l * INNER * DIMM;
        size_t w1 = (size_t)l * DIMM * MLPD;
        size_t w2 = (size_t)l * MLPD * DIMM;

        ln_kernel<<<TOK, 256>>>(x, ln1_g + (size_t)l * DIMM,
                                   ln1_b + (size_t)l * DIMM, hh, hl);
        mma_gemm<0><<<dim3(3 * INNER / 128, TOK / 128), 256, GEMM_SMEM>>>(
            hh, hl, wqh + wq, wql + wq, qkvb, nullptr, nullptr, nullptr,
            TOK, 3 * INNER, DIMM);
        attn_kernel<<<dim3(NN / 64, BB * HEADS), 256, ATT_SMEM>>>(qkvb, mask, oh, ol);
        mma_gemm<1><<<dim3(DIMM / 128, TOK / 128), 256, GEMM_SMEM>>>(
            oh, ol, woh + wo, wol + wo, x, out_b + (size_t)l * DIMM,
            nullptr, nullptr, TOK, DIMM, INNER);
        ln_kernel<<<TOK, 256>>>(x, ln2_g + (size_t)l * DIMM,
                                   ln2_b + (size_t)l * DIMM, hh, hl);
        mma_gemm<2><<<dim3(MLPD / 128, TOK / 128), 256, GEMM_SMEM>>>(
            hh, hl, wf1h + w1, wf1l + w1, nullptr, ff1_b + (size_t)l * MLPD,
            h2h, h2l, TOK, MLPD, DIMM);
        mma_gemm<1><<<dim3(DIMM / 128, TOK / 128), 256, GEMM_SMEM>>>(
            h2h, h2l, wf2h + w2, wf2l + w2, x, ff2_b + (size_t)l * DIMM,
            nullptr, nullptr, TOK, DIMM, MLPD);
    }
}

// round 9
// speedup vs baseline: 2.3340x; 1.0646x over previous
#include <cuda_runtime.h>
#include <cuda_bf16.h>
#include <math.h>
#include <stdint.h>

// Problem constants
#define BB     2
#define NN     1024
#define DIMM   1024
#define DEPTH  4
#define HEADS  16
#define DHEAD  64
#define INNER  1024
#define MLPD   4096
#define TOK    (BB*NN)       // 2048

typedef __nv_bfloat16 bf16;

// ---------------------------------------------------------------------------
// Scratch (no cudaMalloc allowed)
// ---------------------------------------------------------------------------
__device__ float g_qkv[TOK * 3 * INNER];          // fp32 QKV (attention input)
__device__ float g_part[4 * TOK * DIMM];          // split-K partials (32 MB)

// bf16 hi/lo activations
__device__ bf16 g_hh [TOK * DIMM],  g_hl [TOK * DIMM];    // LN output
__device__ bf16 g_h2h[TOK * MLPD],  g_h2l[TOK * MLPD];    // GELU output
__device__ bf16 g_oh [TOK * INNER], g_ol [TOK * INNER];   // attention output

// bf16 hi/lo weights (converted once per launch)
__device__ bf16 g_wqkv_h[DEPTH * DIMM * 3 * INNER], g_wqkv_l[DEPTH * DIMM * 3 * INNER];
__device__ bf16 g_wout_h[DEPTH * INNER * DIMM],     g_wout_l[DEPTH * INNER * DIMM];
__device__ bf16 g_wff1_h[DEPTH * DIMM * MLPD],      g_wff1_l[DEPTH * DIMM * MLPD];
__device__ bf16 g_wff2_h[DEPTH * MLPD * DIMM],      g_wff2_l[DEPTH * MLPD * DIMM];

// ---------------------------------------------------------------------------
// Helpers
// ---------------------------------------------------------------------------
__device__ __forceinline__ uint32_t s2u(const void* p) {
    uint32_t a;
    asm("{ .reg .u64 t; cvta.to.shared.u64 t, %1; cvt.u32.u64 %0, t; }"
        : "=r"(a) : "l"(p));
    return a;
}

__device__ __forceinline__ void split1(float x, bf16& h, bf16& l) {
    h = __float2bfloat16(x);
    l = __float2bfloat16(x - __bfloat162float(h));
}

#define LDX4(r, addr) \
    asm volatile("ldmatrix.sync.aligned.m8n8.x4.shared.b16 {%0,%1,%2,%3}, [%4];" \
        : "=r"((r)[0]), "=r"((r)[1]), "=r"((r)[2]), "=r"((r)[3]) : "r"(addr))

#define LDX4T(r, addr) \
    asm volatile("ldmatrix.sync.aligned.m8n8.x4.trans.shared.b16 {%0,%1,%2,%3}, [%4];" \
        : "=r"((r)[0]), "=r"((r)[1]), "=r"((r)[2]), "=r"((r)[3]) : "r"(addr))

#define MMA(cd, a, b) \
    asm volatile("mma.sync.aligned.m16n8k16.row.col.f32.bf16.bf16.f32 " \
        "{%0,%1,%2,%3}, {%4,%5,%6,%7}, {%8,%9}, {%0,%1,%2,%3};" \
        : "+f"((cd)[0]), "+f"((cd)[1]), "+f"((cd)[2]), "+f"((cd)[3]) \
        : "r"((a)[0]), "r"((a)[1]), "r"((a)[2]), "r"((a)[3]), \
          "r"((b)[0]), "r"((b)[1]))

#define CP16(dst, src) \
    asm volatile("cp.async.cg.shared.global [%0], [%1], 16;" \
        :: "r"(dst), "l"(src) : "memory")

__device__ __forceinline__ float gelu1(float v) {
    return 0.5f * v * (1.f + erff(v * 0.70710678118654752f));
}

// ---------------------------------------------------------------------------
// fp32 -> bf16 hi/lo elementwise convert (grid-stride, float4)
// ---------------------------------------------------------------------------
__global__ void cvt_kernel(const float* __restrict__ in,
                           bf16* __restrict__ h, bf16* __restrict__ l, int n4)
{
    for (int i = blockIdx.x * blockDim.x + threadIdx.x; i < n4;
         i += gridDim.x * blockDim.x) {
        float4 v = ((const float4*)in)[i];
        bf16 h0, l0, h1, l1, h2, l2, h3, l3;
        split1(v.x, h0, l0); split1(v.y, h1, l1);
        split1(v.z, h2, l2); split1(v.w, h3, l3);
        __nv_bfloat162 hp0 = __halves2bfloat162(h0, h1);
        __nv_bfloat162 hp1 = __halves2bfloat162(h2, h3);
        __nv_bfloat162 lp0 = __halves2bfloat162(l0, l1);
        __nv_bfloat162 lp1 = __halves2bfloat162(l2, l3);
        ((uint2*)h)[i] = make_uint2(*(uint32_t*)&hp0, *(uint32_t*)&hp1);
        ((uint2*)l)[i] = make_uint2(*(uint32_t*)&lp0, *(uint32_t*)&lp1);
    }
}

// ---------------------------------------------------------------------------
// Split-K reduce: x[i] += bias[col] + sum_p part[p][i]   (fixed order, det.)
// ---------------------------------------------------------------------------
template <int NP>
__global__ void reduce_kernel(float* __restrict__ x,
                              const float* __restrict__ bias,
                              const float* __restrict__ part, int n4)
{
    int i = blockIdx.x * blockDim.x + threadIdx.x;
    if (i >= n4) return;
    float4 v = ((const float4*)x)[i];
    float4 b = ((const float4*)bias)[i & (DIMM / 4 - 1)];
    v.x += b.x; v.y += b.y; v.z += b.z; v.w += b.w;
#pragma unroll
    for (int p = 0; p < NP; ++p) {
        float4 pv = ((const float4*)(part + (size_t)p * TOK * DIMM))[i];
        v.x += pv.x; v.y += pv.y; v.z += pv.z; v.w += pv.w;
    }
    ((float4*)x)[i] = v;
}

// ---------------------------------------------------------------------------
// Tensor-core GEMM, bf16 hi/lo inputs, 3-term split MMA, fp32 accumulate.
// 128x128 tile/CTA, 256 threads (8 warps x 64x32), K-chunk 16,
// 3-stage cp.async ring, one __syncthreads per chunk.
// blockIdx.z = split-K slice (A col-offset z*Kpart, C offset z*M*Ncols).
// EPI: 0 plain fp32 store, 2 +bias+GELU -> bf16 hi/lo outputs.
// ---------------------------------------------------------------------------
#define APITCH 24
#define BPITCH 136
#define AH_OFF 0
#define AL_OFF (128 * APITCH * 2)              // 6144
#define BH_OFF (2 * 128 * APITCH * 2)          // 12288
#define BL_OFF (BH_OFF + 16 * BPITCH * 2)      // 16640
#define STG_BYTES (BL_OFF + 16 * BPITCH * 2)   // 20992
#define NST 3
#define GEMM_SMEM (NST * STG_BYTES)            // 62976

template <int EPI>
__global__ __launch_bounds__(256, 2)
void mma_gemm(const bf16* __restrict__ Ah, const bf16* __restrict__ Al,
              const bf16* __restrict__ Bh, const bf16* __restrict__ Bl,
              float* __restrict__ C, const float* __restrict__ bias,
              bf16* __restrict__ Ch, bf16* __restrict__ Cl,
              int M, int Ncols, int lda, int Kpart)
{
    extern __shared__ __align__(16) char smem[];
    const uint32_t sbase = s2u(smem);

    const int tid = threadIdx.x, lane = tid & 31, wid = tid >> 5;
    const int m0 = blockIdx.y * 128, n0 = blockIdx.x * 128;
    const int wm = (wid >> 2) * 64, wn = (wid & 3) * 32;
    const int koff = blockIdx.z * Kpart;
    C += (size_t)blockIdx.z * M * Ncols;

    // loader mapping
    const int ar = tid >> 1, ac = (tid & 1) * 8;     // A: row 0..127, k-col8
    const int bkr = tid >> 4, bn = (tid & 15) * 8;   // B: k-row 0..15, n-col8

    const bf16* agh = Ah + (size_t)(m0 + ar) * lda + koff + ac;
    const bf16* agl = Al + (size_t)(m0 + ar) * lda + koff + ac;
    const bf16* bgh = Bh + (size_t)(koff + bkr) * Ncols + n0 + bn;
    const bf16* bgl = Bl + (size_t)(koff + bkr) * Ncols + n0 + bn;

    const uint32_t wAh = sbase + AH_OFF + (ar * APITCH + ac) * 2;
    const uint32_t wAl = sbase + AL_OFF + (ar * APITCH + ac) * 2;
    const uint32_t wBh = sbase + BH_OFF + (bkr * BPITCH + bn) * 2;
    const uint32_t wBl = sbase + BL_OFF + (bkr * BPITCH + bn) * 2;

    float acc[4][4][4];
#pragma unroll
    for (int i = 0; i < 4; ++i)
#pragma unroll
        for (int j = 0; j < 4; ++j)
#pragma unroll
            for (int q = 0; q < 4; ++q) acc[i][j][q] = 0.f;

    // ldmatrix per-lane element offsets (relative to stage base)
    const uint32_t a_off = ((wm + (lane & 15)) * APITCH + (lane >> 4) * 8) * 2;
    const uint32_t b_off = ((lane & 15) * BPITCH + wn + (lane >> 4) * 8) * 2;

    const int NCH = Kpart / 16;

    // prologue: stages 0 and 1
#pragma unroll
    for (int p = 0; p < 2; ++p) {
        uint32_t so = p * STG_BYTES;
        CP16(wAh + so, agh + p * 16);
        CP16(wAl + so, agl + p * 16);
        CP16(wBh + so, bgh + (size_t)p * 16 * Ncols);
        CP16(wBl + so, bgl + (size_t)p * 16 * Ncols);
        asm volatile("cp.async.commit_group;" ::: "memory");
    }

    int st = 0, wr = 2;
    for (int c = 0; c < NCH; ++c) {
        if (c + 1 < NCH)
            asm volatile("cp.async.wait_group 1;" ::: "memory");
        else
            asm volatile("cp.async.wait_group 0;" ::: "memory");
        __syncthreads();

        if (c + 2 < NCH) {
            uint32_t so = wr * STG_BYTES;
            CP16(wAh + so, agh + (c + 2) * 16);
            CP16(wAl + so, agl + (c + 2) * 16);
            CP16(wBh + so, bgh + (size_t)(c + 2) * 16 * Ncols);
            CP16(wBl + so, bgl + (size_t)(c + 2) * 16 * Ncols);
            asm volatile("cp.async.commit_group;" ::: "memory");
            wr = (wr + 1 == NST) ? 0 : wr + 1;
        }

        uint32_t sb = sbase + st * STG_BYTES;
        // B fragments (kept live across all mi)
        uint32_t bh[8], bl[8];
        {
            uint32_t bb = sb + BH_OFF + b_off;
            uint32_t lb = sb + BL_OFF + b_off;
            LDX4T(bh + 0, bb);
            LDX4T(bh + 4, bb + 32);
            LDX4T(bl + 0, lb);
            LDX4T(bl + 4, lb + 32);
        }
        uint32_t ab = sb + AH_OFF + a_off;
        uint32_t la = sb + AL_OFF + a_off;
        // A fragments loaded per-mi (8 live regs instead of 32)
#pragma unroll
        for (int mi = 0; mi < 4; ++mi) {
            uint32_t ah[4], al[4];
            LDX4(ah, ab + mi * 16 * APITCH * 2);
            LDX4(al, la + mi * 16 * APITCH * 2);
#pragma unroll
            for (int ni = 0; ni < 4; ++ni) {
                MMA(acc[mi][ni], ah, bh + ni * 2);
                MMA(acc[mi][ni], ah, bl + ni * 2);
                MMA(acc[mi][ni], al, bh + ni * 2);
            }
        }
        st = (st + 1 == NST) ? 0 : st + 1;
    }

    // epilogue
#pragma unroll
    for (int mi = 0; mi < 4; ++mi) {
        int row = m0 + wm + mi * 16 + (lane >> 2);
#pragma unroll
        for (int ni = 0; ni < 4; ++ni) {
            int col = n0 + wn + ni * 8 + (lane & 3) * 2;
#pragma unroll
            for (int half = 0; half < 2; ++half) {
                int r = row + half * 8;
                float v0 = acc[mi][ni][half * 2 + 0];
                float v1 = acc[mi][ni][half * 2 + 1];
                size_t idx = (size_t)r * Ncols + col;
                if (EPI == 0) {
                    *(float2*)(C + idx) = make_float2(v0, v1);
                } else {
                    v0 = gelu1(v0 + bias[col]);
                    v1 = gelu1(v1 + bias[col + 1]);
                    bf16 h0, l0, h1, l1;
                    split1(v0, h0, l0);
                    split1(v1, h1, l1);
                    __nv_bfloat162 hp = __halves2bfloat162(h0, h1);
                    __nv_bfloat162 lp = __halves2bfloat162(l0, l1);
                    *(uint32_t*)(Ch + idx) = *(uint32_t*)&hp;
                    *(uint32_t*)(Cl + idx) = *(uint32_t*)&lp;
                }
            }
        }
    }
}

// ---------------------------------------------------------------------------
// LayerNorm: one block (256 thr) per token row, vectorized, bf16 hi/lo out
// ---------------------------------------------------------------------------
__global__ void ln_kernel(const float* __restrict__ x,
                          const float* __restrict__ g,
                          const float* __restrict__ b,
                          bf16* __restrict__ oh, bf16* __restrict__ ol)
{
    int row = blockIdx.x;
    int tid = threadIdx.x;
    int lane = tid & 31, wid = tid >> 5;
    __shared__ float red[8];
    __shared__ float bc[2];

    float4 v = *(const float4*)(x + (size_t)row * DIMM + tid * 4);

    float s = v.x + v.y + v.z + v.w;
#pragma unroll
    for (int o = 16; o > 0; o >>= 1) s += __shfl_xor_sync(~0u, s, o);
    if (lane == 0) red[wid] = s;
    __syncthreads();
    if (tid == 0) {
        float t = 0.f;
#pragma unroll
        for (int i = 0; i < 8; ++i) t += red[i];
        bc[0] = t * (1.f / DIMM);
    }
    __syncthreads();
    float mu = bc[0];

    float dx = v.x - mu, dy = v.y - mu, dz = v.z - mu, dw = v.w - mu;
    float s2 = dx * dx + dy * dy + dz * dz + dw * dw;
#pragma unroll
    for (int o = 16; o > 0; o >>= 1) s2 += __shfl_xor_sync(~0u, s2, o);
    if (lane == 0) red[wid] = s2;
    __syncthreads();
    if (tid == 0) {
        float t = 0.f;
#pragma unroll
        for (int i = 0; i < 8; ++i) t += red[i];
        bc[1] = rsqrtf(t * (1.f / DIMM) + 1e-5f);
    }
    __syncthreads();
    float rstd = bc[1];

    float4 gg = *(const float4*)(g + tid * 4);
    float4 bb = *(const float4*)(b + tid * 4);
    float o0 = dx * rstd * gg.x + bb.x;
    float o1 = dy * rstd * gg.y + bb.y;
    float o2 = dz * rstd * gg.z + bb.z;
    float o3 = dw * rstd * gg.w + bb.w;

    bf16 h0, l0, h1, l1, h2, l2, h3, l3;
    split1(o0, h0, l0); split1(o1, h1, l1);
    split1(o2, h2, l2); split1(o3, h3, l3);
    __nv_bfloat162 hp0 = __halves2bfloat162(h0, h1);
    __nv_bfloat162 hp1 = __halves2bfloat162(h2, h3);
    __nv_bfloat162 lp0 = __halves2bfloat162(l0, l1);
    __nv_bfloat162 lp1 = __halves2bfloat162(l2, l3);
    size_t idx = (size_t)row * DIMM + tid * 4;
    *(uint2*)(oh + idx) = make_uint2(*(uint32_t*)&hp0, *(uint32_t*)&hp1);
    *(uint2*)(ol + idx) = make_uint2(*(uint32_t*)&lp0, *(uint32_t*)&lp1);
}

// ---------------------------------------------------------------------------
// Fused attention (flash-style), fp32 compute, bf16 hi/lo output.
// ---------------------------------------------------------------------------
#define ATT_SMEM (4 * 64 * 65 * 4)

__global__ __launch_bounds__(256)
void attn_kernel(const float* __restrict__ qkv,
                 const int* __restrict__ mask,
                 bf16* __restrict__ oh, bf16* __restrict__ ol)
{
    extern __shared__ float sm[];
    float* Qs = sm;
    float* Ks = Qs + 64 * 65;
    float* Vs = Ks + 64 * 65;
    float* Ss = Vs + 64 * 65;
    __shared__ float m_s[64], l_s[64], corr_s[64];

    int tid = threadIdx.x;
    int bh = blockIdx.y;
    int b  = bh >> 4;
    int h  = bh & 15;
    int q0 = blockIdx.x * 64;

    int tr = tid >> 4;
    int tc = tid & 15;
    const float scale = 0.125f;

    const float* qbase = qkv + ((size_t)(b * NN + q0)) * (3 * INNER) + h * DHEAD;
    for (int idx = tid; idx < 64 * 16; idx += 256) {
        int r = idx >> 4, c4 = (idx & 15) * 4;
        float4 v = *(const float4*)(qbase + (size_t)r * (3 * INNER) + c4);
        float* q = &Qs[r * 65 + c4];
        q[0] = v.x; q[1] = v.y; q[2] = v.z; q[3] = v.w;
    }
    if (tid < 64) { m_s[tid] = -INFINITY; l_s[tid] = 0.f; }

    float oacc[4][4];
#pragma unroll
    for (int i = 0; i < 4; ++i)
#pragma unroll
        for (int j = 0; j < 4; ++j) oacc[i][j] = 0.f;

    __syncthreads();

    for (int k0 = 0; k0 < NN; k0 += 64) {
        const float* kbase = qkv + ((size_t)(b * NN + k0)) * (3 * INNER) + INNER + h * DHEAD;
        const float* vbase = kbase + INNER;
        for (int idx = tid; idx < 64 * 16; idx += 256) {
            int r = idx >> 4, c4 = (idx & 15) * 4;
            float4 kv = *(const float4*)(kbase + (size_t)r * (3 * INNER) + c4);
            float4 vv = *(const float4*)(vbase + (size_t)r * (3 * INNER) + c4);
            float* kp = &Ks[r * 65 + c4];
            float* vp = &Vs[r * 65 + c4];
            kp[0] = kv.x; kp[1] = kv.y; kp[2] = kv.z; kp[3] = kv.w;
            vp[0] = vv.x; vp[1] = vv.y; vp[2] = vv.z; vp[3] = vv.w;
        }
        __syncthreads();

        float s[4][4] = {};
#pragma unroll 4
        for (int d = 0; d < 64; ++d) {
            float a[4], kk[4];
#pragma unroll
            for (int i = 0; i < 4; ++i) a[i]  = Qs[(tr * 4 + i) * 65 + d];
#pragma unroll
            for (int j = 0; j < 4; ++j) kk[j] = Ks[(tc * 4 + j) * 65 + d];
#pragma unroll
            for (int i = 0; i < 4; ++i)
#pragma unroll
                for (int j = 0; j < 4; ++j)
                    s[i][j] += a[i] * kk[j];
        }

#pragma unroll
        for (int i = 0; i < 4; ++i) {
            int qrow = q0 + tr * 4 + i;
            const int* mrow = mask + ((size_t)b * NN + qrow) * NN + k0;
#pragma unroll
            for (int j = 0; j < 4; ++j) {
                float v = s[i][j] * scale;
                if (mrow[tc * 4 + j] == 0) v = -1e9f;
                Ss[(tr * 4 + i) * 65 + tc * 4 + j] = v;
            }
        }
        __syncthreads();

        // Online softmax: 4 threads per row
        {
            int r = tid >> 2, q = tid & 3;
            float* row = &Ss[r * 65 + q * 16];
            float mx = m_s[r];
            float tmax = -INFINITY;
#pragma unroll
            for (int j = 0; j < 16; ++j) tmax = fmaxf(tmax, row[j]);
            tmax = fmaxf(tmax, __shfl_xor_sync(~0u, tmax, 1));
            tmax = fmaxf(tmax, __shfl_xor_sync(~0u, tmax, 2));
            float nm = fmaxf(mx, tmax);
            float sum = 0.f;
#pragma unroll
            for (int j = 0; j < 16; ++j) {
                float p = __expf(row[j] - nm);
                row[j] = p;
                sum += p;
            }
            sum += __shfl_xor_sync(~0u, sum, 1);
            sum += __shfl_xor_sync(~0u, sum, 2);
            if (q == 0) {
                float corr = __expf(mx - nm);
                m_s[r] = nm;
                l_s[r] = l_s[r] * corr + sum;
                corr_s[r] = corr;
            }
        }
        __syncthreads();

#pragma unroll
        for (int i = 0; i < 4; ++i) {
            float corr = corr_s[tr * 4 + i];
#pragma unroll
            for (int j = 0; j < 4; ++j) oacc[i][j] *= corr;
        }
#pragma unroll 4
        for (int j = 0; j < 64; ++j) {
            float p[4], v[4];
#pragma unroll
            for (int i = 0; i < 4; ++i) p[i] = Ss[(tr * 4 + i) * 65 + j];
#pragma unroll
            for (int c = 0; c < 4; ++c) v[c] = Vs[j * 65 + tc * 4 + c];
#pragma unroll
            for (int i = 0; i < 4; ++i)
#pragma unroll
                for (int c = 0; c < 4; ++c)
                    oacc[i][c] += p[i] * v[c];
        }
        __syncthreads();
    }

#pragma unroll
    for (int i = 0; i < 4; ++i) {
        int r = tr * 4 + i;
        float inv = 1.f / l_s[r];
        size_t idx = ((size_t)(b * NN + q0 + r)) * INNER + h * DHEAD + tc * 4;
        float o0 = oacc[i][0] * inv, o1 = oacc[i][1] * inv;
        float o2 = oacc[i][2] * inv, o3 = oacc[i][3] * inv;
        bf16 h0, l0, h1, l1, h2, l2, h3, l3;
        split1(o0, h0, l0); split1(o1, h1, l1);
        split1(o2, h2, l2); split1(o3, h3, l3);
        __nv_bfloat162 hp0 = __halves2bfloat162(h0, h1);
        __nv_bfloat162 hp1 = __halves2bfloat162(h2, h3);
        __nv_bfloat162 lp0 = __halves2bfloat162(l0, l1);
        __nv_bfloat162 lp1 = __halves2bfloat162(l2, l3);
        *(uint2*)(oh + idx) = make_uint2(*(uint32_t*)&hp0, *(uint32_t*)&hp1);
        *(uint2*)(ol + idx) = make_uint2(*(uint32_t*)&lp0, *(uint32_t*)&lp1);
    }
}

// ---------------------------------------------------------------------------
// Launch
// ---------------------------------------------------------------------------
extern "C" void kernel_launch(void* const* d_in, const int* in_sizes, int n_in,
                              void* d_out, int out_size)
{
    const float* x_in  = (const float*)d_in[0];
    const int*   mask  = (const int*)  d_in[1];
    const float* ln1_g = (const float*)d_in[2];
    const float* ln1_b = (const float*)d_in[3];
    const float* qkv_w = (const float*)d_in[4];
    const float* out_w = (const float*)d_in[5];
    const float* out_b = (const float*)d_in[6];
    const float* ln2_g = (const float*)d_in[7];
    const float* ln2_b = (const float*)d_in[8];
    const float* ff1_w = (const float*)d_in[9];
    const float* ff1_b = (const float*)d_in[10];
    const float* ff2_w = (const float*)d_in[11];
    const float* ff2_b = (const float*)d_in[12];
    float* x = (float*)d_out;

    float *qkvb, *part;
    bf16 *hh, *hl, *h2h, *h2l, *oh, *ol;
    bf16 *wqh, *wql, *woh, *wol, *wf1h, *wf1l, *wf2h, *wf2l;
    cudaGetSymbolAddress((void**)&qkvb, g_qkv);
    cudaGetSymbolAddress((void**)&part, g_part);
    cudaGetSymbolAddress((void**)&hh,  g_hh);  cudaGetSymbolAddress((void**)&hl,  g_hl);
    cudaGetSymbolAddress((void**)&h2h, g_h2h); cudaGetSymbolAddress((void**)&h2l, g_h2l);
    cudaGetSymbolAddress((void**)&oh,  g_oh);  cudaGetSymbolAddress((void**)&ol,  g_ol);
    cudaGetSymbolAddress((void**)&wqh, g_wqkv_h); cudaGetSymbolAddress((void**)&wql, g_wqkv_l);
    cudaGetSymbolAddress((void**)&woh, g_wout_h); cudaGetSymbolAddress((void**)&wol, g_wout_l);
    cudaGetSymbolAddress((void**)&wf1h, g_wff1_h); cudaGetSymbolAddress((void**)&wf1l, g_wff1_l);
    cudaGetSymbolAddress((void**)&wf2h, g_wff2_h); cudaGetSymbolAddress((void**)&wf2l, g_wff2_l);

    cudaFuncSetAttribute(attn_kernel,
                         cudaFuncAttributeMaxDynamicSharedMemorySize, ATT_SMEM);
    cudaFuncSetAttribute(mma_gemm<0>,
                         cudaFuncAttributeMaxDynamicSharedMemorySize, GEMM_SMEM);
    cudaFuncSetAttribute(mma_gemm<2>,
                         cudaFuncAttributeMaxDynamicSharedMemorySize, GEMM_SMEM);

    // residual stream in d_out
    cudaMemcpyAsync(x, x_in, sizeof(float) * (size_t)TOK * DIMM,
                    cudaMemcpyDeviceToDevice);

    // weight conversion (once per launch)
    cvt_kernel<<<4096, 256>>>(qkv_w, wqh, wql, DEPTH * DIMM * 3 * INNER / 4);
    cvt_kernel<<<2048, 256>>>(out_w, woh, wol, DEPTH * INNER * DIMM / 4);
    cvt_kernel<<<4096, 256>>>(ff1_w, wf1h, wf1l, DEPTH * DIMM * MLPD / 4);
    cvt_kernel<<<4096, 256>>>(ff2_w, wf2h, wf2l, DEPTH * MLPD * DIMM / 4);

    const int RED_N4 = TOK * DIMM / 4;

    for (int l = 0; l < DEPTH; ++l) {
        size_t wq = (size_t)l * DIMM * 3 * INNER;
        size_t wo = (size_t)l * INNER * DIMM;
        size_t w1 = (size_t)l * DIMM * MLPD;
        size_t w2 = (size_t)l * MLPD * DIMM;

        ln_kernel<<<TOK, 256>>>(x, ln1_g + (size_t)l * DIMM,
                                   ln1_b + (size_t)l * DIMM, hh, hl);
        // qkv = h @ qkv_w
        mma_gemm<0><<<dim3(3 * INNER / 128, TOK / 128, 1), 256, GEMM_SMEM>>>(
            hh, hl, wqh + wq, wql + wq, qkvb, nullptr, nullptr, nullptr,
            TOK, 3 * INNER, DIMM, DIMM);
        attn_kernel<<<dim3(NN / 64, BB * HEADS), 256, ATT_SMEM>>>(qkvb, mask, oh, ol);
        // out-proj, split-K 2 -> partials, then reduce (+bias +residual)
        mma_gemm<0><<<dim3(DIMM / 128, TOK / 128, 2), 256, GEMM_SMEM>>>(
            oh, ol, woh + wo, wol + wo, part, nullptr, nullptr, nullptr,
            TOK, DIMM, INNER, INNER / 2);
        reduce_kernel<2><<<RED_N4 / 256, 256>>>(x, out_b + (size_t)l * DIMM,
                                                part, RED_N4);
        ln_kernel<<<TOK, 256>>>(x, ln2_g + (size_t)l * DIMM,
                                   ln2_b + (size_t)l * DIMM, hh, hl);
        // ff1 + GELU -> bf16 hi/lo
        mma_gemm<2><<<dim3(MLPD / 128, TOK / 128, 1), 256, GEMM_SMEM>>>(
            hh, hl, wf1h + w1, wf1l + w1, nullptr, ff1_b + (size_t)l * MLPD,
            h2h, h2l, TOK, MLPD, DIMM, DIMM);
        // ff2, split-K 4 -> partials, then reduce (+bias +residual)
        mma_gemm<0><<<dim3(DIMM / 128, TOK / 128, 4), 256, GEMM_SMEM>>>(
            h2h, h2l, wf2h + w2, wf2l + w2, part, nullptr, nullptr, nullptr,
            TOK, DIMM, MLPD, MLPD / 4);
        reduce_kernel<4><<<RED_N4 / 256, 256>>>(x, ff2_b + (size_t)l * DIMM,
                                                part, RED_N4);
    }
}

// round 11
// speedup vs baseline: 2.4208x; 1.0372x over previous
#include <cuda_runtime.h>
#include <cuda_bf16.h>
#include <math.h>
#include <stdint.h>

// Problem constants
#define BB     2
#define NN     1024
#define DIMM   1024
#define DEPTH  4
#define HEADS  16
#define DHEAD  64
#define INNER  1024
#define MLPD   4096
#define TOK    (BB*NN)       // 2048

typedef __nv_bfloat16 bf16;

// ---------------------------------------------------------------------------
// Scratch (no cudaMalloc allowed)
// ---------------------------------------------------------------------------
__device__ float g_qkv[TOK * 3 * INNER];
__device__ float g_part[4 * TOK * DIMM];

__device__ bf16 g_hh [TOK * DIMM],  g_hl [TOK * DIMM];
__device__ bf16 g_h2h[TOK * MLPD],  g_h2l[TOK * MLPD];
__device__ bf16 g_oh [TOK * INNER], g_ol [TOK * INNER];

__device__ bf16 g_wqkv_h[DEPTH * DIMM * 3 * INNER], g_wqkv_l[DEPTH * DIMM * 3 * INNER];
__device__ bf16 g_wout_h[DEPTH * INNER * DIMM],     g_wout_l[DEPTH * INNER * DIMM];
__device__ bf16 g_wff1_h[DEPTH * DIMM * MLPD],      g_wff1_l[DEPTH * DIMM * MLPD];
__device__ bf16 g_wff2_h[DEPTH * MLPD * DIMM],      g_wff2_l[DEPTH * MLPD * DIMM];

// ---------------------------------------------------------------------------
// Helpers
// ---------------------------------------------------------------------------
__device__ __forceinline__ uint32_t s2u(const void* p) {
    uint32_t a;
    asm("{ .reg .u64 t; cvta.to.shared.u64 t, %1; cvt.u32.u64 %0, t; }"
        : "=r"(a) : "l"(p));
    return a;
}

__device__ __forceinline__ void split1(float x, bf16& h, bf16& l) {
    h = __float2bfloat16(x);
    l = __float2bfloat16(x - __bfloat162float(h));
}

#define LDX4(r, addr) \
    asm volatile("ldmatrix.sync.aligned.m8n8.x4.shared.b16 {%0,%1,%2,%3}, [%4];" \
        : "=r"((r)[0]), "=r"((r)[1]), "=r"((r)[2]), "=r"((r)[3]) : "r"(addr))

#define LDX4T(r, addr) \
    asm volatile("ldmatrix.sync.aligned.m8n8.x4.trans.shared.b16 {%0,%1,%2,%3}, [%4];" \
        : "=r"((r)[0]), "=r"((r)[1]), "=r"((r)[2]), "=r"((r)[3]) : "r"(addr))

#define MMA(cd, a, b) \
    asm volatile("mma.sync.aligned.m16n8k16.row.col.f32.bf16.bf16.f32 " \
        "{%0,%1,%2,%3}, {%4,%5,%6,%7}, {%8,%9}, {%0,%1,%2,%3};" \
        : "+f"((cd)[0]), "+f"((cd)[1]), "+f"((cd)[2]), "+f"((cd)[3]) \
        : "r"((a)[0]), "r"((a)[1]), "r"((a)[2]), "r"((a)[3]), \
          "r"((b)[0]), "r"((b)[1]))

#define CP16(dst, src) \
    asm volatile("cp.async.cg.shared.global [%0], [%1], 16;" \
        :: "r"(dst), "l"(src) : "memory")

__device__ __forceinline__ float gelu1(float v) {
    return 0.5f * v * (1.f + erff(v * 0.70710678118654752f));
}

// ---------------------------------------------------------------------------
// fp32 -> bf16 hi/lo elementwise convert
// ---------------------------------------------------------------------------
__global__ void cvt_kernel(const float* __restrict__ in,
                           bf16* __restrict__ h, bf16* __restrict__ l, int n4)
{
    for (int i = blockIdx.x * blockDim.x + threadIdx.x; i < n4;
         i += gridDim.x * blockDim.x) {
        float4 v = ((const float4*)in)[i];
        bf16 h0, l0, h1, l1, h2, l2, h3, l3;
        split1(v.x, h0, l0); split1(v.y, h1, l1);
        split1(v.z, h2, l2); split1(v.w, h3, l3);
        __nv_bfloat162 hp0 = __halves2bfloat162(h0, h1);
        __nv_bfloat162 hp1 = __halves2bfloat162(h2, h3);
        __nv_bfloat162 lp0 = __halves2bfloat162(l0, l1);
        __nv_bfloat162 lp1 = __halves2bfloat162(l2, l3);
        ((uint2*)h)[i] = make_uint2(*(uint32_t*)&hp0, *(uint32_t*)&hp1);
        ((uint2*)l)[i] = make_uint2(*(uint32_t*)&lp0, *(uint32_t*)&lp1);
    }
}

// ---------------------------------------------------------------------------
// Split-K reduce: x[i] += bias[col] + sum_p part[p][i]
// ---------------------------------------------------------------------------
template <int NP>
__global__ void reduce_kernel(float* __restrict__ x,
                              const float* __restrict__ bias,
                              const float* __restrict__ part, int n4)
{
    int i = blockIdx.x * blockDim.x + threadIdx.x;
    if (i >= n4) return;
    float4 v = ((const float4*)x)[i];
    float4 b = ((const float4*)bias)[i & (DIMM / 4 - 1)];
    v.x += b.x; v.y += b.y; v.z += b.z; v.w += b.w;
#pragma unroll
    for (int p = 0; p < NP; ++p) {
        float4 pv = ((const float4*)(part + (size_t)p * TOK * DIMM))[i];
        v.x += pv.x; v.y += pv.y; v.z += pv.z; v.w += pv.w;
    }
    ((float4*)x)[i] = v;
}

// ---------------------------------------------------------------------------
// Tensor-core GEMM, bf16 hi/lo, 3-term split MMA, fp32 accumulate.
// 128x128 tile/CTA, 256 threads (8 warps x 64x32), K-chunk 32 (2x k16 steps),
// 2-stage cp.async ring (fixed wait ordering), term-reordered MMAs.
// ---------------------------------------------------------------------------
#define APITCH 40                                // 32 k + 8 pad (elems)
#define BPITCH 136                               // 128 n + 8 pad (elems)
#define AH_OFF 0
#define AL_OFF (128 * APITCH * 2)                // 10240
#define BH_OFF (2 * 128 * APITCH * 2)            // 20480
#define BL_OFF (BH_OFF + 32 * BPITCH * 2)        // 29184
#define STG_TOTAL (BL_OFF + 32 * BPITCH * 2)     // 37888
#define NST 2
#define GEMM_SMEM (NST * STG_TOTAL)              // 75776

template <int EPI>
__global__ __launch_bounds__(256, 2)
void mma_gemm(const bf16* __restrict__ Ah, const bf16* __restrict__ Al,
              const bf16* __restrict__ Bh, const bf16* __restrict__ Bl,
              float* __restrict__ C, const float* __restrict__ bias,
              bf16* __restrict__ Ch, bf16* __restrict__ Cl,
              int M, int Ncols, int lda, int Kpart)
{
    extern __shared__ __align__(16) char smem[];
    const uint32_t sbase = s2u(smem);

    const int tid = threadIdx.x, lane = tid & 31, wid = tid >> 5;
    const int m0 = blockIdx.y * 128, n0 = blockIdx.x * 128;
    const int wm = (wid >> 2) * 64, wn = (wid & 3) * 32;
    const int koff = blockIdx.z * Kpart;
    C += (size_t)blockIdx.z * M * Ncols;

    float acc[4][4][4];
#pragma unroll
    for (int i = 0; i < 4; ++i)
#pragma unroll
        for (int j = 0; j < 4; ++j)
#pragma unroll
            for (int q = 0; q < 4; ++q) acc[i][j][q] = 0.f;

    // ldmatrix per-lane byte offsets (relative to stage base)
    const uint32_t a_off = ((wm + (lane & 15)) * APITCH + (lane >> 4) * 8) * 2;
    const uint32_t b_off = ((lane & 15) * BPITCH + wn + (lane >> 4) * 8) * 2;

    const int NCH = Kpart / 32;

    // issue loads for chunk cc into stage buffer at byte offset so
    auto issue = [&](int cc, uint32_t so) {
#pragma unroll
        for (int i = 0; i < 2; ++i) {
            int idx = tid + i * 256;               // 0..511
            int arow = idx >> 2, akc = (idx & 3) * 8;
            CP16(sbase + so + AH_OFF + (arow * APITCH + akc) * 2,
                 Ah + (size_t)(m0 + arow) * lda + koff + cc * 32 + akc);
            CP16(sbase + so + AL_OFF + (arow * APITCH + akc) * 2,
                 Al + (size_t)(m0 + arow) * lda + koff + cc * 32 + akc);
            int bkr = idx >> 4, bn = (idx & 15) * 8;
            CP16(sbase + so + BH_OFF + (bkr * BPITCH + bn) * 2,
                 Bh + (size_t)(koff + cc * 32 + bkr) * Ncols + n0 + bn);
            CP16(sbase + so + BL_OFF + (bkr * BPITCH + bn) * 2,
                 Bl + (size_t)(koff + cc * 32 + bkr) * Ncols + n0 + bn);
        }
        asm volatile("cp.async.commit_group;" ::: "memory");
    };

    // prologue: chunk 0 into buffer 0
    issue(0, 0);

    for (int c = 0; c < NCH; ++c) {
        const uint32_t so = (uint32_t)(c & 1) * STG_TOTAL;

        // drain reads of the buffer we are about to overwrite (from iter c-1)
        __syncthreads();
        if (c + 1 < NCH) {
            issue(c + 1, (uint32_t)((c + 1) & 1) * STG_TOTAL);
            // pending groups = {c, c+1}; wait until <=1 pending => chunk c done
            asm volatile("cp.async.wait_group 1;" ::: "memory");
        } else {
            asm volatile("cp.async.wait_group 0;" ::: "memory");
        }
        __syncthreads();   // make chunk c's smem visible to all threads

        // two k16 sub-steps
#pragma unroll
        for (int ks = 0; ks < 2; ++ks) {
            uint32_t bh[8], bl[8];
            {
                uint32_t bb = sbase + so + BH_OFF + b_off + ks * 16 * BPITCH * 2;
                uint32_t lb = sbase + so + BL_OFF + b_off + ks * 16 * BPITCH * 2;
                LDX4T(bh + 0, bb);
                LDX4T(bh + 4, bb + 32);
                LDX4T(bl + 0, lb);
                LDX4T(bl + 4, lb + 32);
            }
            uint32_t abase = sbase + so + AH_OFF + a_off + ks * 32;
            uint32_t lbase = sbase + so + AL_OFF + a_off + ks * 32;
#pragma unroll
            for (int mi = 0; mi < 4; ++mi) {
                uint32_t ah[4], al[4];
                LDX4(ah, abase + mi * 16 * APITCH * 2);
                LDX4(al, lbase + mi * 16 * APITCH * 2);
                // term-reordered: same-acc MMAs are 4 apart
#pragma unroll
                for (int ni = 0; ni < 4; ++ni) MMA(acc[mi][ni], ah, bh + ni * 2);
#pragma unroll
                for (int ni = 0; ni < 4; ++ni) MMA(acc[mi][ni], ah, bl + ni * 2);
#pragma unroll
                for (int ni = 0; ni < 4; ++ni) MMA(acc[mi][ni], al, bh + ni * 2);
            }
        }
    }

    // epilogue
#pragma unroll
    for (int mi = 0; mi < 4; ++mi) {
        int row = m0 + wm + mi * 16 + (lane >> 2);
#pragma unroll
        for (int ni = 0; ni < 4; ++ni) {
            int col = n0 + wn + ni * 8 + (lane & 3) * 2;
#pragma unroll
            for (int half = 0; half < 2; ++half) {
                int r = row + half * 8;
                float v0 = acc[mi][ni][half * 2 + 0];
                float v1 = acc[mi][ni][half * 2 + 1];
                size_t idx = (size_t)r * Ncols + col;
                if (EPI == 0) {
                    *(float2*)(C + idx) = make_float2(v0, v1);
                } else {
                    v0 = gelu1(v0 + bias[col]);
                    v1 = gelu1(v1 + bias[col + 1]);
                    bf16 h0, l0, h1, l1;
                    split1(v0, h0, l0);
                    split1(v1, h1, l1);
                    __nv_bfloat162 hp = __halves2bfloat162(h0, h1);
                    __nv_bfloat162 lp = __halves2bfloat162(l0, l1);
                    *(uint32_t*)(Ch + idx) = *(uint32_t*)&hp;
                    *(uint32_t*)(Cl + idx) = *(uint32_t*)&lp;
                }
            }
        }
    }
}

// ---------------------------------------------------------------------------
// LayerNorm
// ---------------------------------------------------------------------------
__global__ void ln_kernel(const float* __restrict__ x,
                          const float* __restrict__ g,
                          const float* __restrict__ b,
                          bf16* __restrict__ oh, bf16* __restrict__ ol)
{
    int row = blockIdx.x;
    int tid = threadIdx.x;
    int lane = tid & 31, wid = tid >> 5;
    __shared__ float red[8];
    __shared__ float bc[2];

    float4 v = *(const float4*)(x + (size_t)row * DIMM + tid * 4);

    float s = v.x + v.y + v.z + v.w;
#pragma unroll
    for (int o = 16; o > 0; o >>= 1) s += __shfl_xor_sync(~0u, s, o);
    if (lane == 0) red[wid] = s;
    __syncthreads();
    if (tid == 0) {
        float t = 0.f;
#pragma unroll
        for (int i = 0; i < 8; ++i) t += red[i];
        bc[0] = t * (1.f / DIMM);
    }
    __syncthreads();
    float mu = bc[0];

    float dx = v.x - mu, dy = v.y - mu, dz = v.z - mu, dw = v.w - mu;
    float s2 = dx * dx + dy * dy + dz * dz + dw * dw;
#pragma unroll
    for (int o = 16; o > 0; o >>= 1) s2 += __shfl_xor_sync(~0u, s2, o);
    if (lane == 0) red[wid] = s2;
    __syncthreads();
    if (tid == 0) {
        float t = 0.f;
#pragma unroll
        for (int i = 0; i < 8; ++i) t += red[i];
        bc[1] = rsqrtf(t * (1.f / DIMM) + 1e-5f);
    }
    __syncthreads();
    float rstd = bc[1];

    float4 gg = *(const float4*)(g + tid * 4);
    float4 bb = *(const float4*)(b + tid * 4);
    float o0 = dx * rstd * gg.x + bb.x;
    float o1 = dy * rstd * gg.y + bb.y;
    float o2 = dz * rstd * gg.z + bb.z;
    float o3 = dw * rstd * gg.w + bb.w;

    bf16 h0, l0, h1, l1, h2, l2, h3, l3;
    split1(o0, h0, l0); split1(o1, h1, l1);
    split1(o2, h2, l2); split1(o3, h3, l3);
    __nv_bfloat162 hp0 = __halves2bfloat162(h0, h1);
    __nv_bfloat162 hp1 = __halves2bfloat162(h2, h3);
    __nv_bfloat162 lp0 = __halves2bfloat162(l0, l1);
    __nv_bfloat162 lp1 = __halves2bfloat162(l2, l3);
    size_t idx = (size_t)row * DIMM + tid * 4;
    *(uint2*)(oh + idx) = make_uint2(*(uint32_t*)&hp0, *(uint32_t*)&hp1);
    *(uint2*)(ol + idx) = make_uint2(*(uint32_t*)&lp0, *(uint32_t*)&lp1);
}

// ---------------------------------------------------------------------------
// Fused attention (flash-style), fp32 compute, bf16 hi/lo output.
// ---------------------------------------------------------------------------
#define ATT_SMEM (4 * 64 * 65 * 4)

__global__ __launch_bounds__(256)
void attn_kernel(const float* __restrict__ qkv,
                 const int* __restrict__ mask,
                 bf16* __restrict__ oh, bf16* __restrict__ ol)
{
    extern __shared__ float sm[];
    float* Qs = sm;
    float* Ks = Qs + 64 * 65;
    float* Vs = Ks + 64 * 65;
    float* Ss = Vs + 64 * 65;
    __shared__ float m_s[64], l_s[64], corr_s[64];

    int tid = threadIdx.x;
    int bh = blockIdx.y;
    int b  = bh >> 4;
    int h  = bh & 15;
    int q0 = blockIdx.x * 64;

    int tr = tid >> 4;
    int tc = tid & 15;
    const float scale = 0.125f;

    const float* qbase = qkv + ((size_t)(b * NN + q0)) * (3 * INNER) + h * DHEAD;
    for (int idx = tid; idx < 64 * 16; idx += 256) {
        int r = idx >> 4, c4 = (idx & 15) * 4;
        float4 v = *(const float4*)(qbase + (size_t)r * (3 * INNER) + c4);
        float* q = &Qs[r * 65 + c4];
        q[0] = v.x; q[1] = v.y; q[2] = v.z; q[3] = v.w;
    }
    if (tid < 64) { m_s[tid] = -INFINITY; l_s[tid] = 0.f; }

    float oacc[4][4];
#pragma unroll
    for (int i = 0; i < 4; ++i)
#pragma unroll
        for (int j = 0; j < 4; ++j) oacc[i][j] = 0.f;

    __syncthreads();

    for (int k0 = 0; k0 < NN; k0 += 64) {
        const float* kbase = qkv + ((size_t)(b * NN + k0)) * (3 * INNER) + INNER + h * DHEAD;
        const float* vbase = kbase + INNER;
        for (int idx = tid; idx < 64 * 16; idx += 256) {
            int r = idx >> 4, c4 = (idx & 15) * 4;
            float4 kv = *(const float4*)(kbase + (size_t)r * (3 * INNER) + c4);
            float4 vv = *(const float4*)(vbase + (size_t)r * (3 * INNER) + c4);
            float* kp = &Ks[r * 65 + c4];
            float* vp = &Vs[r * 65 + c4];
            kp[0] = kv.x; kp[1] = kv.y; kp[2] = kv.z; kp[3] = kv.w;
            vp[0] = vv.x; vp[1] = vv.y; vp[2] = vv.z; vp[3] = vv.w;
        }
        __syncthreads();

        float s[4][4] = {};
#pragma unroll 4
        for (int d = 0; d < 64; ++d) {
            float a[4], kk[4];
#pragma unroll
            for (int i = 0; i < 4; ++i) a[i]  = Qs[(tr * 4 + i) * 65 + d];
#pragma unroll
            for (int j = 0; j < 4; ++j) kk[j] = Ks[(tc * 4 + j) * 65 + d];
#pragma unroll
            for (int i = 0; i < 4; ++i)
#pragma unroll
                for (int j = 0; j < 4; ++j)
                    s[i][j] += a[i] * kk[j];
        }

#pragma unroll
        for (int i = 0; i < 4; ++i) {
            int qrow = q0 + tr * 4 + i;
            const int* mrow = mask + ((size_t)b * NN + qrow) * NN + k0;
#pragma unroll
            for (int j = 0; j < 4; ++j) {
                float v = s[i][j] * scale;
                if (mrow[tc * 4 + j] == 0) v = -1e9f;
                Ss[(tr * 4 + i) * 65 + tc * 4 + j] = v;
            }
        }
        __syncthreads();

        {
            int r = tid >> 2, q = tid & 3;
            float* row = &Ss[r * 65 + q * 16];
            float mx = m_s[r];
            float tmax = -INFINITY;
#pragma unroll
            for (int j = 0; j < 16; ++j) tmax = fmaxf(tmax, row[j]);
            tmax = fmaxf(tmax, __shfl_xor_sync(~0u, tmax, 1));
            tmax = fmaxf(tmax, __shfl_xor_sync(~0u, tmax, 2));
            float nm = fmaxf(mx, tmax);
            float sum = 0.f;
#pragma unroll
            for (int j = 0; j < 16; ++j) {
                float p = __expf(row[j] - nm);
                row[j] = p;
                sum += p;
            }
            sum += __shfl_xor_sync(~0u, sum, 1);
            sum += __shfl_xor_sync(~0u, sum, 2);
            if (q == 0) {
                float corr = __expf(mx - nm);
                m_s[r] = nm;
                l_s[r] = l_s[r] * corr + sum;
                corr_s[r] = corr;
            }
        }
        __syncthreads();

#pragma unroll
        for (int i = 0; i < 4; ++i) {
            float corr = corr_s[tr * 4 + i];
#pragma unroll
            for (int j = 0; j < 4; ++j) oacc[i][j] *= corr;
        }
#pragma unroll 4
        for (int j = 0; j < 64; ++j) {
            float p[4], v[4];
#pragma unroll
            for (int i = 0; i < 4; ++i) p[i] = Ss[(tr * 4 + i) * 65 + j];
#pragma unroll
            for (int c = 0; c < 4; ++c) v[c] = Vs[j * 65 + tc * 4 + c];
#pragma unroll
            for (int i = 0; i < 4; ++i)
#pragma unroll
                for (int c = 0; c < 4; ++c)
                    oacc[i][c] += p[i] * v[c];
        }
        __syncthreads();
    }

#pragma unroll
    for (int i = 0; i < 4; ++i) {
        int r = tr * 4 + i;
        float inv = 1.f / l_s[r];
        size_t idx = ((size_t)(b * NN + q0 + r)) * INNER + h * DHEAD + tc * 4;
        float o0 = oacc[i][0] * inv, o1 = oacc[i][1] * inv;
        float o2 = oacc[i][2] * inv, o3 = oacc[i][3] * inv;
        bf16 h0, l0, h1, l1, h2, l2, h3, l3;
        split1(o0, h0, l0); split1(o1, h1, l1);
        split1(o2, h2, l2); split1(o3, h3, l3);
        __nv_bfloat162 hp0 = __halves2bfloat162(h0, h1);
        __nv_bfloat162 hp1 = __halves2bfloat162(h2, h3);
        __nv_bfloat162 lp0 = __halves2bfloat162(l0, l1);
        __nv_bfloat162 lp1 = __halves2bfloat162(l2, l3);
        *(uint2*)(oh + idx) = make_uint2(*(uint32_t*)&hp0, *(uint32_t*)&hp1);
        *(uint2*)(ol + idx) = make_uint2(*(uint32_t*)&lp0, *(uint32_t*)&lp1);
    }
}

// ---------------------------------------------------------------------------
// Launch
// ---------------------------------------------------------------------------
extern "C" void kernel_launch(void* const* d_in, const int* in_sizes, int n_in,
                              void* d_out, int out_size)
{
    const float* x_in  = (const float*)d_in[0];
    const int*   mask  = (const int*)  d_in[1];
    const float* ln1_g = (const float*)d_in[2];
    const float* ln1_b = (const float*)d_in[3];
    const float* qkv_w = (const float*)d_in[4];
    const float* out_w = (const float*)d_in[5];
    const float* out_b = (const float*)d_in[6];
    const float* ln2_g = (const float*)d_in[7];
    const float* ln2_b = (const float*)d_in[8];
    const float* ff1_w = (const float*)d_in[9];
    const float* ff1_b = (const float*)d_in[10];
    const float* ff2_w = (const float*)d_in[11];
    const float* ff2_b = (const float*)d_in[12];
    float* x = (float*)d_out;

    float *qkvb, *part;
    bf16 *hh, *hl, *h2h, *h2l, *oh, *ol;
    bf16 *wqh, *wql, *woh, *wol, *wf1h, *wf1l, *wf2h, *wf2l;
    cudaGetSymbolAddress((void**)&qkvb, g_qkv);
    cudaGetSymbolAddress((void**)&part, g_part);
    cudaGetSymbolAddress((void**)&hh,  g_hh);  cudaGetSymbolAddress((void**)&hl,  g_hl);
    cudaGetSymbolAddress((void**)&h2h, g_h2h); cudaGetSymbolAddress((void**)&h2l, g_h2l);
    cudaGetSymbolAddress((void**)&oh,  g_oh);  cudaGetSymbolAddress((void**)&ol,  g_ol);
    cudaGetSymbolAddress((void**)&wqh, g_wqkv_h); cudaGetSymbolAddress((void**)&wql, g_wqkv_l);
    cudaGetSymbolAddress((void**)&woh, g_wout_h); cudaGetSymbolAddress((void**)&wol, g_wout_l);
    cudaGetSymbolAddress((void**)&wf1h, g_wff1_h); cudaGetSymbolAddress((void**)&wf1l, g_wff1_l);
    cudaGetSymbolAddress((void**)&wf2h, g_wff2_h); cudaGetSymbolAddress((void**)&wf2l, g_wff2_l);

    cudaFuncSetAttribute(attn_kernel,
                         cudaFuncAttributeMaxDynamicSharedMemorySize, ATT_SMEM);
    cudaFuncSetAttribute(mma_gemm<0>,
                         cudaFuncAttributeMaxDynamicSharedMemorySize, GEMM_SMEM);
    cudaFuncSetAttribute(mma_gemm<2>,
                         cudaFuncAttributeMaxDynamicSharedMemorySize, GEMM_SMEM);

    cudaMemcpyAsync(x, x_in, sizeof(float) * (size_t)TOK * DIMM,
                    cudaMemcpyDeviceToDevice);

    cvt_kernel<<<4096, 256>>>(qkv_w, wqh, wql, DEPTH * DIMM * 3 * INNER / 4);
    cvt_kernel<<<2048, 256>>>(out_w, woh, wol, DEPTH * INNER * DIMM / 4);
    cvt_kernel<<<4096, 256>>>(ff1_w, wf1h, wf1l, DEPTH * DIMM * MLPD / 4);
    cvt_kernel<<<4096, 256>>>(ff2_w, wf2h, wf2l, DEPTH * MLPD * DIMM / 4);

    const int RED_N4 = TOK * DIMM / 4;

    for (int l = 0; l < DEPTH; ++l) {
        size_t wq = (size_t)l * DIMM * 3 * INNER;
        size_t wo = (size_t)l * INNER * DIMM;
        size_t w1 = (size_t)l * DIMM * MLPD;
        size_t w2 = (size_t)l * MLPD * DIMM;

        ln_kernel<<<TOK, 256>>>(x, ln1_g + (size_t)l * DIMM,
                                   ln1_b + (size_t)l * DIMM, hh, hl);
        mma_gemm<0><<<dim3(3 * INNER / 128, TOK / 128, 1), 256, GEMM_SMEM>>>(
            hh, hl, wqh + wq, wql + wq, qkvb, nullptr, nullptr, nullptr,
            TOK, 3 * INNER, DIMM, DIMM);
        attn_kernel<<<dim3(NN / 64, BB * HEADS), 256, ATT_SMEM>>>(qkvb, mask, oh, ol);
        mma_gemm<0><<<dim3(DIMM / 128, TOK / 128, 2), 256, GEMM_SMEM>>>(
            oh, ol, woh + wo, wol + wo, part, nullptr, nullptr, nullptr,
            TOK, DIMM, INNER, INNER / 2);
        reduce_kernel<2><<<RED_N4 / 256, 256>>>(x, out_b + (size_t)l * DIMM,
                                                part, RED_N4);
        ln_kernel<<<TOK, 256>>>(x, ln2_g + (size_t)l * DIMM,
                                   ln2_b + (size_t)l * DIMM, hh, hl);
        mma_gemm<2><<<dim3(MLPD / 128, TOK / 128, 1), 256, GEMM_SMEM>>>(
            hh, hl, wf1h + w1, wf1l + w1, nullptr, ff1_b + (size_t)l * MLPD,
            h2h, h2l, TOK, MLPD, DIMM, DIMM);
        mma_gemm<0><<<dim3(DIMM / 128, TOK / 128, 4), 256, GEMM_SMEM>>>(
            h2h, h2l, wf2h + w2, wf2l + w2, part, nullptr, nullptr, nullptr,
            TOK, DIMM, MLPD, MLPD / 4);
        reduce_kernel<4><<<RED_N4 / 256, 256>>>(x, ff2_b + (size_t)l * DIMM,
                                                part, RED_N4);
    }
}

// round 12
// speedup vs baseline: 2.4314x; 1.0044x over previous
#include <cuda_runtime.h>
#include <cuda_bf16.h>
#include <math.h>
#include <stdint.h>

// Problem constants
#define BB     2
#define NN     1024
#define DIMM   1024
#define DEPTH  4
#define HEADS  16
#define DHEAD  64
#define INNER  1024
#define MLPD   4096
#define TOK    (BB*NN)       // 2048

typedef __nv_bfloat16 bf16;

// ---------------------------------------------------------------------------
// Scratch (no cudaMalloc allowed)
// ---------------------------------------------------------------------------
__device__ float g_qkv[TOK * 3 * INNER];
__device__ float g_part[4 * TOK * DIMM];

__device__ bf16 g_hh [TOK * DIMM],  g_hl [TOK * DIMM];
__device__ bf16 g_h2h[TOK * MLPD],  g_h2l[TOK * MLPD];
__device__ bf16 g_oh [TOK * INNER], g_ol [TOK * INNER];

__device__ bf16 g_wqkv_h[DEPTH * DIMM * 3 * INNER], g_wqkv_l[DEPTH * DIMM * 3 * INNER];
__device__ bf16 g_wout_h[DEPTH * INNER * DIMM],     g_wout_l[DEPTH * INNER * DIMM];
__device__ bf16 g_wff1_h[DEPTH * DIMM * MLPD],      g_wff1_l[DEPTH * DIMM * MLPD];
__device__ bf16 g_wff2_h[DEPTH * MLPD * DIMM],      g_wff2_l[DEPTH * MLPD * DIMM];

// ---------------------------------------------------------------------------
// Helpers
// ---------------------------------------------------------------------------
__device__ __forceinline__ uint32_t s2u(const void* p) {
    uint32_t a;
    asm("{ .reg .u64 t; cvta.to.shared.u64 t, %1; cvt.u32.u64 %0, t; }"
        : "=r"(a) : "l"(p));
    return a;
}

__device__ __forceinline__ void split1(float x, bf16& h, bf16& l) {
    h = __float2bfloat16(x);
    l = __float2bfloat16(x - __bfloat162float(h));
}

#define LDX4(r, addr) \
    asm volatile("ldmatrix.sync.aligned.m8n8.x4.shared.b16 {%0,%1,%2,%3}, [%4];" \
        : "=r"((r)[0]), "=r"((r)[1]), "=r"((r)[2]), "=r"((r)[3]) : "r"(addr))

#define LDX4T(r, addr) \
    asm volatile("ldmatrix.sync.aligned.m8n8.x4.trans.shared.b16 {%0,%1,%2,%3}, [%4];" \
        : "=r"((r)[0]), "=r"((r)[1]), "=r"((r)[2]), "=r"((r)[3]) : "r"(addr))

#define MMA(cd, a, b) \
    asm volatile("mma.sync.aligned.m16n8k16.row.col.f32.bf16.bf16.f32 " \
        "{%0,%1,%2,%3}, {%4,%5,%6,%7}, {%8,%9}, {%0,%1,%2,%3};" \
        : "+f"((cd)[0]), "+f"((cd)[1]), "+f"((cd)[2]), "+f"((cd)[3]) \
        : "r"((a)[0]), "r"((a)[1]), "r"((a)[2]), "r"((a)[3]), \
          "r"((b)[0]), "r"((b)[1]))

#define CP16(dst, src) \
    asm volatile("cp.async.cg.shared.global [%0], [%1], 16;" \
        :: "r"(dst), "l"(src) : "memory")

__device__ __forceinline__ float gelu1(float v) {
    return 0.5f * v * (1.f + erff(v * 0.70710678118654752f));
}

// ---------------------------------------------------------------------------
// fp32 -> bf16 hi/lo elementwise convert
// ---------------------------------------------------------------------------
__global__ void cvt_kernel(const float* __restrict__ in,
                           bf16* __restrict__ h, bf16* __restrict__ l, int n4)
{
    for (int i = blockIdx.x * blockDim.x + threadIdx.x; i < n4;
         i += gridDim.x * blockDim.x) {
        float4 v = ((const float4*)in)[i];
        bf16 h0, l0, h1, l1, h2, l2, h3, l3;
        split1(v.x, h0, l0); split1(v.y, h1, l1);
        split1(v.z, h2, l2); split1(v.w, h3, l3);
        __nv_bfloat162 hp0 = __halves2bfloat162(h0, h1);
        __nv_bfloat162 hp1 = __halves2bfloat162(h2, h3);
        __nv_bfloat162 lp0 = __halves2bfloat162(l0, l1);
        __nv_bfloat162 lp1 = __halves2bfloat162(l2, l3);
        ((uint2*)h)[i] = make_uint2(*(uint32_t*)&hp0, *(uint32_t*)&hp1);
        ((uint2*)l)[i] = make_uint2(*(uint32_t*)&lp0, *(uint32_t*)&lp1);
    }
}

// ---------------------------------------------------------------------------
// Split-K reduce: x[i] += bias[col] + sum_p part[p][i]
// ---------------------------------------------------------------------------
template <int NP>
__global__ void reduce_kernel(float* __restrict__ x,
                              const float* __restrict__ bias,
                              const float* __restrict__ part, int n4)
{
    int i = blockIdx.x * blockDim.x + threadIdx.x;
    if (i >= n4) return;
    float4 v = ((const float4*)x)[i];
    float4 b = ((const float4*)bias)[i & (DIMM / 4 - 1)];
    v.x += b.x; v.y += b.y; v.z += b.z; v.w += b.w;
#pragma unroll
    for (int p = 0; p < NP; ++p) {
        float4 pv = ((const float4*)(part + (size_t)p * TOK * DIMM))[i];
        v.x += pv.x; v.y += pv.y; v.z += pv.z; v.w += pv.w;
    }
    ((float4*)x)[i] = v;
}

// ---------------------------------------------------------------------------
// Tensor-core GEMM, bf16 hi/lo, 3-term split MMA, fp32 accumulate.
// 128x128 tile/CTA, 256 threads (8 warps x 64x32), K-chunk 32 (2x k16 steps),
// 2-stage cp.async ring, A-fragment register double-buffering.
// ---------------------------------------------------------------------------
#define APITCH 40                                // 32 k + 8 pad (elems)
#define BPITCH 136                               // 128 n + 8 pad (elems)
#define AH_OFF 0
#define AL_OFF (128 * APITCH * 2)                // 10240
#define BH_OFF (2 * 128 * APITCH * 2)            // 20480
#define BL_OFF (BH_OFF + 32 * BPITCH * 2)        // 29184
#define STG_TOTAL (BL_OFF + 32 * BPITCH * 2)     // 37888
#define NST 2
#define GEMM_SMEM (NST * STG_TOTAL)              // 75776

template <int EPI>
__global__ __launch_bounds__(256, 2)
void mma_gemm(const bf16* __restrict__ Ah, const bf16* __restrict__ Al,
              const bf16* __restrict__ Bh, const bf16* __restrict__ Bl,
              float* __restrict__ C, const float* __restrict__ bias,
              bf16* __restrict__ Ch, bf16* __restrict__ Cl,
              int M, int Ncols, int lda, int Kpart)
{
    extern __shared__ __align__(16) char smem[];
    const uint32_t sbase = s2u(smem);

    const int tid = threadIdx.x, lane = tid & 31, wid = tid >> 5;
    const int m0 = blockIdx.y * 128, n0 = blockIdx.x * 128;
    const int wm = (wid >> 2) * 64, wn = (wid & 3) * 32;
    const int koff = blockIdx.z * Kpart;
    C += (size_t)blockIdx.z * M * Ncols;

    float acc[4][4][4];
#pragma unroll
    for (int i = 0; i < 4; ++i)
#pragma unroll
        for (int j = 0; j < 4; ++j)
#pragma unroll
            for (int q = 0; q < 4; ++q) acc[i][j][q] = 0.f;

    // ldmatrix per-lane byte offsets (relative to stage base)
    const uint32_t a_off = ((wm + (lane & 15)) * APITCH + (lane >> 4) * 8) * 2;
    const uint32_t b_off = ((lane & 15) * BPITCH + wn + (lane >> 4) * 8) * 2;

    const int NCH = Kpart / 32;

    // issue loads for chunk cc into stage buffer at byte offset so
    auto issue = [&](int cc, uint32_t so) {
#pragma unroll
        for (int i = 0; i < 2; ++i) {
            int idx = tid + i * 256;               // 0..511
            int arow = idx >> 2, akc = (idx & 3) * 8;
            CP16(sbase + so + AH_OFF + (arow * APITCH + akc) * 2,
                 Ah + (size_t)(m0 + arow) * lda + koff + cc * 32 + akc);
            CP16(sbase + so + AL_OFF + (arow * APITCH + akc) * 2,
                 Al + (size_t)(m0 + arow) * lda + koff + cc * 32 + akc);
            int bkr = idx >> 4, bn = (idx & 15) * 8;
            CP16(sbase + so + BH_OFF + (bkr * BPITCH + bn) * 2,
                 Bh + (size_t)(koff + cc * 32 + bkr) * Ncols + n0 + bn);
            CP16(sbase + so + BL_OFF + (bkr * BPITCH + bn) * 2,
                 Bl + (size_t)(koff + cc * 32 + bkr) * Ncols + n0 + bn);
        }
        asm volatile("cp.async.commit_group;" ::: "memory");
    };

    // prologue: chunk 0 into buffer 0
    issue(0, 0);

    for (int c = 0; c < NCH; ++c) {
        const uint32_t so = (uint32_t)(c & 1) * STG_TOTAL;

        // drain reads of the buffer we are about to overwrite (from iter c-1)
        __syncthreads();
        if (c + 1 < NCH) {
            issue(c + 1, (uint32_t)((c + 1) & 1) * STG_TOTAL);
            // pending groups = {c, c+1}; wait until <=1 pending => chunk c done
            asm volatile("cp.async.wait_group 1;" ::: "memory");
        } else {
            asm volatile("cp.async.wait_group 0;" ::: "memory");
        }
        __syncthreads();   // make chunk c's smem visible to all threads

        // two k16 sub-steps, A-fragments software-pipelined in registers
#pragma unroll
        for (int ks = 0; ks < 2; ++ks) {
            uint32_t bh[8], bl[8];
            {
                uint32_t bb = sbase + so + BH_OFF + b_off + ks * 16 * BPITCH * 2;
                uint32_t lb = sbase + so + BL_OFF + b_off + ks * 16 * BPITCH * 2;
                LDX4T(bh + 0, bb);
                LDX4T(bh + 4, bb + 32);
                LDX4T(bl + 0, lb);
                LDX4T(bl + 4, lb + 32);
            }
            const uint32_t abase = sbase + so + AH_OFF + a_off + ks * 32;
            const uint32_t lbase = sbase + so + AL_OFF + a_off + ks * 32;

            uint32_t afr[2][8];          // [buf][0..3]=A_hi frag, [4..7]=A_lo frag
            LDX4(afr[0] + 0, abase);
            LDX4(afr[0] + 4, lbase);
#pragma unroll
            for (int mi = 0; mi < 4; ++mi) {
                const int cur = mi & 1;
                if (mi < 3) {            // prefetch next A while current MMAs run
                    LDX4(afr[cur ^ 1] + 0, abase + (mi + 1) * 16 * APITCH * 2);
                    LDX4(afr[cur ^ 1] + 4, lbase + (mi + 1) * 16 * APITCH * 2);
                }
#pragma unroll
                for (int ni = 0; ni < 4; ++ni) MMA(acc[mi][ni], afr[cur],     bh + ni * 2);
#pragma unroll
                for (int ni = 0; ni < 4; ++ni) MMA(acc[mi][ni], afr[cur],     bl + ni * 2);
#pragma unroll
                for (int ni = 0; ni < 4; ++ni) MMA(acc[mi][ni], afr[cur] + 4, bh + ni * 2);
            }
        }
    }

    // epilogue
#pragma unroll
    for (int mi = 0; mi < 4; ++mi) {
        int row = m0 + wm + mi * 16 + (lane >> 2);
#pragma unroll
        for (int ni = 0; ni < 4; ++ni) {
            int col = n0 + wn + ni * 8 + (lane & 3) * 2;
#pragma unroll
            for (int half = 0; half < 2; ++half) {
                int r = row + half * 8;
                float v0 = acc[mi][ni][half * 2 + 0];
                float v1 = acc[mi][ni][half * 2 + 1];
                size_t idx = (size_t)r * Ncols + col;
                if (EPI == 0) {
                    *(float2*)(C + idx) = make_float2(v0, v1);
                } else {
                    v0 = gelu1(v0 + bias[col]);
                    v1 = gelu1(v1 + bias[col + 1]);
                    bf16 h0, l0, h1, l1;
                    split1(v0, h0, l0);
                    split1(v1, h1, l1);
                    __nv_bfloat162 hp = __halves2bfloat162(h0, h1);
                    __nv_bfloat162 lp = __halves2bfloat162(l0, l1);
                    *(uint32_t*)(Ch + idx) = *(uint32_t*)&hp;
                    *(uint32_t*)(Cl + idx) = *(uint32_t*)&lp;
                }
            }
        }
    }
}

// ---------------------------------------------------------------------------
// LayerNorm
// ---------------------------------------------------------------------------
__global__ void ln_kernel(const float* __restrict__ x,
                          const float* __restrict__ g,
                          const float* __restrict__ b,
                          bf16* __restrict__ oh, bf16* __restrict__ ol)
{
    int row = blockIdx.x;
    int tid = threadIdx.x;
    int lane = tid & 31, wid = tid >> 5;
    __shared__ float red[8];
    __shared__ float bc[2];

    float4 v = *(const float4*)(x + (size_t)row * DIMM + tid * 4);

    float s = v.x + v.y + v.z + v.w;
#pragma unroll
    for (int o = 16; o > 0; o >>= 1) s += __shfl_xor_sync(~0u, s, o);
    if (lane == 0) red[wid] = s;
    __syncthreads();
    if (tid == 0) {
        float t = 0.f;
#pragma unroll
        for (int i = 0; i < 8; ++i) t += red[i];
        bc[0] = t * (1.f / DIMM);
    }
    __syncthreads();
    float mu = bc[0];

    float dx = v.x - mu, dy = v.y - mu, dz = v.z - mu, dw = v.w - mu;
    float s2 = dx * dx + dy * dy + dz * dz + dw * dw;
#pragma unroll
    for (int o = 16; o > 0; o >>= 1) s2 += __shfl_xor_sync(~0u, s2, o);
    if (lane == 0) red[wid] = s2;
    __syncthreads();
    if (tid == 0) {
        float t = 0.f;
#pragma unroll
        for (int i = 0; i < 8; ++i) t += red[i];
        bc[1] = rsqrtf(t * (1.f / DIMM) + 1e-5f);
    }
    __syncthreads();
    float rstd = bc[1];

    float4 gg = *(const float4*)(g + tid * 4);
    float4 bb = *(const float4*)(b + tid * 4);
    float o0 = dx * rstd * gg.x + bb.x;
    float o1 = dy * rstd * gg.y + bb.y;
    float o2 = dz * rstd * gg.z + bb.z;
    float o3 = dw * rstd * gg.w + bb.w;

    bf16 h0, l0, h1, l1, h2, l2, h3, l3;
    split1(o0, h0, l0); split1(o1, h1, l1);
    split1(o2, h2, l2); split1(o3, h3, l3);
    __nv_bfloat162 hp0 = __halves2bfloat162(h0, h1);
    __nv_bfloat162 hp1 = __halves2bfloat162(h2, h3);
    __nv_bfloat162 lp0 = __halves2bfloat162(l0, l1);
    __nv_bfloat162 lp1 = __halves2bfloat162(l2, l3);
    size_t idx = (size_t)row * DIMM + tid * 4;
    *(uint2*)(oh + idx) = make_uint2(*(uint32_t*)&hp0, *(uint32_t*)&hp1);
    *(uint2*)(ol + idx) = make_uint2(*(uint32_t*)&lp0, *(uint32_t*)&lp1);
}

// ---------------------------------------------------------------------------
// Fused attention (flash-style), fp32 compute, bf16 hi/lo output.
// ---------------------------------------------------------------------------
#define ATT_SMEM (4 * 64 * 65 * 4)

__global__ __launch_bounds__(256)
void attn_kernel(const float* __restrict__ qkv,
                 const int* __restrict__ mask,
                 bf16* __restrict__ oh, bf16* __restrict__ ol)
{
    extern __shared__ float sm[];
    float* Qs = sm;
    float* Ks = Qs + 64 * 65;
    float* Vs = Ks + 64 * 65;
    float* Ss = Vs + 64 * 65;
    __shared__ float m_s[64], l_s[64], corr_s[64];

    int tid = threadIdx.x;
    int bh = blockIdx.y;
    int b  = bh >> 4;
    int h  = bh & 15;
    int q0 = blockIdx.x * 64;

    int tr = tid >> 4;
    int tc = tid & 15;
    const float scale = 0.125f;

    const float* qbase = qkv + ((size_t)(b * NN + q0)) * (3 * INNER) + h * DHEAD;
    for (int idx = tid; idx < 64 * 16; idx += 256) {
        int r = idx >> 4, c4 = (idx & 15) * 4;
        float4 v = *(const float4*)(qbase + (size_t)r * (3 * INNER) + c4);
        float* q = &Qs[r * 65 + c4];
        q[0] = v.x; q[1] = v.y; q[2] = v.z; q[3] = v.w;
    }
    if (tid < 64) { m_s[tid] = -INFINITY; l_s[tid] = 0.f; }

    float oacc[4][4];
#pragma unroll
    for (int i = 0; i < 4; ++i)
#pragma unroll
        for (int j = 0; j < 4; ++j) oacc[i][j] = 0.f;

    __syncthreads();

    for (int k0 = 0; k0 < NN; k0 += 64) {
        const float* kbase = qkv + ((size_t)(b * NN + k0)) * (3 * INNER) + INNER + h * DHEAD;
        const float* vbase = kbase + INNER;
        for (int idx = tid; idx < 64 * 16; idx += 256) {
            int r = idx >> 4, c4 = (idx & 15) * 4;
            float4 kv = *(const float4*)(kbase + (size_t)r * (3 * INNER) + c4);
            float4 vv = *(const float4*)(vbase + (size_t)r * (3 * INNER) + c4);
            float* kp = &Ks[r * 65 + c4];
            float* vp = &Vs[r * 65 + c4];
            kp[0] = kv.x; kp[1] = kv.y; kp[2] = kv.z; kp[3] = kv.w;
            vp[0] = vv.x; vp[1] = vv.y; vp[2] = vv.z; vp[3] = vv.w;
        }
        __syncthreads();

        float s[4][4] = {};
#pragma unroll 4
        for (int d = 0; d < 64; ++d) {
            float a[4], kk[4];
#pragma unroll
            for (int i = 0; i < 4; ++i) a[i]  = Qs[(tr * 4 + i) * 65 + d];
#pragma unroll
            for (int j = 0; j < 4; ++j) kk[j] = Ks[(tc * 4 + j) * 65 + d];
#pragma unroll
            for (int i = 0; i < 4; ++i)
#pragma unroll
                for (int j = 0; j < 4; ++j)
                    s[i][j] += a[i] * kk[j];
        }

#pragma unroll
        for (int i = 0; i < 4; ++i) {
            int qrow = q0 + tr * 4 + i;
            const int* mrow = mask + ((size_t)b * NN + qrow) * NN + k0;
#pragma unroll
            for (int j = 0; j < 4; ++j) {
                float v = s[i][j] * scale;
                if (mrow[tc * 4 + j] == 0) v = -1e9f;
                Ss[(tr * 4 + i) * 65 + tc * 4 + j] = v;
            }
        }
        __syncthreads();

        {
            int r = tid >> 2, q = tid & 3;
            float* row = &Ss[r * 65 + q * 16];
            float mx = m_s[r];
            float tmax = -INFINITY;
#pragma unroll
            for (int j = 0; j < 16; ++j) tmax = fmaxf(tmax, row[j]);
            tmax = fmaxf(tmax, __shfl_xor_sync(~0u, tmax, 1));
            tmax = fmaxf(tmax, __shfl_xor_sync(~0u, tmax, 2));
            float nm = fmaxf(mx, tmax);
            float sum = 0.f;
#pragma unroll
            for (int j = 0; j < 16; ++j) {
                float p = __expf(row[j] - nm);
                row[j] = p;
                sum += p;
            }
            sum += __shfl_xor_sync(~0u, sum, 1);
            sum += __shfl_xor_sync(~0u, sum, 2);
            if (q == 0) {
                float corr = __expf(mx - nm);
                m_s[r] = nm;
                l_s[r] = l_s[r] * corr + sum;
                corr_s[r] = corr;
            }
        }
        __syncthreads();

#pragma unroll
        for (int i = 0; i < 4; ++i) {
            float corr = corr_s[tr * 4 + i];
#pragma unroll
            for (int j = 0; j < 4; ++j) oacc[i][j] *= corr;
        }
#pragma unroll 4
        for (int j = 0; j < 64; ++j) {
            float p[4], v[4];
#pragma unroll
            for (int i = 0; i < 4; ++i) p[i] = Ss[(tr * 4 + i) * 65 + j];
#pragma unroll
            for (int c = 0; c < 4; ++c) v[c] = Vs[j * 65 + tc * 4 + c];
#pragma unroll
            for (int i = 0; i < 4; ++i)
#pragma unroll
                for (int c = 0; c < 4; ++c)
                    oacc[i][c] += p[i] * v[c];
        }
        __syncthreads();
    }

#pragma unroll
    for (int i = 0; i < 4; ++i) {
        int r = tr * 4 + i;
        float inv = 1.f / l_s[r];
        size_t idx = ((size_t)(b * NN + q0 + r)) * INNER + h * DHEAD + tc * 4;
        float o0 = oacc[i][0] * inv, o1 = oacc[i][1] * inv;
        float o2 = oacc[i][2] * inv, o3 = oacc[i][3] * inv;
        bf16 h0, l0, h1, l1, h2, l2, h3, l3;
        split1(o0, h0, l0); split1(o1, h1, l1);
        split1(o2, h2, l2); split1(o3, h3, l3);
        __nv_bfloat162 hp0 = __halves2bfloat162(h0, h1);
        __nv_bfloat162 hp1 = __halves2bfloat162(h2, h3);
        __nv_bfloat162 lp0 = __halves2bfloat162(l0, l1);
        __nv_bfloat162 lp1 = __halves2bfloat162(l2, l3);
        *(uint2*)(oh + idx) = make_uint2(*(uint32_t*)&hp0, *(uint32_t*)&hp1);
        *(uint2*)(ol + idx) = make_uint2(*(uint32_t*)&lp0, *(uint32_t*)&lp1);
    }
}

// ---------------------------------------------------------------------------
// Launch
// ---------------------------------------------------------------------------
extern "C" void kernel_launch(void* const* d_in, const int* in_sizes, int n_in,
                              void* d_out, int out_size)
{
    const float* x_in  = (const float*)d_in[0];
    const int*   mask  = (const int*)  d_in[1];
    const float* ln1_g = (const float*)d_in[2];
    const float* ln1_b = (const float*)d_in[3];
    const float* qkv_w = (const float*)d_in[4];
    const float* out_w = (const float*)d_in[5];
    const float* out_b = (const float*)d_in[6];
    const float* ln2_g = (const float*)d_in[7];
    const float* ln2_b = (const float*)d_in[8];
    const float* ff1_w = (const float*)d_in[9];
    const float* ff1_b = (const float*)d_in[10];
    const float* ff2_w = (const float*)d_in[11];
    const float* ff2_b = (const float*)d_in[12];
    float* x = (float*)d_out;

    float *qkvb, *part;
    bf16 *hh, *hl, *h2h, *h2l, *oh, *ol;
    bf16 *wqh, *wql, *woh, *wol, *wf1h, *wf1l, *wf2h, *wf2l;
    cudaGetSymbolAddress((void**)&qkvb, g_qkv);
    cudaGetSymbolAddress((void**)&part, g_part);
    cudaGetSymbolAddress((void**)&hh,  g_hh);  cudaGetSymbolAddress((void**)&hl,  g_hl);
    cudaGetSymbolAddress((void**)&h2h, g_h2h); cudaGetSymbolAddress((void**)&h2l, g_h2l);
    cudaGetSymbolAddress((void**)&oh,  g_oh);  cudaGetSymbolAddress((void**)&ol,  g_ol);
    cudaGetSymbolAddress((void**)&wqh, g_wqkv_h); cudaGetSymbolAddress((void**)&wql, g_wqkv_l);
    cudaGetSymbolAddress((void**)&woh, g_wout_h); cudaGetSymbolAddress((void**)&wol, g_wout_l);
    cudaGetSymbolAddress((void**)&wf1h, g_wff1_h); cudaGetSymbolAddress((void**)&wf1l, g_wff1_l);
    cudaGetSymbolAddress((void**)&wf2h, g_wff2_h); cudaGetSymbolAddress((void**)&wf2l, g_wff2_l);

    cudaFuncSetAttribute(attn_kernel,
                         cudaFuncAttributeMaxDynamicSharedMemorySize, ATT_SMEM);
    cudaFuncSetAttribute(mma_gemm<0>,
                         cudaFuncAttributeMaxDynamicSharedMemorySize, GEMM_SMEM);
    cudaFuncSetAttribute(mma_gemm<2>,
                         cudaFuncAttributeMaxDynamicSharedMemorySize, GEMM_SMEM);

    // weight conversion first (also positions mma_gemm at ncu's -s 5 capture slot)
    cvt_kernel<<<4096, 256>>>(qkv_w, wqh, wql, DEPTH * DIMM * 3 * INNER / 4);
    cvt_kernel<<<2048, 256>>>(out_w, woh, wol, DEPTH * INNER * DIMM / 4);
    cvt_kernel<<<4096, 256>>>(ff1_w, wf1h, wf1l, DEPTH * DIMM * MLPD / 4);
    cvt_kernel<<<4096, 256>>>(ff2_w, wf2h, wf2l, DEPTH * MLPD * DIMM / 4);

    cudaMemcpyAsync(x, x_in, sizeof(float) * (size_t)TOK * DIMM,
                    cudaMemcpyDeviceToDevice);

    const int RED_N4 = TOK * DIMM / 4;

    for (int l = 0; l < DEPTH; ++l) {
        size_t wq = (size_t)l * DIMM * 3 * INNER;
        size_t wo = (size_t)l * INNER * DIMM;
        size_t w1 = (size_t)l * DIMM * MLPD;
        size_t w2 = (size_t)l * MLPD * DIMM;

        ln_kernel<<<TOK, 256>>>(x, ln1_g + (size_t)l * DIMM,
                                   ln1_b + (size_t)l * DIMM, hh, hl);
        mma_gemm<0><<<dim3(3 * INNER / 128, TOK / 128, 1), 256, GEMM_SMEM>>>(
            hh, hl, wqh + wq, wql + wq, qkvb, nullptr, nullptr, nullptr,
            TOK, 3 * INNER, DIMM, DIMM);
        attn_kernel<<<dim3(NN / 64, BB * HEADS), 256, ATT_SMEM>>>(qkvb, mask, oh, ol);
        mma_gemm<0><<<dim3(DIMM / 128, TOK / 128, 2), 256, GEMM_SMEM>>>(
            oh, ol, woh + wo, wol + wo, part, nullptr, nullptr, nullptr,
            TOK, DIMM, INNER, INNER / 2);
        reduce_kernel<2><<<RED_N4 / 256, 256>>>(x, out_b + (size_t)l * DIMM,
                                                part, RED_N4);
        ln_kernel<<<TOK, 256>>>(x, ln2_g + (size_t)l * DIMM,
                                   ln2_b + (size_t)l * DIMM, hh, hl);
        mma_gemm<2><<<dim3(MLPD / 128, TOK / 128, 1), 256, GEMM_SMEM>>>(
            hh, hl, wf1h + w1, wf1l + w1, nullptr, ff1_b + (size_t)l * MLPD,
            h2h, h2l, TOK, MLPD, DIMM, DIMM);
        mma_gemm<0><<<dim3(DIMM / 128, TOK / 128, 4), 256, GEMM_SMEM>>>(
            h2h, h2l, wf2h + w2, wf2l + w2, part, nullptr, nullptr, nullptr,
            TOK, DIMM, MLPD, MLPD / 4);
        reduce_kernel<4><<<RED_N4 / 256, 256>>>(x, ff2_b + (size_t)l * DIMM,
                                                part, RED_N4);
    }
}

// round 13
// speedup vs baseline: 3.1034x; 1.2764x over previous
#include <cuda_runtime.h>
#include <cuda_bf16.h>
#include <math.h>
#include <stdint.h>

// Problem constants
#define BB     2
#define NN     1024
#define DIMM   1024
#define DEPTH  4
#define HEADS  16
#define DHEAD  64
#define INNER  1024
#define MLPD   4096
#define TOK    (BB*NN)       // 2048

typedef __nv_bfloat16 bf16;

// ---------------------------------------------------------------------------
// Scratch (no cudaMalloc allowed)
// ---------------------------------------------------------------------------
__device__ float g_part[4 * TOK * DIMM];

__device__ bf16 g_qkvh[TOK * 3 * INNER], g_qkvl[TOK * 3 * INNER];
__device__ bf16 g_hh [TOK * DIMM],  g_hl [TOK * DIMM];
__device__ bf16 g_h2h[TOK * MLPD],  g_h2l[TOK * MLPD];
__device__ bf16 g_oh [TOK * INNER], g_ol [TOK * INNER];

__device__ bf16 g_wqkv_h[DEPTH * DIMM * 3 * INNER], g_wqkv_l[DEPTH * DIMM * 3 * INNER];
__device__ bf16 g_wout_h[DEPTH * INNER * DIMM],     g_wout_l[DEPTH * INNER * DIMM];
__device__ bf16 g_wff1_h[DEPTH * DIMM * MLPD],      g_wff1_l[DEPTH * DIMM * MLPD];
__device__ bf16 g_wff2_h[DEPTH * MLPD * DIMM],      g_wff2_l[DEPTH * MLPD * DIMM];

// ---------------------------------------------------------------------------
// Helpers
// ---------------------------------------------------------------------------
__device__ __forceinline__ uint32_t s2u(const void* p) {
    uint32_t a;
    asm("{ .reg .u64 t; cvta.to.shared.u64 t, %1; cvt.u32.u64 %0, t; }"
        : "=r"(a) : "l"(p));
    return a;
}

__device__ __forceinline__ void split1(float x, bf16& h, bf16& l) {
    h = __float2bfloat16(x);
    l = __float2bfloat16(x - __bfloat162float(h));
}

__device__ __forceinline__ uint32_t pack2(float a, float b) {
    __nv_bfloat162 p = __halves2bfloat162(__float2bfloat16(a), __float2bfloat16(b));
    return *reinterpret_cast<uint32_t*>(&p);
}

#define LDX4(r, addr) \
    asm volatile("ldmatrix.sync.aligned.m8n8.x4.shared.b16 {%0,%1,%2,%3}, [%4];" \
        : "=r"((r)[0]), "=r"((r)[1]), "=r"((r)[2]), "=r"((r)[3]) : "r"(addr))

#define LDX4T(r, addr) \
    asm volatile("ldmatrix.sync.aligned.m8n8.x4.trans.shared.b16 {%0,%1,%2,%3}, [%4];" \
        : "=r"((r)[0]), "=r"((r)[1]), "=r"((r)[2]), "=r"((r)[3]) : "r"(addr))

#define MMA(cd, a, b) \
    asm volatile("mma.sync.aligned.m16n8k16.row.col.f32.bf16.bf16.f32 " \
        "{%0,%1,%2,%3}, {%4,%5,%6,%7}, {%8,%9}, {%0,%1,%2,%3};" \
        : "+f"((cd)[0]), "+f"((cd)[1]), "+f"((cd)[2]), "+f"((cd)[3]) \
        : "r"((a)[0]), "r"((a)[1]), "r"((a)[2]), "r"((a)[3]), \
          "r"((b)[0]), "r"((b)[1]))

#define CP16(dst, src) \
    asm volatile("cp.async.cg.shared.global [%0], [%1], 16;" \
        :: "r"(dst), "l"(src) : "memory")

__device__ __forceinline__ float gelu1(float v) {
    return 0.5f * v * (1.f + erff(v * 0.70710678118654752f));
}

// ---------------------------------------------------------------------------
// fp32 -> bf16 hi/lo elementwise convert
// ---------------------------------------------------------------------------
__global__ void cvt_kernel(const float* __restrict__ in,
                           bf16* __restrict__ h, bf16* __restrict__ l, int n4)
{
    for (int i = blockIdx.x * blockDim.x + threadIdx.x; i < n4;
         i += gridDim.x * blockDim.x) {
        float4 v = ((const float4*)in)[i];
        bf16 h0, l0, h1, l1, h2, l2, h3, l3;
        split1(v.x, h0, l0); split1(v.y, h1, l1);
        split1(v.z, h2, l2); split1(v.w, h3, l3);
        __nv_bfloat162 hp0 = __halves2bfloat162(h0, h1);
        __nv_bfloat162 hp1 = __halves2bfloat162(h2, h3);
        __nv_bfloat162 lp0 = __halves2bfloat162(l0, l1);
        __nv_bfloat162 lp1 = __halves2bfloat162(l2, l3);
        ((uint2*)h)[i] = make_uint2(*(uint32_t*)&hp0, *(uint32_t*)&hp1);
        ((uint2*)l)[i] = make_uint2(*(uint32_t*)&lp0, *(uint32_t*)&lp1);
    }
}

// ---------------------------------------------------------------------------
// Split-K reduce: x[i] += bias[col] + sum_p part[p][i]
// ---------------------------------------------------------------------------
template <int NP>
__global__ void reduce_kernel(float* __restrict__ x,
                              const float* __restrict__ bias,
                              const float* __restrict__ part, int n4)
{
    int i = blockIdx.x * blockDim.x + threadIdx.x;
    if (i >= n4) return;
    float4 v = ((const float4*)x)[i];
    float4 b = ((const float4*)bias)[i & (DIMM / 4 - 1)];
    v.x += b.x; v.y += b.y; v.z += b.z; v.w += b.w;
#pragma unroll
    for (int p = 0; p < NP; ++p) {
        float4 pv = ((const float4*)(part + (size_t)p * TOK * DIMM))[i];
        v.x += pv.x; v.y += pv.y; v.z += pv.z; v.w += pv.w;
    }
    ((float4*)x)[i] = v;
}

// ---------------------------------------------------------------------------
// Tensor-core GEMM, bf16 hi/lo, 3-term split MMA, fp32 accumulate.
// EPI: 0 plain fp32, 2 +bias+GELU -> bf16 h/l, 3 plain -> bf16 h/l
// ---------------------------------------------------------------------------
#define APITCH 40
#define BPITCH 136
#define AH_OFF 0
#define AL_OFF (128 * APITCH * 2)
#define BH_OFF (2 * 128 * APITCH * 2)
#define BL_OFF (BH_OFF + 32 * BPITCH * 2)
#define STG_TOTAL (BL_OFF + 32 * BPITCH * 2)     // 37888
#define NST 2
#define GEMM_SMEM (NST * STG_TOTAL)              // 75776

template <int EPI>
__global__ __launch_bounds__(256, 2)
void mma_gemm(const bf16* __restrict__ Ah, const bf16* __restrict__ Al,
              const bf16* __restrict__ Bh, const bf16* __restrict__ Bl,
              float* __restrict__ C, const float* __restrict__ bias,
              bf16* __restrict__ Ch, bf16* __restrict__ Cl,
              int M, int Ncols, int lda, int Kpart)
{
    extern __shared__ __align__(16) char smem[];
    const uint32_t sbase = s2u(smem);

    const int tid = threadIdx.x, lane = tid & 31, wid = tid >> 5;
    const int m0 = blockIdx.y * 128, n0 = blockIdx.x * 128;
    const int wm = (wid >> 2) * 64, wn = (wid & 3) * 32;
    const int koff = blockIdx.z * Kpart;
    C += (size_t)blockIdx.z * M * Ncols;

    float acc[4][4][4];
#pragma unroll
    for (int i = 0; i < 4; ++i)
#pragma unroll
        for (int j = 0; j < 4; ++j)
#pragma unroll
            for (int q = 0; q < 4; ++q) acc[i][j][q] = 0.f;

    const uint32_t a_off = ((wm + (lane & 15)) * APITCH + (lane >> 4) * 8) * 2;
    const uint32_t b_off = ((lane & 15) * BPITCH + wn + (lane >> 4) * 8) * 2;

    const int NCH = Kpart / 32;

    auto issue = [&](int cc, uint32_t so) {
#pragma unroll
        for (int i = 0; i < 2; ++i) {
            int idx = tid + i * 256;
            int arow = idx >> 2, akc = (idx & 3) * 8;
            CP16(sbase + so + AH_OFF + (arow * APITCH + akc) * 2,
                 Ah + (size_t)(m0 + arow) * lda + koff + cc * 32 + akc);
            CP16(sbase + so + AL_OFF + (arow * APITCH + akc) * 2,
                 Al + (size_t)(m0 + arow) * lda + koff + cc * 32 + akc);
            int bkr = idx >> 4, bn = (idx & 15) * 8;
            CP16(sbase + so + BH_OFF + (bkr * BPITCH + bn) * 2,
                 Bh + (size_t)(koff + cc * 32 + bkr) * Ncols + n0 + bn);
            CP16(sbase + so + BL_OFF + (bkr * BPITCH + bn) * 2,
                 Bl + (size_t)(koff + cc * 32 + bkr) * Ncols + n0 + bn);
        }
        asm volatile("cp.async.commit_group;" ::: "memory");
    };

    issue(0, 0);

    for (int c = 0; c < NCH; ++c) {
        const uint32_t so = (uint32_t)(c & 1) * STG_TOTAL;
        __syncthreads();
        if (c + 1 < NCH) {
            issue(c + 1, (uint32_t)((c + 1) & 1) * STG_TOTAL);
            asm volatile("cp.async.wait_group 1;" ::: "memory");
        } else {
            asm volatile("cp.async.wait_group 0;" ::: "memory");
        }
        __syncthreads();

#pragma unroll
        for (int ks = 0; ks < 2; ++ks) {
            uint32_t bh[8], bl[8];
            {
                uint32_t bb = sbase + so + BH_OFF + b_off + ks * 16 * BPITCH * 2;
                uint32_t lb = sbase + so + BL_OFF + b_off + ks * 16 * BPITCH * 2;
                LDX4T(bh + 0, bb);
                LDX4T(bh + 4, bb + 32);
                LDX4T(bl + 0, lb);
                LDX4T(bl + 4, lb + 32);
            }
            const uint32_t abase = sbase + so + AH_OFF + a_off + ks * 32;
            const uint32_t lbase = sbase + so + AL_OFF + a_off + ks * 32;
#pragma unroll
            for (int mi = 0; mi < 4; ++mi) {
                uint32_t ah[4], al[4];
                LDX4(ah, abase + mi * 16 * APITCH * 2);
                LDX4(al, lbase + mi * 16 * APITCH * 2);
#pragma unroll
                for (int ni = 0; ni < 4; ++ni) MMA(acc[mi][ni], ah, bh + ni * 2);
#pragma unroll
                for (int ni = 0; ni < 4; ++ni) MMA(acc[mi][ni], ah, bl + ni * 2);
#pragma unroll
                for (int ni = 0; ni < 4; ++ni) MMA(acc[mi][ni], al, bh + ni * 2);
            }
        }
    }

    // epilogue
#pragma unroll
    for (int mi = 0; mi < 4; ++mi) {
        int row = m0 + wm + mi * 16 + (lane >> 2);
#pragma unroll
        for (int ni = 0; ni < 4; ++ni) {
            int col = n0 + wn + ni * 8 + (lane & 3) * 2;
#pragma unroll
            for (int half = 0; half < 2; ++half) {
                int r = row + half * 8;
                float v0 = acc[mi][ni][half * 2 + 0];
                float v1 = acc[mi][ni][half * 2 + 1];
                size_t idx = (size_t)r * Ncols + col;
                if (EPI == 0) {
                    *(float2*)(C + idx) = make_float2(v0, v1);
                } else {
                    if (EPI == 2) {
                        v0 = gelu1(v0 + bias[col]);
                        v1 = gelu1(v1 + bias[col + 1]);
                    }
                    bf16 h0, l0, h1, l1;
                    split1(v0, h0, l0);
                    split1(v1, h1, l1);
                    __nv_bfloat162 hp = __halves2bfloat162(h0, h1);
                    __nv_bfloat162 lp = __halves2bfloat162(l0, l1);
                    *(uint32_t*)(Ch + idx) = *(uint32_t*)&hp;
                    *(uint32_t*)(Cl + idx) = *(uint32_t*)&lp;
                }
            }
        }
    }
}

// ---------------------------------------------------------------------------
// LayerNorm
// ---------------------------------------------------------------------------
__global__ void ln_kernel(const float* __restrict__ x,
                          const float* __restrict__ g,
                          const float* __restrict__ b,
                          bf16* __restrict__ oh, bf16* __restrict__ ol)
{
    int row = blockIdx.x;
    int tid = threadIdx.x;
    int lane = tid & 31, wid = tid >> 5;
    __shared__ float red[8];
    __shared__ float bc[2];

    float4 v = *(const float4*)(x + (size_t)row * DIMM + tid * 4);

    float s = v.x + v.y + v.z + v.w;
#pragma unroll
    for (int o = 16; o > 0; o >>= 1) s += __shfl_xor_sync(~0u, s, o);
    if (lane == 0) red[wid] = s;
    __syncthreads();
    if (tid == 0) {
        float t = 0.f;
#pragma unroll
        for (int i = 0; i < 8; ++i) t += red[i];
        bc[0] = t * (1.f / DIMM);
    }
    __syncthreads();
    float mu = bc[0];

    float dx = v.x - mu, dy = v.y - mu, dz = v.z - mu, dw = v.w - mu;
    float s2 = dx * dx + dy * dy + dz * dz + dw * dw;
#pragma unroll
    for (int o = 16; o > 0; o >>= 1) s2 += __shfl_xor_sync(~0u, s2, o);
    if (lane == 0) red[wid] = s2;
    __syncthreads();
    if (tid == 0) {
        float t = 0.f;
#pragma unroll
        for (int i = 0; i < 8; ++i) t += red[i];
        bc[1] = rsqrtf(t * (1.f / DIMM) + 1e-5f);
    }
    __syncthreads();
    float rstd = bc[1];

    float4 gg = *(const float4*)(g + tid * 4);
    float4 bb = *(const float4*)(b + tid * 4);
    float o0 = dx * rstd * gg.x + bb.x;
    float o1 = dy * rstd * gg.y + bb.y;
    float o2 = dz * rstd * gg.z + bb.z;
    float o3 = dw * rstd * gg.w + bb.w;

    bf16 h0, l0, h1, l1, h2, l2, h3, l3;
    split1(o0, h0, l0); split1(o1, h1, l1);
    split1(o2, h2, l2); split1(o3, h3, l3);
    __nv_bfloat162 hp0 = __halves2bfloat162(h0, h1);
    __nv_bfloat162 hp1 = __halves2bfloat162(h2, h3);
    __nv_bfloat162 lp0 = __halves2bfloat162(l0, l1);
    __nv_bfloat162 lp1 = __halves2bfloat162(l2, l3);
    size_t idx = (size_t)row * DIMM + tid * 4;
    *(uint2*)(oh + idx) = make_uint2(*(uint32_t*)&hp0, *(uint32_t*)&hp1);
    *(uint2*)(ol + idx) = make_uint2(*(uint32_t*)&lp0, *(uint32_t*)&lp1);
}

// ---------------------------------------------------------------------------
// MMA-based fused attention. bf16 hi/lo Q,K,V (3-term split), fp32 softmax.
// CTA: 64 q-rows for one (batch, head). 8 warps, each 16x32 of the 64x64 tile.
// ---------------------------------------------------------------------------
#define ATP 72                                 // bf16 tile pitch (elems)
#define SPITCH 68                              // fp32 S pitch (elems)
#define AQH 0
#define AQL (AQH + 64 * ATP * 2)               // 9216 steps
#define AKH (AQL + 64 * ATP * 2)
#define AKL (AKH + 64 * ATP * 2)
#define AVH (AKL + 64 * ATP * 2)
#define AVL (AVH + 64 * ATP * 2)
#define APH (AVL + 64 * ATP * 2)
#define APL (APH + 64 * ATP * 2)
#define ASS (APL + 64 * ATP * 2)               // 73728
#define ASTAT (ASS + 64 * SPITCH * 4)          // 91136
#define ATT_SMEM (ASTAT + 3 * 64 * 4)          // 91904

__global__ __launch_bounds__(256, 2)
void attn_kernel(const bf16* __restrict__ qkvh, const bf16* __restrict__ qkvl,
                 const int* __restrict__ mask,
                 bf16* __restrict__ oh, bf16* __restrict__ ol)
{
    extern __shared__ __align__(16) char sm[];
    const uint32_t sb = s2u(sm);
    float* Ss     = (float*)(sm + ASS);
    float* m_s    = (float*)(sm + ASTAT);
    float* l_s    = m_s + 64;
    float* corr_s = l_s + 64;

    const int tid = threadIdx.x, lane = tid & 31, wid = tid >> 5;
    const int bh = blockIdx.y, b = bh >> 4, h = bh & 15;
    const int q0 = blockIdx.x * 64;
    const int wr = (wid & 3) * 16, wc = (wid >> 2) * 32;
    const float scale = 0.125f;
    const size_t rs = 3 * INNER;

    // load Q tile (64x64) hi/lo
    {
        const bf16* qh_g = qkvh + ((size_t)(b * NN + q0)) * rs + h * DHEAD;
        const bf16* ql_g = qkvl + ((size_t)(b * NN + q0)) * rs + h * DHEAD;
        for (int idx = tid; idx < 512; idx += 256) {
            int r = idx >> 3, ch = (idx & 7) * 8;
            size_t off = (size_t)r * rs + ch;
            *(uint4*)(sm + AQH + (r * ATP + ch) * 2) = *(const uint4*)(qh_g + off);
            *(uint4*)(sm + AQL + (r * ATP + ch) * 2) = *(const uint4*)(ql_g + off);
        }
    }
    if (tid < 64) { m_s[tid] = -INFINITY; l_s[tid] = 0.f; }

    float oacc[4][4];
#pragma unroll
    for (int i = 0; i < 4; ++i)
#pragma unroll
        for (int j = 0; j < 4; ++j) oacc[i][j] = 0.f;

    // fragment base addresses
    const uint32_t frag_a = ((lane & 15) * ATP + (lane >> 4) * 8) * 2;
    const uint32_t qa  = sb + AQH + wr * ATP * 2 + frag_a;
    const uint32_t qla = sb + AQL + wr * ATP * 2 + frag_a;
    const uint32_t ka  = sb + AKH + wc * ATP * 2 + frag_a;
    const uint32_t kla = sb + AKL + wc * ATP * 2 + frag_a;
    const uint32_t pa  = sb + APH + wr * ATP * 2 + frag_a;
    const uint32_t pla = sb + APL + wr * ATP * 2 + frag_a;
    const uint32_t va  = sb + AVH + ((lane & 15) * ATP + wc + (lane >> 4) * 8) * 2;
    const uint32_t vla = sb + AVL + ((lane & 15) * ATP + wc + (lane >> 4) * 8) * 2;

    for (int kt = 0; kt < NN / 64; ++kt) {
        const int k0 = kt * 64;
        __syncthreads();   // protect K/V/P from overwrite while still being read

        // load K,V tiles hi/lo
        {
            const bf16* kh_g = qkvh + ((size_t)(b * NN + k0)) * rs + INNER + h * DHEAD;
            const bf16* kl_g = qkvl + ((size_t)(b * NN + k0)) * rs + INNER + h * DHEAD;
            for (int idx = tid; idx < 512; idx += 256) {
                int r = idx >> 3, ch = (idx & 7) * 8;
                size_t off = (size_t)r * rs + ch;
                *(uint4*)(sm + AKH + (r * ATP + ch) * 2) = *(const uint4*)(kh_g + off);
                *(uint4*)(sm + AKL + (r * ATP + ch) * 2) = *(const uint4*)(kl_g + off);
                *(uint4*)(sm + AVH + (r * ATP + ch) * 2) = *(const uint4*)(kh_g + INNER + off);
                *(uint4*)(sm + AVL + (r * ATP + ch) * 2) = *(const uint4*)(kl_g + INNER + off);
            }
        }
        __syncthreads();

        // ---- S = Q K^T (3-term split) ----
        float sacc[4][4];
#pragma unroll
        for (int i = 0; i < 4; ++i)
#pragma unroll
            for (int j = 0; j < 4; ++j) sacc[i][j] = 0.f;

#pragma unroll
        for (int kd = 0; kd < 4; ++kd) {
            uint32_t aqh[4], aql[4];
            LDX4(aqh, qa + kd * 32);
            LDX4(aql, qla + kd * 32);
            uint32_t t0[4], t1[4], kh[8], kl[8];
            LDX4(t0, ka + kd * 32);
            LDX4(t1, ka + 16 * ATP * 2 + kd * 32);
            kh[0] = t0[0]; kh[1] = t0[2]; kh[2] = t0[1]; kh[3] = t0[3];
            kh[4] = t1[0]; kh[5] = t1[2]; kh[6] = t1[1]; kh[7] = t1[3];
            LDX4(t0, kla + kd * 32);
            LDX4(t1, kla + 16 * ATP * 2 + kd * 32);
            kl[0] = t0[0]; kl[1] = t0[2]; kl[2] = t0[1]; kl[3] = t0[3];
            kl[4] = t1[0]; kl[5] = t1[2]; kl[6] = t1[1]; kl[7] = t1[3];
#pragma unroll
            for (int nt = 0; nt < 4; ++nt) MMA(sacc[nt], aqh, kh + nt * 2);
#pragma unroll
            for (int nt = 0; nt < 4; ++nt) MMA(sacc[nt], aqh, kl + nt * 2);
#pragma unroll
            for (int nt = 0; nt < 4; ++nt) MMA(sacc[nt], aql, kh + nt * 2);
        }

        // write S (scaled + masked) to smem
        {
            const int* mbase = mask + ((size_t)b * NN + q0) * NN + k0;
            int r0 = wr + (lane >> 2), r1 = r0 + 8;
#pragma unroll
            for (int nt = 0; nt < 4; ++nt) {
                int col = wc + nt * 8 + (lane & 3) * 2;
                const int* m0p = mbase + (size_t)r0 * NN + col;
                const int* m1p = mbase + (size_t)r1 * NN + col;
                Ss[r0 * SPITCH + col]     = m0p[0] ? sacc[nt][0] * scale : -1e9f;
                Ss[r0 * SPITCH + col + 1] = m0p[1] ? sacc[nt][1] * scale : -1e9f;
                Ss[r1 * SPITCH + col]     = m1p[0] ? sacc[nt][2] * scale : -1e9f;
                Ss[r1 * SPITCH + col + 1] = m1p[1] ? sacc[nt][3] * scale : -1e9f;
            }
        }
        __syncthreads();

        // ---- online softmax (4 threads per row) ----
        {
            int r = tid >> 2, q = tid & 3;
            float* row = &Ss[r * SPITCH + q * 16];
            float mx = m_s[r];
            float tmax = -INFINITY;
#pragma unroll
            for (int j = 0; j < 16; ++j) tmax = fmaxf(tmax, row[j]);
            tmax = fmaxf(tmax, __shfl_xor_sync(~0u, tmax, 1));
            tmax = fmaxf(tmax, __shfl_xor_sync(~0u, tmax, 2));
            float nm = fmaxf(mx, tmax);
            float sum = 0.f;
#pragma unroll
            for (int j = 0; j < 16; ++j) {
                float p = __expf(row[j] - nm);
                row[j] = p;
                sum += p;
            }
            sum += __shfl_xor_sync(~0u, sum, 1);
            sum += __shfl_xor_sync(~0u, sum, 2);
            if (q == 0) {
                float corr = __expf(mx - nm);
                m_s[r] = nm;
                l_s[r] = l_s[r] * corr + sum;
                corr_s[r] = corr;
            }
        }
        __syncthreads();

        // ---- split P -> bf16 hi/lo smem ----
        for (int idx = tid; idx < 512; idx += 256) {
            int r = idx >> 3, ch = (idx & 7) * 8;
            float4 p0 = *(float4*)&Ss[r * SPITCH + ch];
            float4 p1 = *(float4*)&Ss[r * SPITCH + ch + 4];
            bf16 h0, l0, h1, l1, h2, l2, h3, l3, h4, l4, h5, l5, h6, l6, h7, l7;
            split1(p0.x, h0, l0); split1(p0.y, h1, l1);
            split1(p0.z, h2, l2); split1(p0.w, h3, l3);
            split1(p1.x, h4, l4); split1(p1.y, h5, l5);
            split1(p1.z, h6, l6); split1(p1.w, h7, l7);
            __nv_bfloat162 a0 = __halves2bfloat162(h0, h1), a1 = __halves2bfloat162(h2, h3);
            __nv_bfloat162 a2 = __halves2bfloat162(h4, h5), a3 = __halves2bfloat162(h6, h7);
            __nv_bfloat162 c0 = __halves2bfloat162(l0, l1), c1 = __halves2bfloat162(l2, l3);
            __nv_bfloat162 c2 = __halves2bfloat162(l4, l5), c3 = __halves2bfloat162(l6, l7);
            *(uint4*)(sm + APH + (r * ATP + ch) * 2) =
                make_uint4(*(uint32_t*)&a0, *(uint32_t*)&a1, *(uint32_t*)&a2, *(uint32_t*)&a3);
            *(uint4*)(sm + APL + (r * ATP + ch) * 2) =
                make_uint4(*(uint32_t*)&c0, *(uint32_t*)&c1, *(uint32_t*)&c2, *(uint32_t*)&c3);
        }
        __syncthreads();

        // ---- O = O*corr + P V (3-term split) ----
        {
            float c0 = corr_s[wr + (lane >> 2)];
            float c1 = corr_s[wr + (lane >> 2) + 8];
#pragma unroll
            for (int nt = 0; nt < 4; ++nt) {
                oacc[nt][0] *= c0; oacc[nt][1] *= c0;
                oacc[nt][2] *= c1; oacc[nt][3] *= c1;
            }
        }
#pragma unroll
        for (int kd = 0; kd < 4; ++kd) {
            uint32_t ap[4], apl[4];
            LDX4(ap,  pa  + kd * 32);
            LDX4(apl, pla + kd * 32);
            uint32_t vh[8], vl[8];
            LDX4T(vh + 0, va  + kd * (16 * ATP * 2));
            LDX4T(vh + 4, va  + kd * (16 * ATP * 2) + 32);
            LDX4T(vl + 0, vla + kd * (16 * ATP * 2));
            LDX4T(vl + 4, vla + kd * (16 * ATP * 2) + 32);
#pragma unroll
            for (int nt = 0; nt < 4; ++nt) MMA(oacc[nt], ap,  vh + nt * 2);
#pragma unroll
            for (int nt = 0; nt < 4; ++nt) MMA(oacc[nt], ap,  vl + nt * 2);
#pragma unroll
            for (int nt = 0; nt < 4; ++nt) MMA(oacc[nt], apl, vh + nt * 2);
        }
    }

    // ---- write O (normalized) as bf16 hi/lo ----
    {
        int r0 = wr + (lane >> 2), r1 = r0 + 8;
        float il0 = 1.f / l_s[r0];
        float il1 = 1.f / l_s[r1];
        size_t base0 = ((size_t)(b * NN + q0 + r0)) * INNER + h * DHEAD;
        size_t base1 = ((size_t)(b * NN + q0 + r1)) * INNER + h * DHEAD;
#pragma unroll
        for (int nt = 0; nt < 4; ++nt) {
            int col = wc + nt * 8 + (lane & 3) * 2;
            float v0 = oacc[nt][0] * il0, v1 = oacc[nt][1] * il0;
            float v2 = oacc[nt][2] * il1, v3 = oacc[nt][3] * il1;
            bf16 h0, l0, h1, l1;
            split1(v0, h0, l0); split1(v1, h1, l1);
            __nv_bfloat162 hp = __halves2bfloat162(h0, h1);
            __nv_bfloat162 lp = __halves2bfloat162(l0, l1);
            *(uint32_t*)(oh + base0 + col) = *(uint32_t*)&hp;
            *(uint32_t*)(ol + base0 + col) = *(uint32_t*)&lp;
            split1(v2, h0, l0); split1(v3, h1, l1);
            hp = __halves2bfloat162(h0, h1);
            lp = __halves2bfloat162(l0, l1);
            *(uint32_t*)(oh + base1 + col) = *(uint32_t*)&hp;
            *(uint32_t*)(ol + base1 + col) = *(uint32_t*)&lp;
        }
    }
}

// ---------------------------------------------------------------------------
// Launch
// ---------------------------------------------------------------------------
extern "C" void kernel_launch(void* const* d_in, const int* in_sizes, int n_in,
                              void* d_out, int out_size)
{
    const float* x_in  = (const float*)d_in[0];
    const int*   mask  = (const int*)  d_in[1];
    const float* ln1_g = (const float*)d_in[2];
    const float* ln1_b = (const float*)d_in[3];
    const float* qkv_w = (const float*)d_in[4];
    const float* out_w = (const float*)d_in[5];
    const float* out_b = (const float*)d_in[6];
    const float* ln2_g = (const float*)d_in[7];
    const float* ln2_b = (const float*)d_in[8];
    const float* ff1_w = (const float*)d_in[9];
    const float* ff1_b = (const float*)d_in[10];
    const float* ff2_w = (const float*)d_in[11];
    const float* ff2_b = (const float*)d_in[12];
    float* x = (float*)d_out;

    float* part;
    bf16 *qkvh, *qkvl, *hh, *hl, *h2h, *h2l, *oh, *ol;
    bf16 *wqh, *wql, *woh, *wol, *wf1h, *wf1l, *wf2h, *wf2l;
    cudaGetSymbolAddress((void**)&part, g_part);
    cudaGetSymbolAddress((void**)&qkvh, g_qkvh); cudaGetSymbolAddress((void**)&qkvl, g_qkvl);
    cudaGetSymbolAddress((void**)&hh,  g_hh);  cudaGetSymbolAddress((void**)&hl,  g_hl);
    cudaGetSymbolAddress((void**)&h2h, g_h2h); cudaGetSymbolAddress((void**)&h2l, g_h2l);
    cudaGetSymbolAddress((void**)&oh,  g_oh);  cudaGetSymbolAddress((void**)&ol,  g_ol);
    cudaGetSymbolAddress((void**)&wqh, g_wqkv_h); cudaGetSymbolAddress((void**)&wql, g_wqkv_l);
    cudaGetSymbolAddress((void**)&woh, g_wout_h); cudaGetSymbolAddress((void**)&wol, g_wout_l);
    cudaGetSymbolAddress((void**)&wf1h, g_wff1_h); cudaGetSymbolAddress((void**)&wf1l, g_wff1_l);
    cudaGetSymbolAddress((void**)&wf2h, g_wff2_h); cudaGetSymbolAddress((void**)&wf2l, g_wff2_l);

    cudaFuncSetAttribute(attn_kernel,
                         cudaFuncAttributeMaxDynamicSharedMemorySize, ATT_SMEM);
    cudaFuncSetAttribute(mma_gemm<0>,
                         cudaFuncAttributeMaxDynamicSharedMemorySize, GEMM_SMEM);
    cudaFuncSetAttribute(mma_gemm<2>,
                         cudaFuncAttributeMaxDynamicSharedMemorySize, GEMM_SMEM);
    cudaFuncSetAttribute(mma_gemm<3>,
                         cudaFuncAttributeMaxDynamicSharedMemorySize, GEMM_SMEM);

    cvt_kernel<<<4096, 256>>>(qkv_w, wqh, wql, DEPTH * DIMM * 3 * INNER / 4);
    cvt_kernel<<<2048, 256>>>(out_w, woh, wol, DEPTH * INNER * DIMM / 4);
    cvt_kernel<<<4096, 256>>>(ff1_w, wf1h, wf1l, DEPTH * DIMM * MLPD / 4);
    cvt_kernel<<<4096, 256>>>(ff2_w, wf2h, wf2l, DEPTH * MLPD * DIMM / 4);

    cudaMemcpyAsync(x, x_in, sizeof(float) * (size_t)TOK * DIMM,
                    cudaMemcpyDeviceToDevice);

    const int RED_N4 = TOK * DIMM / 4;

    for (int l = 0; l < DEPTH; ++l) {
        size_t wq = (size_t)l * DIMM * 3 * INNER;
        size_t wo = (size_t)l * INNER * DIMM;
        size_t w1 = (size_t)l * DIMM * MLPD;
        size_t w2 = (size_t)l * MLPD * DIMM;

        ln_kernel<<<TOK, 256>>>(x, ln1_g + (size_t)l * DIMM,
                                   ln1_b + (size_t)l * DIMM, hh, hl);
        // qkv -> bf16 hi/lo directly
        mma_gemm<3><<<dim3(3 * INNER / 128, TOK / 128, 1), 256, GEMM_SMEM>>>(
            hh, hl, wqh + wq, wql + wq, nullptr, nullptr, qkvh, qkvl,
            TOK, 3 * INNER, DIMM, DIMM);
        attn_kernel<<<dim3(NN / 64, BB * HEADS), 256, ATT_SMEM>>>(
            qkvh, qkvl, mask, oh, ol);
        mma_gemm<0><<<dim3(DIMM / 128, TOK / 128, 2), 256, GEMM_SMEM>>>(
            oh, ol, woh + wo, wol + wo, part, nullptr, nullptr, nullptr,
            TOK, DIMM, INNER, INNER / 2);
        reduce_kernel<2><<<RED_N4 / 256, 256>>>(x, out_b + (size_t)l * DIMM,
                                                part, RED_N4);
        ln_kernel<<<TOK, 256>>>(x, ln2_g + (size_t)l * DIMM,
                                   ln2_b + (size_t)l * DIMM, hh, hl);
        mma_gemm<2><<<dim3(MLPD / 128, TOK / 128, 1), 256, GEMM_SMEM>>>(
            hh, hl, wf1h + w1, wf1l + w1, nullptr, ff1_b + (size_t)l * MLPD,
            h2h, h2l, TOK, MLPD, DIMM, DIMM);
        mma_gemm<0><<<dim3(DIMM / 128, TOK / 128, 4), 256, GEMM_SMEM>>>(
            h2h, h2l, wf2h + w2, wf2l + w2, part, nullptr, nullptr, nullptr,
            TOK, DIMM, MLPD, MLPD / 4);
        reduce_kernel<4><<<RED_N4 / 256, 256>>>(x, ff2_b + (size_t)l * DIMM,
                                                part, RED_N4);
    }
}